// round 3
// baseline (speedup 1.0000x reference)
#include <cuda_runtime.h>
#include <math.h>
#include <stdint.h>

#define NH 128
#define MAXN 50000
#define MAXE 800000
#define HCOEF 0.1f
#define EPS_BN 1e-5f
#define SSTR 48  // per-layer scalar stride: Cm[0..15], c[16..19], nr[20..30], pLP[31..40]

// ---------------- device scratch ----------------
__device__ float d_Th[MAXN * NH];
__device__ float d_z[MAXN * NH];
__device__ float d_Xb[4][MAXN * NH];
__device__ float d_qb[4][MAXN * NH];
__device__ float d_kb[4][MAXN * NH];
__device__ float d_T1[MAXN * NH];
__device__ float d_A1[MAXN * NH];
__device__ float d_A2[MAXN * NH];
__device__ float d_AU[MAXN * NH];
__device__ float d_R[MAXN * NH];
__device__ float d_P[MAXN * NH];
__device__ float d_LP[MAXN * NH];
__device__ int   d_rowptr[MAXN + 1];
__device__ int   d_cnt[MAXN];
__device__ int   d_bsum[64];
__device__ int   d_cols[MAXE];
__device__ float d_w[MAXE];
__device__ float d_dinv[MAXN];
__device__ float d_scal[4 * SSTR];

__device__ __forceinline__ float block_reduce_sum(float v) {
    __shared__ float sh[32];
    int lane = threadIdx.x & 31, wid = threadIdx.x >> 5;
#pragma unroll
    for (int o = 16; o; o >>= 1) v += __shfl_xor_sync(0xffffffffu, v, o);
    if (lane == 0) sh[wid] = v;
    __syncthreads();
    float s = 0.f;
    if (threadIdx.x == 0) {
        int nw = (blockDim.x + 31) >> 5;
        for (int i = 0; i < nw; i++) s += sh[i];
    }
    return s;
}

// ---------------- CSR build ----------------
__global__ void count_kernel(const int* __restrict__ EI, int* __restrict__ cnt, int E) {
    int e = blockIdx.x * blockDim.x + threadIdx.x;
    if (e >= E) return;
    int r = EI[e], c = EI[E + e];
    if (r != c) atomicAdd(&cnt[r], 1);
}
__global__ void dinv_kernel(const int* __restrict__ cnt, float* __restrict__ dinv, int N) {
    int i = blockIdx.x * blockDim.x + threadIdx.x;
    if (i >= N) return;
    int d = cnt[i];
    dinv[i] = (d > 0) ? rsqrtf((float)d) : 0.f;
}
__global__ void blocksum_kernel(const int* __restrict__ cnt, int* __restrict__ bsum, int N) {
    __shared__ int sh[1024];
    int i = blockIdx.x * 1024 + threadIdx.x;
    sh[threadIdx.x] = (i < N) ? cnt[i] : 0;
    __syncthreads();
    for (int o = 512; o; o >>= 1) {
        if (threadIdx.x < o) sh[threadIdx.x] += sh[threadIdx.x + o];
        __syncthreads();
    }
    if (threadIdx.x == 0) bsum[blockIdx.x] = sh[0];
}
__global__ void scanbsum_kernel(int* __restrict__ bsum, int* __restrict__ rowptrN, int nb) {
    if (threadIdx.x == 0) {
        int run = 0;
        for (int i = 0; i < nb; i++) { int t = bsum[i]; bsum[i] = run; run += t; }
        *rowptrN = run;
    }
}
__global__ void localscan_kernel(int* __restrict__ cnt, int* __restrict__ rowptr,
                                 const int* __restrict__ bsum, int N) {
    __shared__ int sh[1024];
    int i = blockIdx.x * 1024 + threadIdx.x;
    int x = (i < N) ? cnt[i] : 0;
    sh[threadIdx.x] = x;
    __syncthreads();
    for (int off = 1; off < 1024; off <<= 1) {
        int t = (threadIdx.x >= off) ? sh[threadIdx.x - off] : 0;
        __syncthreads();
        sh[threadIdx.x] += t;
        __syncthreads();
    }
    if (i < N) { int excl = sh[threadIdx.x] - x + bsum[blockIdx.x]; rowptr[i] = excl; cnt[i] = excl; }
}
__global__ void fill_kernel(const int* __restrict__ EI, int* __restrict__ cursor,
                            const float* __restrict__ dinv, int* __restrict__ cols,
                            float* __restrict__ w, int E) {
    int e = blockIdx.x * blockDim.x + threadIdx.x;
    if (e >= E) return;
    int r = EI[e], c = EI[E + e];
    if (r != c) {
        int pos = atomicAdd(&cursor[r], 1);
        cols[pos] = c;
        w[pos] = -dinv[r] * dinv[c];
    }
}

// ---------------- SGEMM: C[N,Oc] = A[N,128] @ W[Oc,128]^T + bias (+BN/act) ----------------
// EPI: 0 bias, 1 BN+ELU, 2 BN+ReLU
template <int EPI>
__global__ __launch_bounds__(256, 2) void gemm_k128(
    const float* __restrict__ A, const float* __restrict__ W,
    const float* __restrict__ bias, float* __restrict__ C, int N, int Oc,
    const float* __restrict__ bng, const float* __restrict__ bnb,
    const float* __restrict__ bnm, const float* __restrict__ bnv) {
    __shared__ float As[8][132];
    __shared__ float Ws[8][132];
    const int tid = threadIdx.x;
    const int brow = blockIdx.x * 128;
    const int lr = tid >> 1, lk = (tid & 1) << 2;
    const int tr = (tid >> 4) << 3, tc = (tid & 15) << 3;
    float acc[8][8];
#pragma unroll
    for (int i = 0; i < 8; i++)
#pragma unroll
        for (int j = 0; j < 8; j++) acc[i][j] = 0.f;
    const int ar = brow + lr;
    for (int k0 = 0; k0 < 128; k0 += 8) {
        float4 av = make_float4(0.f, 0.f, 0.f, 0.f), wv = make_float4(0.f, 0.f, 0.f, 0.f);
        if (ar < N) av = *(const float4*)(A + (size_t)ar * 128 + k0 + lk);
        if (lr < Oc) wv = *(const float4*)(W + (size_t)lr * 128 + k0 + lk);
        __syncthreads();
        As[lk + 0][lr] = av.x; As[lk + 1][lr] = av.y; As[lk + 2][lr] = av.z; As[lk + 3][lr] = av.w;
        Ws[lk + 0][lr] = wv.x; Ws[lk + 1][lr] = wv.y; Ws[lk + 2][lr] = wv.z; Ws[lk + 3][lr] = wv.w;
        __syncthreads();
#pragma unroll
        for (int k = 0; k < 8; k++) {
            float a[8], b[8];
#pragma unroll
            for (int i = 0; i < 8; i++) a[i] = As[k][tr + i];
#pragma unroll
            for (int j = 0; j < 8; j++) b[j] = Ws[k][tc + j];
#pragma unroll
            for (int i = 0; i < 8; i++)
#pragma unroll
                for (int j = 0; j < 8; j++) acc[i][j] = fmaf(a[i], b[j], acc[i][j]);
        }
    }
#pragma unroll
    for (int i = 0; i < 8; i++) {
        int row = brow + tr + i;
        if (row >= N) break;
#pragma unroll
        for (int j = 0; j < 8; j++) {
            int col = tc + j;
            if (col >= Oc) continue;
            float x = acc[i][j] + bias[col];
            if (EPI) {
                float s = bng[col] * rsqrtf(bnv[col] + EPS_BN);
                x = (x - bnm[col]) * s + bnb[col];
                if (EPI == 1) x = (x > 0.f) ? x : expm1f(x);
                else x = fmaxf(x, 0.f);
            }
            C[(size_t)row * Oc + col] = x;
        }
    }
}

// ---------------- attention stats: Cm accum (16 floats, sum over nodes) ----------------
__global__ void attn_kernel(const float* __restrict__ q0, const float* __restrict__ q1,
                            const float* __restrict__ q2, const float* __restrict__ q3,
                            const float* __restrict__ k0, const float* __restrict__ k1,
                            const float* __restrict__ k2, const float* __restrict__ k3,
                            const float* __restrict__ mha, float* __restrict__ Cm, int N) {
    const float scale = 0.08838834764831845f;
    float rfac = fmaxf(mha[0], 0.f);
    int lane = threadIdx.x & 31, wid = threadIdx.x >> 5;
    int gw = blockIdx.x * (blockDim.x >> 5) + wid;
    int tw = gridDim.x * (blockDim.x >> 5);
    const float* qs[4] = {q0, q1, q2, q3};
    const float* ks[4] = {k0, k1, k2, k3};
    float acc[16];
#pragma unroll
    for (int m = 0; m < 16; m++) acc[m] = 0.f;
    for (int n = gw; n < N; n += tw) {
        float4 qv[4], kv[4];
#pragma unroll
        for (int s = 0; s < 4; s++) {
            qv[s] = *(const float4*)(qs[s] + (size_t)n * NH + lane * 4);
            kv[s] = *(const float4*)(ks[s] + (size_t)n * NH + lane * 4);
        }
        float sc[16];
#pragma unroll
        for (int i = 0; i < 4; i++)
#pragma unroll
            for (int j = 0; j < 4; j++) {
                float4 a = qv[i], b = kv[j];
                sc[i * 4 + j] = a.x * b.x + a.y * b.y + a.z * b.z + a.w * b.w;
            }
#pragma unroll
        for (int m = 0; m < 16; m++) {
            float v = sc[m];
#pragma unroll
            for (int o = 16; o; o >>= 1) v += __shfl_xor_sync(0xffffffffu, v, o);
            sc[m] = v * scale;
        }
        if (lane == 0) {
#pragma unroll
            for (int i = 0; i < 4; i++) {
                float s0 = sc[i * 4], s1 = sc[i * 4 + 1], s2 = sc[i * 4 + 2], s3 = sc[i * 4 + 3];
                float mx = fmaxf(fmaxf(s0, s1), fmaxf(s2, s3));
                float e0 = expf(s0 - mx), e1 = expf(s1 - mx), e2 = expf(s2 - mx), e3 = expf(s3 - mx);
                float inv = 1.f / (e0 + e1 + e2 + e3);
                acc[i * 4 + 0] += logf(e0 * inv * rfac + 1e-4f);
                acc[i * 4 + 1] += logf(e1 * inv * rfac + 1e-4f);
                acc[i * 4 + 2] += logf(e2 * inv * rfac + 1e-4f);
                acc[i * 4 + 3] += logf(e3 * inv * rfac + 1e-4f);
            }
        }
    }
    __shared__ float sh[8][16];
    if (lane == 0)
#pragma unroll
        for (int m = 0; m < 16; m++) sh[wid][m] = acc[m];
    __syncthreads();
    int nw = blockDim.x >> 5;
    if (threadIdx.x < 16) {
        float s = 0.f;
        for (int w2 = 0; w2 < nw; w2++) s += sh[w2][threadIdx.x];
        atomicAdd(&Cm[threadIdx.x], s);
    }
}

__global__ void c_kernel(const float* __restrict__ CmAcc, float* __restrict__ c, float Ninv) {
    if (threadIdx.x == 0) {
        float M[16];
        for (int m = 0; m < 16; m++) M[m] = CmAcc[m] * Ninv;
        float cc[4], s = 0.f;
        for (int j = 0; j < 4; j++) { cc[j] = 0.5f * (M[12 + j] + M[j * 4 + 3]); s += cc[j]; }
        float invs = 1.f / s;
        for (int j = 0; j < 4; j++) c[j] = cc[j] * invs;
    }
}

__global__ void combine4(const float* __restrict__ a0, const float* __restrict__ a1,
                         const float* __restrict__ a2, const float* __restrict__ a3,
                         const float* __restrict__ c, float* __restrict__ out, int n4) {
    int i = blockIdx.x * blockDim.x + threadIdx.x;
    if (i >= n4) return;
    float c0 = c[0], c1 = c[1], c2 = c[2], c3 = c[3];
    float4 v0 = ((const float4*)a0)[i], v1 = ((const float4*)a1)[i];
    float4 v2 = ((const float4*)a2)[i], v3 = ((const float4*)a3)[i];
    float4 o;
    o.x = c0 * v0.x + c1 * v1.x + c2 * v2.x + c3 * v3.x;
    o.y = c0 * v0.y + c1 * v1.y + c2 * v2.y + c3 * v3.y;
    o.z = c0 * v0.z + c1 * v1.z + c2 * v2.z + c3 * v3.z;
    o.w = c0 * v0.w + c1 * v1.w + c2 * v2.w + c3 * v3.w;
    ((float4*)out)[i] = o;
}

// Tr = elu(bn(T1 + H*(A1+AU+T1*clip(A2)))); X=R=P=Tr; nr[0]+=sum(Tr^2)
__global__ void reaction_epi(const float* __restrict__ T1, const float* __restrict__ A1,
                             const float* __restrict__ A2, const float* __restrict__ AU,
                             const float* __restrict__ bng, const float* __restrict__ bnb,
                             const float* __restrict__ bnm, const float* __restrict__ bnv,
                             float* __restrict__ X, float* __restrict__ R, float* __restrict__ P,
                             float* __restrict__ nr0, int n4) {
    int i = blockIdx.x * blockDim.x + threadIdx.x;
    float ss = 0.f;
    if (i < n4) {
        int col = (i << 2) & (NH - 1);
        float4 t1 = ((const float4*)T1)[i], a1 = ((const float4*)A1)[i];
        float4 a2 = ((const float4*)A2)[i], au = ((const float4*)AU)[i];
        float tt[4] = {t1.x, t1.y, t1.z, t1.w}, aa1[4] = {a1.x, a1.y, a1.z, a1.w};
        float aa2[4] = {a2.x, a2.y, a2.z, a2.w}, aau[4] = {au.x, au.y, au.z, au.w};
        float v[4];
#pragma unroll
        for (int u = 0; u < 4; u++) {
            int cl = col + u;
            float d2 = fminf(fmaxf(aa2[u], -1.f), 1.f);
            float y = tt[u] + HCOEF * (aa1[u] + aau[u] + tt[u] * d2);
            float s = bng[cl] * rsqrtf(bnv[cl] + EPS_BN);
            y = (y - bnm[cl]) * s + bnb[cl];
            y = (y > 0.f) ? y : expm1f(y);
            v[u] = y;
            ss += y * y;
        }
        float4 o = make_float4(v[0], v[1], v[2], v[3]);
        ((float4*)X)[i] = o; ((float4*)R)[i] = o; ((float4*)P)[i] = o;
    }
    float tot = block_reduce_sum(ss);
    if (threadIdx.x == 0) atomicAdd(nr0, tot);
}

// ---------------- CG ----------------
__global__ void spmv_kernel(const int* __restrict__ rowptr, const int* __restrict__ cols,
                            const float* __restrict__ w, const float* __restrict__ P,
                            float* __restrict__ LP, const float* __restrict__ Kap,
                            const float* __restrict__ nr, float* __restrict__ pLP,
                            int t, int N) {
    for (int j = 1; j <= t; j++)
        if (nr[j] < 1e-5f) return;
    int lane = threadIdx.x & 31, wid = threadIdx.x >> 5;
    int gw = blockIdx.x * (blockDim.x >> 5) + wid;
    int tw = gridDim.x * (blockDim.x >> 5);
    float4 kd;
    {
        float4 kk = *(const float4*)(Kap + lane * 4);
        kd.x = fminf(fmaxf(kk.x, 0.f), 1.f); kd.y = fminf(fmaxf(kk.y, 0.f), 1.f);
        kd.z = fminf(fmaxf(kk.z, 0.f), 1.f); kd.w = fminf(fmaxf(kk.w, 0.f), 1.f);
    }
    float dot = 0.f;
    for (int r = gw; r < N; r += tw) {
        int e0 = rowptr[r], e1 = rowptr[r + 1];
        float4 acc = make_float4(0.f, 0.f, 0.f, 0.f);
        for (int e = e0; e < e1; e++) {
            int c = __ldg(&cols[e]);
            float wt = __ldg(&w[e]);
            float4 y = *(const float4*)(P + (size_t)c * NH + lane * 4);
            acc.x = fmaf(wt, y.x, acc.x); acc.y = fmaf(wt, y.y, acc.y);
            acc.z = fmaf(wt, y.z, acc.z); acc.w = fmaf(wt, y.w, acc.w);
        }
        float4 p = *(const float4*)(P + (size_t)r * NH + lane * 4);
        float4 lp;
        lp.x = p.x + HCOEF * ((p.x + acc.x) * kd.x);
        lp.y = p.y + HCOEF * ((p.y + acc.y) * kd.y);
        lp.z = p.z + HCOEF * ((p.z + acc.z) * kd.z);
        lp.w = p.w + HCOEF * ((p.w + acc.w) * kd.w);
        *(float4*)(LP + (size_t)r * NH + lane * 4) = lp;
        dot += p.x * lp.x + p.y * lp.y + p.z * lp.z + p.w * lp.w;
    }
    float tot = block_reduce_sum(dot);
    if (threadIdx.x == 0) atomicAdd(&pLP[t], tot);
}

__global__ void upd_xr_kernel(float* __restrict__ X, float* __restrict__ R,
                              const float* __restrict__ P, const float* __restrict__ LP,
                              float* __restrict__ nr, const float* __restrict__ pLP,
                              int t, int n4) {
    for (int j = 1; j <= t; j++)
        if (nr[j] < 1e-5f) return;
    float alpha = nr[t] / (pLP[t] + 1e-6f);
    int i = blockIdx.x * blockDim.x + threadIdx.x;
    float ss = 0.f;
    if (i < n4) {
        float4 p = ((const float4*)P)[i], lp = ((const float4*)LP)[i];
        float4 x = ((float4*)X)[i], r = ((float4*)R)[i];
        x.x += alpha * p.x; x.y += alpha * p.y; x.z += alpha * p.z; x.w += alpha * p.w;
        r.x -= alpha * lp.x; r.y -= alpha * lp.y; r.z -= alpha * lp.z; r.w -= alpha * lp.w;
        ((float4*)X)[i] = x; ((float4*)R)[i] = r;
        ss = r.x * r.x + r.y * r.y + r.z * r.z + r.w * r.w;
    }
    float tot = block_reduce_sum(ss);
    if (threadIdx.x == 0) atomicAdd(&nr[t + 1], tot);
}

__global__ void upd_p_kernel(float* __restrict__ P, const float* __restrict__ R,
                             const float* __restrict__ nr, int t, int n4) {
    for (int j = 1; j <= t + 1; j++)
        if (nr[j] < 1e-5f) return;
    float beta = nr[t + 1] / (nr[t] + 1e-6f);
    int i = blockIdx.x * blockDim.x + threadIdx.x;
    if (i >= n4) return;
    float4 p = ((float4*)P)[i];
    float4 r = ((const float4*)R)[i];
    p.x = r.x + beta * p.x; p.y = r.y + beta * p.y;
    p.z = r.z + beta * p.z; p.w = r.w + beta * p.w;
    ((float4*)P)[i] = p;
}

// ---------------- host ----------------
extern "C" void kernel_launch(void* const* d_in, const int* in_sizes, int n_in,
                              void* d_out, int out_size) {
    const float* T      = (const float*)d_in[0];
    const int*   EI     = (const int*)d_in[1];
    const float* KopenW = (const float*)d_in[2];
    const float* Kopenb = (const float*)d_in[3];
    const float* bnOg   = (const float*)d_in[4];
    const float* bnOb   = (const float*)d_in[5];
    const float* bnOm   = (const float*)d_in[6];
    const float* bnOv   = (const float*)d_in[7];
    const float* convW  = (const float*)d_in[8];
    const float* convb  = (const float*)d_in[9];
    const float* bnAg   = (const float*)d_in[10];
    const float* bnAb   = (const float*)d_in[11];
    const float* bnAm   = (const float*)d_in[12];
    const float* bnAv   = (const float*)d_in[13];
    const float* Wq     = (const float*)d_in[14];
    const float* bq     = (const float*)d_in[15];
    const float* Wk     = (const float*)d_in[16];
    const float* bk     = (const float*)d_in[17];
    const float* mha    = (const float*)d_in[18];
    const float* KR1W   = (const float*)d_in[19];
    const float* KR1b   = (const float*)d_in[20];
    const float* KR2W   = (const float*)d_in[21];
    const float* KR2b   = (const float*)d_in[22];
    const float* KRU0W  = (const float*)d_in[23];
    const float* KRU0b  = (const float*)d_in[24];
    const float* bng    = (const float*)d_in[25];
    const float* bnbp   = (const float*)d_in[26];
    const float* bnm    = (const float*)d_in[27];
    const float* bnv    = (const float*)d_in[28];
    const float* Kappa  = (const float*)d_in[29];
    const float* KcloseW= (const float*)d_in[30];
    const float* Kcloseb= (const float*)d_in[31];

    const int N = in_sizes[0] / NH;
    const int E = in_sizes[1] / 2;
    const int n4 = N * (NH / 4);
    const size_t S = (size_t)MAXN * NH;

    float *Th, *z, *Xb, *qb, *kb, *T1, *A1, *A2, *AU, *R, *P, *LP, *dinvp, *wp, *scal;
    int *rowptr, *cnt, *bsum, *cols;
    cudaGetSymbolAddress((void**)&Th, d_Th);
    cudaGetSymbolAddress((void**)&z, d_z);
    cudaGetSymbolAddress((void**)&Xb, d_Xb);
    cudaGetSymbolAddress((void**)&qb, d_qb);
    cudaGetSymbolAddress((void**)&kb, d_kb);
    cudaGetSymbolAddress((void**)&T1, d_T1);
    cudaGetSymbolAddress((void**)&A1, d_A1);
    cudaGetSymbolAddress((void**)&A2, d_A2);
    cudaGetSymbolAddress((void**)&AU, d_AU);
    cudaGetSymbolAddress((void**)&R, d_R);
    cudaGetSymbolAddress((void**)&P, d_P);
    cudaGetSymbolAddress((void**)&LP, d_LP);
    cudaGetSymbolAddress((void**)&dinvp, d_dinv);
    cudaGetSymbolAddress((void**)&wp, d_w);
    cudaGetSymbolAddress((void**)&scal, d_scal);
    cudaGetSymbolAddress((void**)&rowptr, d_rowptr);
    cudaGetSymbolAddress((void**)&cnt, d_cnt);
    cudaGetSymbolAddress((void**)&bsum, d_bsum);
    cudaGetSymbolAddress((void**)&cols, d_cols);

    cudaMemsetAsync(cnt, 0, (size_t)N * sizeof(int));
    cudaMemsetAsync(scal, 0, 4 * SSTR * sizeof(float));

    // CSR build
    count_kernel<<<(E + 255) / 256, 256>>>(EI, cnt, E);
    dinv_kernel<<<(N + 255) / 256, 256>>>(cnt, dinvp, N);
    int nb = (N + 1023) / 1024;
    blocksum_kernel<<<nb, 1024>>>(cnt, bsum, N);
    scanbsum_kernel<<<1, 32>>>(bsum, rowptr + N, nb);
    localscan_kernel<<<nb, 1024>>>(cnt, rowptr, bsum, N);
    fill_kernel<<<(E + 255) / 256, 256>>>(EI, cnt, dinvp, cols, wp, E);

    dim3 gg((N + 127) / 128, 1);
    const int VB = (n4 + 255) / 256;

    // opening + conv
    gemm_k128<1><<<gg, 256>>>(T, KopenW, Kopenb, Th, N, NH, bnOg, bnOb, bnOm, bnOv);
    gemm_k128<2><<<gg, 256>>>(Th, convW, convb, z, N, NH, bnAg, bnAb, bnAm, bnAv);
    // q/k of z -> slot 0
    gemm_k128<0><<<gg, 256>>>(z, Wq, bq, qb, N, NH, 0, 0, 0, 0);
    gemm_k128<0><<<gg, 256>>>(z, Wk, bk, kb, N, NH, 0, 0, 0, 0);

    for (int jj = 0; jj < 4; jj++) {
        if (jj > 0) {  // q/k of X_{jj-1} -> slot jj
            gemm_k128<0><<<gg, 256>>>(Xb + (jj - 1) * S, Wq, bq, qb + jj * S, N, NH, 0, 0, 0, 0);
            gemm_k128<0><<<gg, 256>>>(Xb + (jj - 1) * S, Wk, bk, kb + jj * S, N, NH, 0, 0, 0, 0);
        }
        // acts slot o at layer jj: z if o < 4-jj else X_{o-4+jj}; q/k cache idx 0 or o-3+jj
        const float *aq[4], *ak[4], *aa[4];
        for (int o = 0; o < 4; o++) {
            if (o < 4 - jj) { aq[o] = qb; ak[o] = kb; aa[o] = z; }
            else {
                int m = o - 4 + jj;             // X index
                aq[o] = qb + (m + 1) * S; ak[o] = kb + (m + 1) * S; aa[o] = Xb + m * S;
            }
        }
        float* sl = scal + jj * SSTR;
        attn_kernel<<<400, 256>>>(aq[0], aq[1], aq[2], aq[3], ak[0], ak[1], ak[2], ak[3],
                                  mha, sl, N);
        c_kernel<<<1, 32>>>(sl, sl + 16, 1.0f / (float)N);
        combine4<<<VB, 256>>>(aa[0], aa[1], aa[2], aa[3], sl + 16, T1, n4);

        gemm_k128<0><<<gg, 256>>>(T1, KR1W + jj * NH * NH, KR1b + jj * NH, A1, N, NH, 0, 0, 0, 0);
        gemm_k128<0><<<gg, 256>>>(T1, KR2W + jj * NH * NH, KR2b + jj * NH, A2, N, NH, 0, 0, 0, 0);
        gemm_k128<0><<<gg, 256>>>(Th, KRU0W + jj * NH * NH, KRU0b + jj * NH, AU, N, NH, 0, 0, 0, 0);

        float* X = Xb + jj * S;
        float* nr = sl + 20;
        float* pLP = sl + 31;
        reaction_epi<<<VB, 256>>>(T1, A1, A2, AU, bng + jj * NH, bnbp + jj * NH,
                                  bnm + jj * NH, bnv + jj * NH, X, R, P, nr, n4);
        for (int t = 0; t < 10; t++) {
            spmv_kernel<<<1184, 256>>>(rowptr, cols, wp, P, LP, Kappa + jj * NH, nr, pLP, t, N);
            upd_xr_kernel<<<VB, 256>>>(X, R, P, LP, nr, pLP, t, n4);
            upd_p_kernel<<<VB, 256>>>(P, R, nr, t, n4);
        }
    }
    gemm_k128<0><<<gg, 256>>>(Xb + 3 * S, KcloseW, Kcloseb, (float*)d_out, N, 40, 0, 0, 0, 0);
}

// round 4
// speedup vs baseline: 1.3939x; 1.3939x over previous
#include <cuda_runtime.h>
#include <cuda_bf16.h>
#include <math.h>
#include <stdint.h>

#define NH 128
#define MAXN 50000
#define MAXE 800000
#define HCOEF 0.1f
#define EPS_BN 1e-5f
#define SSTR 48

// ---------------- device scratch ----------------
__device__ float d_Th[MAXN * NH];
__device__ float d_z[MAXN * NH];
__device__ float d_Xb[4][MAXN * NH];
__device__ float d_qb[4][MAXN * NH];
__device__ float d_kb[4][MAXN * NH];
__device__ float d_T1[MAXN * NH];
__device__ float d_A1[MAXN * NH];
__device__ float d_A2[MAXN * NH];
__device__ float d_AU[MAXN * NH];
__device__ float d_R[MAXN * NH];
__device__ float d_P[MAXN * NH];
__device__ float d_LP[MAXN * NH];
__device__ int   d_rowptr[MAXN + 1];
__device__ int   d_cnt[MAXN];
__device__ int   d_bsum[64];
__device__ int   d_cols[MAXE];
__device__ float d_w[MAXE];
__device__ float d_dinv[MAXN];
__device__ float d_scal[4 * SSTR];

__device__ __forceinline__ float block_reduce_sum(float v) {
    __shared__ float sh[32];
    int lane = threadIdx.x & 31, wid = threadIdx.x >> 5;
#pragma unroll
    for (int o = 16; o; o >>= 1) v += __shfl_xor_sync(0xffffffffu, v, o);
    if (lane == 0) sh[wid] = v;
    __syncthreads();
    float s = 0.f;
    if (threadIdx.x == 0) {
        int nw = (blockDim.x + 31) >> 5;
        for (int i = 0; i < nw; i++) s += sh[i];
    }
    return s;
}

// ---------------- CSR build ----------------
__global__ void count_kernel(const int* __restrict__ EI, int* __restrict__ cnt, int E) {
    int e = blockIdx.x * blockDim.x + threadIdx.x;
    if (e >= E) return;
    int r = EI[e], c = EI[E + e];
    if (r != c) atomicAdd(&cnt[r], 1);
}
__global__ void dinv_kernel(const int* __restrict__ cnt, float* __restrict__ dinv, int N) {
    int i = blockIdx.x * blockDim.x + threadIdx.x;
    if (i >= N) return;
    int d = cnt[i];
    dinv[i] = (d > 0) ? rsqrtf((float)d) : 0.f;
}
__global__ void blocksum_kernel(const int* __restrict__ cnt, int* __restrict__ bsum, int N) {
    __shared__ int sh[1024];
    int i = blockIdx.x * 1024 + threadIdx.x;
    sh[threadIdx.x] = (i < N) ? cnt[i] : 0;
    __syncthreads();
    for (int o = 512; o; o >>= 1) {
        if (threadIdx.x < o) sh[threadIdx.x] += sh[threadIdx.x + o];
        __syncthreads();
    }
    if (threadIdx.x == 0) bsum[blockIdx.x] = sh[0];
}
__global__ void scanbsum_kernel(int* __restrict__ bsum, int* __restrict__ rowptrN, int nb) {
    if (threadIdx.x == 0) {
        int run = 0;
        for (int i = 0; i < nb; i++) { int t = bsum[i]; bsum[i] = run; run += t; }
        *rowptrN = run;
    }
}
__global__ void localscan_kernel(int* __restrict__ cnt, int* __restrict__ rowptr,
                                 const int* __restrict__ bsum, int N) {
    __shared__ int sh[1024];
    int i = blockIdx.x * 1024 + threadIdx.x;
    int x = (i < N) ? cnt[i] : 0;
    sh[threadIdx.x] = x;
    __syncthreads();
    for (int off = 1; off < 1024; off <<= 1) {
        int t = (threadIdx.x >= off) ? sh[threadIdx.x - off] : 0;
        __syncthreads();
        sh[threadIdx.x] += t;
        __syncthreads();
    }
    if (i < N) { int excl = sh[threadIdx.x] - x + bsum[blockIdx.x]; rowptr[i] = excl; cnt[i] = excl; }
}
__global__ void fill_kernel(const int* __restrict__ EI, int* __restrict__ cursor,
                            const float* __restrict__ dinv, int* __restrict__ cols,
                            float* __restrict__ w, int E) {
    int e = blockIdx.x * blockDim.x + threadIdx.x;
    if (e >= E) return;
    int r = EI[e], c = EI[E + e];
    if (r != c) {
        int pos = atomicAdd(&cursor[r], 1);
        cols[pos] = c;
        w[pos] = -dinv[r] * dinv[c];
    }
}

// ---------------- tensor-core GEMM (split-bf16): C = A[N,128] @ W[Oc,128]^T + bias ----------------
__device__ __forceinline__ void mma16816(float* c, const uint32_t* a, const uint32_t* b) {
    asm volatile(
        "mma.sync.aligned.m16n8k16.row.col.f32.bf16.bf16.f32 "
        "{%0,%1,%2,%3}, {%4,%5,%6,%7}, {%8,%9}, {%0,%1,%2,%3};\n"
        : "+f"(c[0]), "+f"(c[1]), "+f"(c[2]), "+f"(c[3])
        : "r"(a[0]), "r"(a[1]), "r"(a[2]), "r"(a[3]), "r"(b[0]), "r"(b[1]));
}
__device__ __forceinline__ void ldsm4(uint32_t* d, uint32_t addr) {
    asm volatile("ldmatrix.sync.aligned.m8n8.x4.shared.b16 {%0,%1,%2,%3}, [%4];"
                 : "=r"(d[0]), "=r"(d[1]), "=r"(d[2]), "=r"(d[3]) : "r"(addr));
}
__device__ __forceinline__ void ldsm2(uint32_t* d, uint32_t addr) {
    asm volatile("ldmatrix.sync.aligned.m8n8.x2.shared.b16 {%0,%1}, [%2];"
                 : "=r"(d[0]), "=r"(d[1]) : "r"(addr));
}

#define LDW 136                           // padded row width (bf16 elems)
#define TILE_BYTES (128 * LDW * 2)        // one 128x136 bf16 plane
#define GSMEM (4 * TILE_BYTES)            // Ah, Al, Wh, Wl

// EPI: 0 bias, 1 BN+ELU, 2 BN+ReLU
template <int EPI>
__global__ __launch_bounds__(256, 1) void gemm_tc(
    const float* __restrict__ A, const float* __restrict__ W,
    const float* __restrict__ bias, float* __restrict__ C, int N, int Oc,
    const float* __restrict__ bng, const float* __restrict__ bnb,
    const float* __restrict__ bnm, const float* __restrict__ bnv) {
    extern __shared__ __align__(16) char smem_raw[];
    __nv_bfloat16* Ah = (__nv_bfloat16*)smem_raw;
    __nv_bfloat16* Al = Ah + 128 * LDW;
    __nv_bfloat16* Wh = Al + 128 * LDW;
    __nv_bfloat16* Wl = Wh + 128 * LDW;

    const int tid = threadIdx.x;
    const int brow = blockIdx.x * 128;

    // load + split-convert A and W into smem
#pragma unroll
    for (int i = 0; i < 16; i++) {
        int fl = i * 256 + tid;          // 0..4095
        int row = fl >> 5;               // 32 float4 per row
        int c4 = (fl & 31) << 2;
        float4 av = make_float4(0.f, 0.f, 0.f, 0.f);
        int gr = brow + row;
        if (gr < N) av = *(const float4*)(A + (size_t)gr * 128 + c4);
        float4 wv = make_float4(0.f, 0.f, 0.f, 0.f);
        if (row < Oc) wv = *(const float4*)(W + (size_t)row * 128 + c4);
        float aval[4] = {av.x, av.y, av.z, av.w};
        float wval[4] = {wv.x, wv.y, wv.z, wv.w};
        int base = row * LDW + c4;
#pragma unroll
        for (int u = 0; u < 4; u++) {
            __nv_bfloat16 h = __float2bfloat16(aval[u]);
            Ah[base + u] = h;
            Al[base + u] = __float2bfloat16(aval[u] - __bfloat162float(h));
            __nv_bfloat16 wh = __float2bfloat16(wval[u]);
            Wh[base + u] = wh;
            Wl[base + u] = __float2bfloat16(wval[u] - __bfloat162float(wh));
        }
    }
    __syncthreads();

    const int w = tid >> 5, lane = tid & 31;
    const int wm = w >> 2, wn = w & 3;   // warp tile: rows [wm*64,+64), cols [wn*32,+32)

    float acc[4][4][4];
#pragma unroll
    for (int mt = 0; mt < 4; mt++)
#pragma unroll
        for (int nt = 0; nt < 4; nt++)
#pragma unroll
            for (int u = 0; u < 4; u++) acc[mt][nt][u] = 0.f;

    uint32_t sAh = (uint32_t)__cvta_generic_to_shared(Ah);
    uint32_t sAl = (uint32_t)__cvta_generic_to_shared(Al);
    uint32_t sWh = (uint32_t)__cvta_generic_to_shared(Wh);
    uint32_t sWl = (uint32_t)__cvta_generic_to_shared(Wl);
    uint32_t aBase[3] = {sAh, sAl, sAh};
    uint32_t wBase[3] = {sWh, sWh, sWl};

#pragma unroll
    for (int p = 0; p < 3; p++) {
        uint32_t ab = aBase[p], wb = wBase[p];
#pragma unroll
        for (int kk = 0; kk < 8; kk++) {
            uint32_t bfr[4][2];
            {
                int r = lane & 7, sel = (lane >> 3) & 1;
                int kcol = kk * 16 + sel * 8;
#pragma unroll
                for (int nt = 0; nt < 4; nt++) {
                    int row = wn * 32 + nt * 8 + r;
                    ldsm2(bfr[nt], wb + (uint32_t)(row * LDW + kcol) * 2);
                }
            }
#pragma unroll
            for (int mt = 0; mt < 4; mt++) {
                uint32_t afr[4];
                int q = lane >> 3, r = lane & 7;
                int row = wm * 64 + mt * 16 + (q & 1) * 8 + r;
                int kcol = kk * 16 + (q >> 1) * 8;
                ldsm4(afr, ab + (uint32_t)(row * LDW + kcol) * 2);
#pragma unroll
                for (int nt = 0; nt < 4; nt++)
                    mma16816(acc[mt][nt], afr, bfr[nt]);
            }
        }
    }

    // epilogue
    const int g = lane >> 2, t2 = (lane & 3) * 2;
#pragma unroll
    for (int mt = 0; mt < 4; mt++) {
#pragma unroll
        for (int nt = 0; nt < 4; nt++) {
            int col0 = wn * 32 + nt * 8 + t2;
#pragma unroll
            for (int half = 0; half < 2; half++) {
                int row = brow + wm * 64 + mt * 16 + g + half * 8;
                if (row >= N) continue;
#pragma unroll
                for (int u = 0; u < 2; u++) {
                    int col = col0 + u;
                    if (col >= Oc) continue;
                    float x = acc[mt][nt][half * 2 + u] + bias[col];
                    if (EPI) {
                        float s = bng[col] * rsqrtf(bnv[col] + EPS_BN);
                        x = (x - bnm[col]) * s + bnb[col];
                        if (EPI == 1) x = (x > 0.f) ? x : expm1f(x);
                        else x = fmaxf(x, 0.f);
                    }
                    C[(size_t)row * Oc + col] = x;
                }
            }
        }
    }
}

// ---------------- attention stats ----------------
__global__ void attn_kernel(const float* __restrict__ q0, const float* __restrict__ q1,
                            const float* __restrict__ q2, const float* __restrict__ q3,
                            const float* __restrict__ k0, const float* __restrict__ k1,
                            const float* __restrict__ k2, const float* __restrict__ k3,
                            const float* __restrict__ mha, float* __restrict__ Cm, int N) {
    const float scale = 0.08838834764831845f;
    float rfac = fmaxf(mha[0], 0.f);
    int lane = threadIdx.x & 31, wid = threadIdx.x >> 5;
    int gw = blockIdx.x * (blockDim.x >> 5) + wid;
    int tw = gridDim.x * (blockDim.x >> 5);
    const float* qs[4] = {q0, q1, q2, q3};
    const float* ks[4] = {k0, k1, k2, k3};
    float acc[16];
#pragma unroll
    for (int m = 0; m < 16; m++) acc[m] = 0.f;
    for (int n = gw; n < N; n += tw) {
        float4 qv[4], kv[4];
#pragma unroll
        for (int s = 0; s < 4; s++) {
            qv[s] = *(const float4*)(qs[s] + (size_t)n * NH + lane * 4);
            kv[s] = *(const float4*)(ks[s] + (size_t)n * NH + lane * 4);
        }
        float sc[16];
#pragma unroll
        for (int i = 0; i < 4; i++)
#pragma unroll
            for (int j = 0; j < 4; j++) {
                float4 a = qv[i], b = kv[j];
                sc[i * 4 + j] = a.x * b.x + a.y * b.y + a.z * b.z + a.w * b.w;
            }
#pragma unroll
        for (int m = 0; m < 16; m++) {
            float v = sc[m];
#pragma unroll
            for (int o = 16; o; o >>= 1) v += __shfl_xor_sync(0xffffffffu, v, o);
            sc[m] = v * scale;
        }
        if (lane == 0) {
#pragma unroll
            for (int i = 0; i < 4; i++) {
                float s0 = sc[i * 4], s1 = sc[i * 4 + 1], s2 = sc[i * 4 + 2], s3 = sc[i * 4 + 3];
                float mx = fmaxf(fmaxf(s0, s1), fmaxf(s2, s3));
                float e0 = expf(s0 - mx), e1 = expf(s1 - mx), e2 = expf(s2 - mx), e3 = expf(s3 - mx);
                float inv = 1.f / (e0 + e1 + e2 + e3);
                acc[i * 4 + 0] += logf(e0 * inv * rfac + 1e-4f);
                acc[i * 4 + 1] += logf(e1 * inv * rfac + 1e-4f);
                acc[i * 4 + 2] += logf(e2 * inv * rfac + 1e-4f);
                acc[i * 4 + 3] += logf(e3 * inv * rfac + 1e-4f);
            }
        }
    }
    __shared__ float sh[8][16];
    if (lane == 0)
#pragma unroll
        for (int m = 0; m < 16; m++) sh[wid][m] = acc[m];
    __syncthreads();
    int nw = blockDim.x >> 5;
    if (threadIdx.x < 16) {
        float s = 0.f;
        for (int w2 = 0; w2 < nw; w2++) s += sh[w2][threadIdx.x];
        atomicAdd(&Cm[threadIdx.x], s);
    }
}

__global__ void c_kernel(const float* __restrict__ CmAcc, float* __restrict__ c, float Ninv) {
    if (threadIdx.x == 0) {
        float M[16];
        for (int m = 0; m < 16; m++) M[m] = CmAcc[m] * Ninv;
        float cc[4], s = 0.f;
        for (int j = 0; j < 4; j++) { cc[j] = 0.5f * (M[12 + j] + M[j * 4 + 3]); s += cc[j]; }
        float invs = 1.f / s;
        for (int j = 0; j < 4; j++) c[j] = cc[j] * invs;
    }
}

__global__ void combine4(const float* __restrict__ a0, const float* __restrict__ a1,
                         const float* __restrict__ a2, const float* __restrict__ a3,
                         const float* __restrict__ c, float* __restrict__ out, int n4) {
    int i = blockIdx.x * blockDim.x + threadIdx.x;
    if (i >= n4) return;
    float c0 = c[0], c1 = c[1], c2 = c[2], c3 = c[3];
    float4 v0 = ((const float4*)a0)[i], v1 = ((const float4*)a1)[i];
    float4 v2 = ((const float4*)a2)[i], v3 = ((const float4*)a3)[i];
    float4 o;
    o.x = c0 * v0.x + c1 * v1.x + c2 * v2.x + c3 * v3.x;
    o.y = c0 * v0.y + c1 * v1.y + c2 * v2.y + c3 * v3.y;
    o.z = c0 * v0.z + c1 * v1.z + c2 * v2.z + c3 * v3.z;
    o.w = c0 * v0.w + c1 * v1.w + c2 * v2.w + c3 * v3.w;
    ((float4*)out)[i] = o;
}

__global__ void reaction_epi(const float* __restrict__ T1, const float* __restrict__ A1,
                             const float* __restrict__ A2, const float* __restrict__ AU,
                             const float* __restrict__ bng, const float* __restrict__ bnb,
                             const float* __restrict__ bnm, const float* __restrict__ bnv,
                             float* __restrict__ X, float* __restrict__ R, float* __restrict__ P,
                             float* __restrict__ nr0, int n4) {
    int i = blockIdx.x * blockDim.x + threadIdx.x;
    float ss = 0.f;
    if (i < n4) {
        int col = (i << 2) & (NH - 1);
        float4 t1 = ((const float4*)T1)[i], a1 = ((const float4*)A1)[i];
        float4 a2 = ((const float4*)A2)[i], au = ((const float4*)AU)[i];
        float tt[4] = {t1.x, t1.y, t1.z, t1.w}, aa1[4] = {a1.x, a1.y, a1.z, a1.w};
        float aa2[4] = {a2.x, a2.y, a2.z, a2.w}, aau[4] = {au.x, au.y, au.z, au.w};
        float v[4];
#pragma unroll
        for (int u = 0; u < 4; u++) {
            int cl = col + u;
            float d2 = fminf(fmaxf(aa2[u], -1.f), 1.f);
            float y = tt[u] + HCOEF * (aa1[u] + aau[u] + tt[u] * d2);
            float s = bng[cl] * rsqrtf(bnv[cl] + EPS_BN);
            y = (y - bnm[cl]) * s + bnb[cl];
            y = (y > 0.f) ? y : expm1f(y);
            v[u] = y;
            ss += y * y;
        }
        float4 o = make_float4(v[0], v[1], v[2], v[3]);
        ((float4*)X)[i] = o; ((float4*)R)[i] = o; ((float4*)P)[i] = o;
    }
    float tot = block_reduce_sum(ss);
    if (threadIdx.x == 0) atomicAdd(nr0, tot);
}

// ---------------- CG ----------------
__global__ void spmv_kernel(const int* __restrict__ rowptr, const int* __restrict__ cols,
                            const float* __restrict__ w, const float* __restrict__ P,
                            float* __restrict__ LP, const float* __restrict__ Kap,
                            const float* __restrict__ nr, float* __restrict__ pLP,
                            int t, int N) {
    for (int j = 1; j <= t; j++)
        if (nr[j] < 1e-5f) return;
    int lane = threadIdx.x & 31, wid = threadIdx.x >> 5;
    int gw = blockIdx.x * (blockDim.x >> 5) + wid;
    int tw = gridDim.x * (blockDim.x >> 5);
    float4 kd;
    {
        float4 kk = *(const float4*)(Kap + lane * 4);
        kd.x = fminf(fmaxf(kk.x, 0.f), 1.f); kd.y = fminf(fmaxf(kk.y, 0.f), 1.f);
        kd.z = fminf(fmaxf(kk.z, 0.f), 1.f); kd.w = fminf(fmaxf(kk.w, 0.f), 1.f);
    }
    float dot = 0.f;
    for (int r = gw; r < N; r += tw) {
        int e0 = rowptr[r], e1 = rowptr[r + 1];
        float4 acc = make_float4(0.f, 0.f, 0.f, 0.f);
        for (int e = e0; e < e1; e++) {
            int c = __ldg(&cols[e]);
            float wt = __ldg(&w[e]);
            float4 y = *(const float4*)(P + (size_t)c * NH + lane * 4);
            acc.x = fmaf(wt, y.x, acc.x); acc.y = fmaf(wt, y.y, acc.y);
            acc.z = fmaf(wt, y.z, acc.z); acc.w = fmaf(wt, y.w, acc.w);
        }
        float4 p = *(const float4*)(P + (size_t)r * NH + lane * 4);
        float4 lp;
        lp.x = p.x + HCOEF * ((p.x + acc.x) * kd.x);
        lp.y = p.y + HCOEF * ((p.y + acc.y) * kd.y);
        lp.z = p.z + HCOEF * ((p.z + acc.z) * kd.z);
        lp.w = p.w + HCOEF * ((p.w + acc.w) * kd.w);
        *(float4*)(LP + (size_t)r * NH + lane * 4) = lp;
        dot += p.x * lp.x + p.y * lp.y + p.z * lp.z + p.w * lp.w;
    }
    float tot = block_reduce_sum(dot);
    if (threadIdx.x == 0) atomicAdd(&pLP[t], tot);
}

__global__ void upd_xr_kernel(float* __restrict__ X, float* __restrict__ R,
                              const float* __restrict__ P, const float* __restrict__ LP,
                              float* __restrict__ nr, const float* __restrict__ pLP,
                              int t, int n4) {
    for (int j = 1; j <= t; j++)
        if (nr[j] < 1e-5f) return;
    float alpha = nr[t] / (pLP[t] + 1e-6f);
    int i = blockIdx.x * blockDim.x + threadIdx.x;
    float ss = 0.f;
    if (i < n4) {
        float4 p = ((const float4*)P)[i], lp = ((const float4*)LP)[i];
        float4 x = ((float4*)X)[i], r = ((float4*)R)[i];
        x.x += alpha * p.x; x.y += alpha * p.y; x.z += alpha * p.z; x.w += alpha * p.w;
        r.x -= alpha * lp.x; r.y -= alpha * lp.y; r.z -= alpha * lp.z; r.w -= alpha * lp.w;
        ((float4*)X)[i] = x; ((float4*)R)[i] = r;
        ss = r.x * r.x + r.y * r.y + r.z * r.z + r.w * r.w;
    }
    float tot = block_reduce_sum(ss);
    if (threadIdx.x == 0) atomicAdd(&nr[t + 1], tot);
}

__global__ void upd_p_kernel(float* __restrict__ P, const float* __restrict__ R,
                             const float* __restrict__ nr, int t, int n4) {
    for (int j = 1; j <= t + 1; j++)
        if (nr[j] < 1e-5f) return;
    float beta = nr[t + 1] / (nr[t] + 1e-6f);
    int i = blockIdx.x * blockDim.x + threadIdx.x;
    if (i >= n4) return;
    float4 p = ((float4*)P)[i];
    float4 r = ((const float4*)R)[i];
    p.x = r.x + beta * p.x; p.y = r.y + beta * p.y;
    p.z = r.z + beta * p.z; p.w = r.w + beta * p.w;
    ((float4*)P)[i] = p;
}

// ---------------- host ----------------
extern "C" void kernel_launch(void* const* d_in, const int* in_sizes, int n_in,
                              void* d_out, int out_size) {
    const float* T      = (const float*)d_in[0];
    const int*   EI     = (const int*)d_in[1];
    const float* KopenW = (const float*)d_in[2];
    const float* Kopenb = (const float*)d_in[3];
    const float* bnOg   = (const float*)d_in[4];
    const float* bnOb   = (const float*)d_in[5];
    const float* bnOm   = (const float*)d_in[6];
    const float* bnOv   = (const float*)d_in[7];
    const float* convW  = (const float*)d_in[8];
    const float* convb  = (const float*)d_in[9];
    const float* bnAg   = (const float*)d_in[10];
    const float* bnAb   = (const float*)d_in[11];
    const float* bnAm   = (const float*)d_in[12];
    const float* bnAv   = (const float*)d_in[13];
    const float* Wq     = (const float*)d_in[14];
    const float* bq     = (const float*)d_in[15];
    const float* Wk     = (const float*)d_in[16];
    const float* bk     = (const float*)d_in[17];
    const float* mha    = (const float*)d_in[18];
    const float* KR1W   = (const float*)d_in[19];
    const float* KR1b   = (const float*)d_in[20];
    const float* KR2W   = (const float*)d_in[21];
    const float* KR2b   = (const float*)d_in[22];
    const float* KRU0W  = (const float*)d_in[23];
    const float* KRU0b  = (const float*)d_in[24];
    const float* bng    = (const float*)d_in[25];
    const float* bnbp   = (const float*)d_in[26];
    const float* bnm    = (const float*)d_in[27];
    const float* bnv    = (const float*)d_in[28];
    const float* Kappa  = (const float*)d_in[29];
    const float* KcloseW= (const float*)d_in[30];
    const float* Kcloseb= (const float*)d_in[31];

    const int N = in_sizes[0] / NH;
    const int E = in_sizes[1] / 2;
    const int n4 = N * (NH / 4);
    const size_t S = (size_t)MAXN * NH;

    float *Th, *z, *Xb, *qb, *kb, *T1, *A1, *A2, *AU, *R, *P, *LP, *dinvp, *wp, *scal;
    int *rowptr, *cnt, *bsum, *cols;
    cudaGetSymbolAddress((void**)&Th, d_Th);
    cudaGetSymbolAddress((void**)&z, d_z);
    cudaGetSymbolAddress((void**)&Xb, d_Xb);
    cudaGetSymbolAddress((void**)&qb, d_qb);
    cudaGetSymbolAddress((void**)&kb, d_kb);
    cudaGetSymbolAddress((void**)&T1, d_T1);
    cudaGetSymbolAddress((void**)&A1, d_A1);
    cudaGetSymbolAddress((void**)&A2, d_A2);
    cudaGetSymbolAddress((void**)&AU, d_AU);
    cudaGetSymbolAddress((void**)&R, d_R);
    cudaGetSymbolAddress((void**)&P, d_P);
    cudaGetSymbolAddress((void**)&LP, d_LP);
    cudaGetSymbolAddress((void**)&dinvp, d_dinv);
    cudaGetSymbolAddress((void**)&wp, d_w);
    cudaGetSymbolAddress((void**)&scal, d_scal);
    cudaGetSymbolAddress((void**)&rowptr, d_rowptr);
    cudaGetSymbolAddress((void**)&cnt, d_cnt);
    cudaGetSymbolAddress((void**)&bsum, d_bsum);
    cudaGetSymbolAddress((void**)&cols, d_cols);

    static bool attr_done = false;
    if (!attr_done) {
        cudaFuncSetAttribute(gemm_tc<0>, cudaFuncAttributeMaxDynamicSharedMemorySize, GSMEM);
        cudaFuncSetAttribute(gemm_tc<1>, cudaFuncAttributeMaxDynamicSharedMemorySize, GSMEM);
        cudaFuncSetAttribute(gemm_tc<2>, cudaFuncAttributeMaxDynamicSharedMemorySize, GSMEM);
        attr_done = true;
    }

    cudaMemsetAsync(cnt, 0, (size_t)N * sizeof(int));
    cudaMemsetAsync(scal, 0, 4 * SSTR * sizeof(float));

    count_kernel<<<(E + 255) / 256, 256>>>(EI, cnt, E);
    dinv_kernel<<<(N + 255) / 256, 256>>>(cnt, dinvp, N);
    int nb = (N + 1023) / 1024;
    blocksum_kernel<<<nb, 1024>>>(cnt, bsum, N);
    scanbsum_kernel<<<1, 32>>>(bsum, rowptr + N, nb);
    localscan_kernel<<<nb, 1024>>>(cnt, rowptr, bsum, N);
    fill_kernel<<<(E + 255) / 256, 256>>>(EI, cnt, dinvp, cols, wp, E);

    const int GB = (N + 127) / 128;
    const int VB = (n4 + 255) / 256;

    gemm_tc<1><<<GB, 256, GSMEM>>>(T, KopenW, Kopenb, Th, N, NH, bnOg, bnOb, bnOm, bnOv);
    gemm_tc<2><<<GB, 256, GSMEM>>>(Th, convW, convb, z, N, NH, bnAg, bnAb, bnAm, bnAv);
    gemm_tc<0><<<GB, 256, GSMEM>>>(z, Wq, bq, qb, N, NH, 0, 0, 0, 0);
    gemm_tc<0><<<GB, 256, GSMEM>>>(z, Wk, bk, kb, N, NH, 0, 0, 0, 0);

    for (int jj = 0; jj < 4; jj++) {
        if (jj > 0) {
            gemm_tc<0><<<GB, 256, GSMEM>>>(Xb + (jj - 1) * S, Wq, bq, qb + jj * S, N, NH, 0, 0, 0, 0);
            gemm_tc<0><<<GB, 256, GSMEM>>>(Xb + (jj - 1) * S, Wk, bk, kb + jj * S, N, NH, 0, 0, 0, 0);
        }
        const float *aq[4], *ak[4], *aa[4];
        for (int o = 0; o < 4; o++) {
            if (o < 4 - jj) { aq[o] = qb; ak[o] = kb; aa[o] = z; }
            else {
                int m = o - 4 + jj;
                aq[o] = qb + (m + 1) * S; ak[o] = kb + (m + 1) * S; aa[o] = Xb + m * S;
            }
        }
        float* sl = scal + jj * SSTR;
        attn_kernel<<<400, 256>>>(aq[0], aq[1], aq[2], aq[3], ak[0], ak[1], ak[2], ak[3],
                                  mha, sl, N);
        c_kernel<<<1, 32>>>(sl, sl + 16, 1.0f / (float)N);
        combine4<<<VB, 256>>>(aa[0], aa[1], aa[2], aa[3], sl + 16, T1, n4);

        gemm_tc<0><<<GB, 256, GSMEM>>>(T1, KR1W + jj * NH * NH, KR1b + jj * NH, A1, N, NH, 0, 0, 0, 0);
        gemm_tc<0><<<GB, 256, GSMEM>>>(T1, KR2W + jj * NH * NH, KR2b + jj * NH, A2, N, NH, 0, 0, 0, 0);
        gemm_tc<0><<<GB, 256, GSMEM>>>(Th, KRU0W + jj * NH * NH, KRU0b + jj * NH, AU, N, NH, 0, 0, 0, 0);

        float* X = Xb + jj * S;
        float* nr = sl + 20;
        float* pLP = sl + 31;
        reaction_epi<<<VB, 256>>>(T1, A1, A2, AU, bng + jj * NH, bnbp + jj * NH,
                                  bnm + jj * NH, bnv + jj * NH, X, R, P, nr, n4);
        for (int t = 0; t < 10; t++) {
            spmv_kernel<<<1184, 256>>>(rowptr, cols, wp, P, LP, Kappa + jj * NH, nr, pLP, t, N);
            upd_xr_kernel<<<VB, 256>>>(X, R, P, LP, nr, pLP, t, n4);
            upd_p_kernel<<<VB, 256>>>(P, R, nr, t, n4);
        }
    }
    gemm_tc<0><<<GB, 256, GSMEM>>>(Xb + 3 * S, KcloseW, Kcloseb, (float*)d_out, N, 40, 0, 0, 0, 0);
}

// round 5
// speedup vs baseline: 1.5224x; 1.0922x over previous
#include <cuda_runtime.h>
#include <cuda_bf16.h>
#include <math.h>
#include <stdint.h>

#define NH 128
#define MAXN 50000
#define MAXE 800000
#define HCOEF 0.1f
#define EPS_BN 1e-5f
#define SSTR 48
#define NBLK 148
#define CGT 1024

// ---------------- device scratch ----------------
__device__ float d_Th[MAXN * NH];
__device__ float d_z[MAXN * NH];
__device__ float d_Xb[4][MAXN * NH];
__device__ float d_qb[4][MAXN * NH];
__device__ float d_kb[4][MAXN * NH];
__device__ float d_T1[MAXN * NH];
__device__ float d_A1[MAXN * NH];
__device__ float d_A2[MAXN * NH];
__device__ float d_AU[MAXN * NH];
__device__ float d_R[MAXN * NH];
__device__ float d_P[MAXN * NH];
__device__ float d_LP[MAXN * NH];
__device__ int   d_rowptr[MAXN + 1];
__device__ int   d_cnt[MAXN];
__device__ int   d_bsum[64];
__device__ int   d_cols[MAXE];
__device__ float d_w[MAXE];
__device__ float d_dinv[MAXN];
__device__ float d_scal[4 * SSTR];
__device__ volatile unsigned d_barcnt = 0;
__device__ volatile unsigned d_bargen = 0;

__device__ __forceinline__ float block_reduce_sum(float v) {
    __shared__ float sh[32];
    int lane = threadIdx.x & 31, wid = threadIdx.x >> 5;
#pragma unroll
    for (int o = 16; o; o >>= 1) v += __shfl_xor_sync(0xffffffffu, v, o);
    if (lane == 0) sh[wid] = v;
    __syncthreads();
    float s = 0.f;
    if (threadIdx.x == 0) {
        int nw = (blockDim.x + 31) >> 5;
        for (int i = 0; i < nw; i++) s += sh[i];
    }
    return s;
}

__device__ __forceinline__ void grid_barrier() {
    __syncthreads();
    if (threadIdx.x == 0) {
        unsigned g = d_bargen;
        __threadfence();
        unsigned a = atomicInc((unsigned*)&d_barcnt, NBLK - 1);
        if (a == NBLK - 1) {
            __threadfence();
            d_bargen = g + 1;
        } else {
            while (d_bargen == g) __nanosleep(128);
        }
        __threadfence();
    }
    __syncthreads();
}

// ---------------- CSR build ----------------
__global__ void count_kernel(const int* __restrict__ EI, int* __restrict__ cnt, int E) {
    int e = blockIdx.x * blockDim.x + threadIdx.x;
    if (e >= E) return;
    int r = EI[e], c = EI[E + e];
    if (r != c) atomicAdd(&cnt[r], 1);
}
__global__ void dinv_kernel(const int* __restrict__ cnt, float* __restrict__ dinv, int N) {
    int i = blockIdx.x * blockDim.x + threadIdx.x;
    if (i >= N) return;
    int d = cnt[i];
    dinv[i] = (d > 0) ? rsqrtf((float)d) : 0.f;
}
__global__ void blocksum_kernel(const int* __restrict__ cnt, int* __restrict__ bsum, int N) {
    __shared__ int sh[1024];
    int i = blockIdx.x * 1024 + threadIdx.x;
    sh[threadIdx.x] = (i < N) ? cnt[i] : 0;
    __syncthreads();
    for (int o = 512; o; o >>= 1) {
        if (threadIdx.x < o) sh[threadIdx.x] += sh[threadIdx.x + o];
        __syncthreads();
    }
    if (threadIdx.x == 0) bsum[blockIdx.x] = sh[0];
}
__global__ void scanbsum_kernel(int* __restrict__ bsum, int* __restrict__ rowptrN, int nb) {
    if (threadIdx.x == 0) {
        int run = 0;
        for (int i = 0; i < nb; i++) { int t = bsum[i]; bsum[i] = run; run += t; }
        *rowptrN = run;
    }
}
__global__ void localscan_kernel(int* __restrict__ cnt, int* __restrict__ rowptr,
                                 const int* __restrict__ bsum, int N) {
    __shared__ int sh[1024];
    int i = blockIdx.x * 1024 + threadIdx.x;
    int x = (i < N) ? cnt[i] : 0;
    sh[threadIdx.x] = x;
    __syncthreads();
    for (int off = 1; off < 1024; off <<= 1) {
        int t = (threadIdx.x >= off) ? sh[threadIdx.x - off] : 0;
        __syncthreads();
        sh[threadIdx.x] += t;
        __syncthreads();
    }
    if (i < N) { int excl = sh[threadIdx.x] - x + bsum[blockIdx.x]; rowptr[i] = excl; cnt[i] = excl; }
}
__global__ void fill_kernel(const int* __restrict__ EI, int* __restrict__ cursor,
                            const float* __restrict__ dinv, int* __restrict__ cols,
                            float* __restrict__ w, int E) {
    int e = blockIdx.x * blockDim.x + threadIdx.x;
    if (e >= E) return;
    int r = EI[e], c = EI[E + e];
    if (r != c) {
        int pos = atomicAdd(&cursor[r], 1);
        cols[pos] = c;
        w[pos] = -dinv[r] * dinv[c];
    }
}

// ---------------- tensor-core GEMM (split-bf16), 64-row tiles, optional dual ----------------
__device__ __forceinline__ void mma16816(float* c, const uint32_t* a, const uint32_t* b) {
    asm volatile(
        "mma.sync.aligned.m16n8k16.row.col.f32.bf16.bf16.f32 "
        "{%0,%1,%2,%3}, {%4,%5,%6,%7}, {%8,%9}, {%0,%1,%2,%3};\n"
        : "+f"(c[0]), "+f"(c[1]), "+f"(c[2]), "+f"(c[3])
        : "r"(a[0]), "r"(a[1]), "r"(a[2]), "r"(a[3]), "r"(b[0]), "r"(b[1]));
}
__device__ __forceinline__ void ldsm4(uint32_t* d, uint32_t addr) {
    asm volatile("ldmatrix.sync.aligned.m8n8.x4.shared.b16 {%0,%1,%2,%3}, [%4];"
                 : "=r"(d[0]), "=r"(d[1]), "=r"(d[2]), "=r"(d[3]) : "r"(addr));
}
__device__ __forceinline__ void ldsm2(uint32_t* d, uint32_t addr) {
    asm volatile("ldmatrix.sync.aligned.m8n8.x2.shared.b16 {%0,%1}, [%2];"
                 : "=r"(d[0]), "=r"(d[1]) : "r"(addr));
}

#define LDW 136
#define GSMEM ((2 * 64 + 2 * 128) * LDW * 2)  // Ah,Al 64xLDW; Wh,Wl 128xLDW = 104448

// EPI: 0 bias, 1 BN+ELU, 2 BN+ReLU.  blockIdx.y selects (W,bias,C) vs (W2,bias2,C2)
template <int EPI>
__global__ __launch_bounds__(256, 2) void gemm_tc(
    const float* __restrict__ A,
    const float* __restrict__ W, const float* __restrict__ bias, float* __restrict__ C,
    const float* __restrict__ W2, const float* __restrict__ bias2, float* __restrict__ C2,
    int N, int Oc,
    const float* __restrict__ bng, const float* __restrict__ bnb,
    const float* __restrict__ bnm, const float* __restrict__ bnv) {
    extern __shared__ __align__(16) char smem_raw[];
    __nv_bfloat16* Ah = (__nv_bfloat16*)smem_raw;
    __nv_bfloat16* Al = Ah + 64 * LDW;
    __nv_bfloat16* Wh = Al + 64 * LDW;
    __nv_bfloat16* Wl = Wh + 128 * LDW;

    const float* Wsel = blockIdx.y ? W2 : W;
    const float* bsel = blockIdx.y ? bias2 : bias;
    float* Csel = blockIdx.y ? C2 : C;

    const int tid = threadIdx.x;
    const int brow = blockIdx.x * 64;

    // load + split-convert A (64 rows)
#pragma unroll
    for (int i = 0; i < 8; i++) {
        int fl = i * 256 + tid;          // 0..2047
        int row = fl >> 5;
        int c4 = (fl & 31) << 2;
        float4 av = make_float4(0.f, 0.f, 0.f, 0.f);
        int gr = brow + row;
        if (gr < N) av = *(const float4*)(A + (size_t)gr * 128 + c4);
        float aval[4] = {av.x, av.y, av.z, av.w};
        int base = row * LDW + c4;
#pragma unroll
        for (int u = 0; u < 4; u++) {
            __nv_bfloat16 h = __float2bfloat16(aval[u]);
            Ah[base + u] = h;
            Al[base + u] = __float2bfloat16(aval[u] - __bfloat162float(h));
        }
    }
    // load + split-convert W (128 rows)
#pragma unroll
    for (int i = 0; i < 16; i++) {
        int fl = i * 256 + tid;          // 0..4095
        int row = fl >> 5;
        int c4 = (fl & 31) << 2;
        float4 wv = make_float4(0.f, 0.f, 0.f, 0.f);
        if (row < Oc) wv = *(const float4*)(Wsel + (size_t)row * 128 + c4);
        float wval[4] = {wv.x, wv.y, wv.z, wv.w};
        int base = row * LDW + c4;
#pragma unroll
        for (int u = 0; u < 4; u++) {
            __nv_bfloat16 h = __float2bfloat16(wval[u]);
            Wh[base + u] = h;
            Wl[base + u] = __float2bfloat16(wval[u] - __bfloat162float(h));
        }
    }
    __syncthreads();

    const int w = tid >> 5, lane = tid & 31;
    const int wm = w >> 2, wn = w & 3;   // warp tile rows [wm*32,+32), cols [wn*32,+32)

    float acc[2][4][4];
#pragma unroll
    for (int mt = 0; mt < 2; mt++)
#pragma unroll
        for (int nt = 0; nt < 4; nt++)
#pragma unroll
            for (int u = 0; u < 4; u++) acc[mt][nt][u] = 0.f;

    uint32_t sAh = (uint32_t)__cvta_generic_to_shared(Ah);
    uint32_t sAl = (uint32_t)__cvta_generic_to_shared(Al);
    uint32_t sWh = (uint32_t)__cvta_generic_to_shared(Wh);
    uint32_t sWl = (uint32_t)__cvta_generic_to_shared(Wl);
    uint32_t aBase[3] = {sAh, sAl, sAh};
    uint32_t wBase[3] = {sWh, sWh, sWl};

#pragma unroll
    for (int p = 0; p < 3; p++) {
        uint32_t ab = aBase[p], wb = wBase[p];
#pragma unroll
        for (int kk = 0; kk < 8; kk++) {
            uint32_t bfr[4][2];
            {
                int r = lane & 7, sel = (lane >> 3) & 1;
                int kcol = kk * 16 + sel * 8;
#pragma unroll
                for (int nt = 0; nt < 4; nt++) {
                    int row = wn * 32 + nt * 8 + r;
                    ldsm2(bfr[nt], wb + (uint32_t)(row * LDW + kcol) * 2);
                }
            }
#pragma unroll
            for (int mt = 0; mt < 2; mt++) {
                uint32_t afr[4];
                int q = lane >> 3, r = lane & 7;
                int row = wm * 32 + mt * 16 + (q & 1) * 8 + r;
                int kcol = kk * 16 + (q >> 1) * 8;
                ldsm4(afr, ab + (uint32_t)(row * LDW + kcol) * 2);
#pragma unroll
                for (int nt = 0; nt < 4; nt++)
                    mma16816(acc[mt][nt], afr, bfr[nt]);
            }
        }
    }

    const int g = lane >> 2, t2 = (lane & 3) * 2;
#pragma unroll
    for (int mt = 0; mt < 2; mt++) {
#pragma unroll
        for (int nt = 0; nt < 4; nt++) {
            int col0 = wn * 32 + nt * 8 + t2;
#pragma unroll
            for (int half = 0; half < 2; half++) {
                int row = brow + wm * 32 + mt * 16 + g + half * 8;
                if (row >= N) continue;
#pragma unroll
                for (int u = 0; u < 2; u++) {
                    int col = col0 + u;
                    if (col >= Oc) continue;
                    float x = acc[mt][nt][half * 2 + u] + bsel[col];
                    if (EPI) {
                        float s = bng[col] * rsqrtf(bnv[col] + EPS_BN);
                        x = (x - bnm[col]) * s + bnb[col];
                        if (EPI == 1) x = (x > 0.f) ? x : expm1f(x);
                        else x = fmaxf(x, 0.f);
                    }
                    Csel[(size_t)row * Oc + col] = x;
                }
            }
        }
    }
}

// ---------------- attention stats ----------------
__global__ void attn_kernel(const float* __restrict__ q0, const float* __restrict__ q1,
                            const float* __restrict__ q2, const float* __restrict__ q3,
                            const float* __restrict__ k0, const float* __restrict__ k1,
                            const float* __restrict__ k2, const float* __restrict__ k3,
                            const float* __restrict__ mha, float* __restrict__ Cm, int N) {
    const float scale = 0.08838834764831845f;
    float rfac = fmaxf(mha[0], 0.f);
    int lane = threadIdx.x & 31, wid = threadIdx.x >> 5;
    int gw = blockIdx.x * (blockDim.x >> 5) + wid;
    int tw = gridDim.x * (blockDim.x >> 5);
    const float* qs[4] = {q0, q1, q2, q3};
    const float* ks[4] = {k0, k1, k2, k3};
    float acc[16];
#pragma unroll
    for (int m = 0; m < 16; m++) acc[m] = 0.f;
    for (int n = gw; n < N; n += tw) {
        float4 qv[4], kv[4];
#pragma unroll
        for (int s = 0; s < 4; s++) {
            qv[s] = *(const float4*)(qs[s] + (size_t)n * NH + lane * 4);
            kv[s] = *(const float4*)(ks[s] + (size_t)n * NH + lane * 4);
        }
        float sc[16];
#pragma unroll
        for (int i = 0; i < 4; i++)
#pragma unroll
            for (int j = 0; j < 4; j++) {
                float4 a = qv[i], b = kv[j];
                sc[i * 4 + j] = a.x * b.x + a.y * b.y + a.z * b.z + a.w * b.w;
            }
#pragma unroll
        for (int m = 0; m < 16; m++) {
            float v = sc[m];
#pragma unroll
            for (int o = 16; o; o >>= 1) v += __shfl_xor_sync(0xffffffffu, v, o);
            sc[m] = v * scale;
        }
        if (lane == 0) {
#pragma unroll
            for (int i = 0; i < 4; i++) {
                float s0 = sc[i * 4], s1 = sc[i * 4 + 1], s2 = sc[i * 4 + 2], s3 = sc[i * 4 + 3];
                float mx = fmaxf(fmaxf(s0, s1), fmaxf(s2, s3));
                float e0 = expf(s0 - mx), e1 = expf(s1 - mx), e2 = expf(s2 - mx), e3 = expf(s3 - mx);
                float inv = 1.f / (e0 + e1 + e2 + e3);
                acc[i * 4 + 0] += logf(e0 * inv * rfac + 1e-4f);
                acc[i * 4 + 1] += logf(e1 * inv * rfac + 1e-4f);
                acc[i * 4 + 2] += logf(e2 * inv * rfac + 1e-4f);
                acc[i * 4 + 3] += logf(e3 * inv * rfac + 1e-4f);
            }
        }
    }
    __shared__ float sh[8][16];
    if (lane == 0)
#pragma unroll
        for (int m = 0; m < 16; m++) sh[wid][m] = acc[m];
    __syncthreads();
    int nw = blockDim.x >> 5;
    if (threadIdx.x < 16) {
        float s = 0.f;
        for (int w2 = 0; w2 < nw; w2++) s += sh[w2][threadIdx.x];
        atomicAdd(&Cm[threadIdx.x], s);
    }
}

__global__ void c_kernel(const float* __restrict__ CmAcc, float* __restrict__ c, float Ninv) {
    if (threadIdx.x == 0) {
        float M[16];
        for (int m = 0; m < 16; m++) M[m] = CmAcc[m] * Ninv;
        float cc[4], s = 0.f;
        for (int j = 0; j < 4; j++) { cc[j] = 0.5f * (M[12 + j] + M[j * 4 + 3]); s += cc[j]; }
        float invs = 1.f / s;
        for (int j = 0; j < 4; j++) c[j] = cc[j] * invs;
    }
}

__global__ void combine4(const float* __restrict__ a0, const float* __restrict__ a1,
                         const float* __restrict__ a2, const float* __restrict__ a3,
                         const float* __restrict__ c, float* __restrict__ out, int n4) {
    int i = blockIdx.x * blockDim.x + threadIdx.x;
    if (i >= n4) return;
    float c0 = c[0], c1 = c[1], c2 = c[2], c3 = c[3];
    float4 v0 = ((const float4*)a0)[i], v1 = ((const float4*)a1)[i];
    float4 v2 = ((const float4*)a2)[i], v3 = ((const float4*)a3)[i];
    float4 o;
    o.x = c0 * v0.x + c1 * v1.x + c2 * v2.x + c3 * v3.x;
    o.y = c0 * v0.y + c1 * v1.y + c2 * v2.y + c3 * v3.y;
    o.z = c0 * v0.z + c1 * v1.z + c2 * v2.z + c3 * v3.z;
    o.w = c0 * v0.w + c1 * v1.w + c2 * v2.w + c3 * v3.w;
    ((float4*)out)[i] = o;
}

// ---------------- persistent CG kernel (reaction prologue + 10 CG iters) ----------------
__global__ __launch_bounds__(CGT, 1) void cg_kernel(
    const float* __restrict__ T1, const float* __restrict__ A1,
    const float* __restrict__ A2, const float* __restrict__ AU,
    const float* __restrict__ bng, const float* __restrict__ bnb,
    const float* __restrict__ bnm, const float* __restrict__ bnv,
    const int* __restrict__ rowptr, const int* __restrict__ cols,
    const float* __restrict__ w, const float* __restrict__ Kap,
    float* __restrict__ X, float* __restrict__ R, float* __restrict__ P,
    float* __restrict__ LP, float* __restrict__ nr, float* __restrict__ pLP, int N) {
    const int n4 = N * (NH / 4);
    const int tid = blockIdx.x * CGT + threadIdx.x;
    const int nth = NBLK * CGT;
    const int lane = threadIdx.x & 31;

    // ---- reaction prologue: Tr -> X,R,P ; nr[0] = sum Tr^2 ----
    float ss = 0.f;
    for (int i = tid; i < n4; i += nth) {
        int col = (i << 2) & (NH - 1);
        float4 t1 = ((const float4*)T1)[i], a1 = ((const float4*)A1)[i];
        float4 a2 = ((const float4*)A2)[i], au = ((const float4*)AU)[i];
        float tt[4] = {t1.x, t1.y, t1.z, t1.w}, aa1[4] = {a1.x, a1.y, a1.z, a1.w};
        float aa2[4] = {a2.x, a2.y, a2.z, a2.w}, aau[4] = {au.x, au.y, au.z, au.w};
        float v[4];
#pragma unroll
        for (int u = 0; u < 4; u++) {
            int cl = col + u;
            float d2 = fminf(fmaxf(aa2[u], -1.f), 1.f);
            float y = tt[u] + HCOEF * (aa1[u] + aau[u] + tt[u] * d2);
            float s = bng[cl] * rsqrtf(bnv[cl] + EPS_BN);
            y = (y - bnm[cl]) * s + bnb[cl];
            y = (y > 0.f) ? y : expm1f(y);
            v[u] = y;
            ss += y * y;
        }
        float4 o = make_float4(v[0], v[1], v[2], v[3]);
        ((float4*)X)[i] = o; ((float4*)R)[i] = o; ((float4*)P)[i] = o;
    }
    float tot = block_reduce_sum(ss);
    if (threadIdx.x == 0) atomicAdd(&nr[0], tot);
    grid_barrier();

    float4 kd;
    {
        float4 kk = *(const float4*)(Kap + lane * 4);
        kd.x = fminf(fmaxf(kk.x, 0.f), 1.f); kd.y = fminf(fmaxf(kk.y, 0.f), 1.f);
        kd.z = fminf(fmaxf(kk.z, 0.f), 1.f); kd.w = fminf(fmaxf(kk.w, 0.f), 1.f);
    }
    const int gw = tid >> 5;
    const int tw = nth >> 5;

    for (int t = 0; t < 10; t++) {
        // freeze check (uniform across grid: nr finalized before last barrier)
        bool frozen = false;
        for (int j = 1; j <= t; j++)
            if (__ldcg(nr + j) < 1e-5f) frozen = true;
        if (frozen) break;

        // ---- spmv: LP = A P ; pLP[t] = <P, LP> ----
        float dot = 0.f;
        for (int r = gw; r < N; r += tw) {
            int e0 = rowptr[r], e1 = rowptr[r + 1];
            float4 acc = make_float4(0.f, 0.f, 0.f, 0.f);
            for (int e = e0; e < e1; e++) {
                int c = __ldg(&cols[e]);
                float wt = __ldg(&w[e]);
                float4 y = *(const float4*)(P + (size_t)c * NH + lane * 4);
                acc.x = fmaf(wt, y.x, acc.x); acc.y = fmaf(wt, y.y, acc.y);
                acc.z = fmaf(wt, y.z, acc.z); acc.w = fmaf(wt, y.w, acc.w);
            }
            float4 p = *(const float4*)(P + (size_t)r * NH + lane * 4);
            float4 lp;
            lp.x = p.x + HCOEF * ((p.x + acc.x) * kd.x);
            lp.y = p.y + HCOEF * ((p.y + acc.y) * kd.y);
            lp.z = p.z + HCOEF * ((p.z + acc.z) * kd.z);
            lp.w = p.w + HCOEF * ((p.w + acc.w) * kd.w);
            *(float4*)(LP + (size_t)r * NH + lane * 4) = lp;
            dot += p.x * lp.x + p.y * lp.y + p.z * lp.z + p.w * lp.w;
        }
        float td = block_reduce_sum(dot);
        if (threadIdx.x == 0) atomicAdd(&pLP[t], td);
        grid_barrier();

        // ---- X += a P ; R -= a LP ; nr[t+1] = |R|^2 ----
        float alpha = __ldcg(nr + t) / (__ldcg(pLP + t) + 1e-6f);
        float ss2 = 0.f;
        for (int i = tid; i < n4; i += nth) {
            float4 p = ((const float4*)P)[i], lp = ((const float4*)LP)[i];
            float4 x = ((float4*)X)[i], r = ((float4*)R)[i];
            x.x += alpha * p.x; x.y += alpha * p.y; x.z += alpha * p.z; x.w += alpha * p.w;
            r.x -= alpha * lp.x; r.y -= alpha * lp.y; r.z -= alpha * lp.z; r.w -= alpha * lp.w;
            ((float4*)X)[i] = x; ((float4*)R)[i] = r;
            ss2 += r.x * r.x + r.y * r.y + r.z * r.z + r.w * r.w;
        }
        float t2 = block_reduce_sum(ss2);
        if (threadIdx.x == 0) atomicAdd(&nr[t + 1], t2);
        grid_barrier();

        // ---- P = R + b P  (skipped once converged; X/R freeze handled by break) ----
        float nrt1 = __ldcg(nr + t + 1);
        if (nrt1 >= 1e-5f) {
            float beta = nrt1 / (__ldcg(nr + t) + 1e-6f);
            for (int i = tid; i < n4; i += nth) {
                float4 p = ((float4*)P)[i];
                float4 r = ((const float4*)R)[i];
                p.x = r.x + beta * p.x; p.y = r.y + beta * p.y;
                p.z = r.z + beta * p.z; p.w = r.w + beta * p.w;
                ((float4*)P)[i] = p;
            }
        }
        grid_barrier();
    }
}

// ---------------- host ----------------
extern "C" void kernel_launch(void* const* d_in, const int* in_sizes, int n_in,
                              void* d_out, int out_size) {
    const float* T      = (const float*)d_in[0];
    const int*   EI     = (const int*)d_in[1];
    const float* KopenW = (const float*)d_in[2];
    const float* Kopenb = (const float*)d_in[3];
    const float* bnOg   = (const float*)d_in[4];
    const float* bnOb   = (const float*)d_in[5];
    const float* bnOm   = (const float*)d_in[6];
    const float* bnOv   = (const float*)d_in[7];
    const float* convW  = (const float*)d_in[8];
    const float* convb  = (const float*)d_in[9];
    const float* bnAg   = (const float*)d_in[10];
    const float* bnAb   = (const float*)d_in[11];
    const float* bnAm   = (const float*)d_in[12];
    const float* bnAv   = (const float*)d_in[13];
    const float* Wq     = (const float*)d_in[14];
    const float* bq     = (const float*)d_in[15];
    const float* Wk     = (const float*)d_in[16];
    const float* bk     = (const float*)d_in[17];
    const float* mha    = (const float*)d_in[18];
    const float* KR1W   = (const float*)d_in[19];
    const float* KR1b   = (const float*)d_in[20];
    const float* KR2W   = (const float*)d_in[21];
    const float* KR2b   = (const float*)d_in[22];
    const float* KRU0W  = (const float*)d_in[23];
    const float* KRU0b  = (const float*)d_in[24];
    const float* bng    = (const float*)d_in[25];
    const float* bnbp   = (const float*)d_in[26];
    const float* bnm    = (const float*)d_in[27];
    const float* bnv    = (const float*)d_in[28];
    const float* Kappa  = (const float*)d_in[29];
    const float* KcloseW= (const float*)d_in[30];
    const float* Kcloseb= (const float*)d_in[31];

    const int N = in_sizes[0] / NH;
    const int E = in_sizes[1] / 2;
    const int n4 = N * (NH / 4);
    const size_t S = (size_t)MAXN * NH;

    float *Th, *z, *Xb, *qb, *kb, *T1, *A1, *A2, *AU, *R, *P, *LP, *dinvp, *wp, *scal;
    int *rowptr, *cnt, *bsum, *cols;
    cudaGetSymbolAddress((void**)&Th, d_Th);
    cudaGetSymbolAddress((void**)&z, d_z);
    cudaGetSymbolAddress((void**)&Xb, d_Xb);
    cudaGetSymbolAddress((void**)&qb, d_qb);
    cudaGetSymbolAddress((void**)&kb, d_kb);
    cudaGetSymbolAddress((void**)&T1, d_T1);
    cudaGetSymbolAddress((void**)&A1, d_A1);
    cudaGetSymbolAddress((void**)&A2, d_A2);
    cudaGetSymbolAddress((void**)&AU, d_AU);
    cudaGetSymbolAddress((void**)&R, d_R);
    cudaGetSymbolAddress((void**)&P, d_P);
    cudaGetSymbolAddress((void**)&LP, d_LP);
    cudaGetSymbolAddress((void**)&dinvp, d_dinv);
    cudaGetSymbolAddress((void**)&wp, d_w);
    cudaGetSymbolAddress((void**)&scal, d_scal);
    cudaGetSymbolAddress((void**)&rowptr, d_rowptr);
    cudaGetSymbolAddress((void**)&cnt, d_cnt);
    cudaGetSymbolAddress((void**)&bsum, d_bsum);
    cudaGetSymbolAddress((void**)&cols, d_cols);

    static bool attr_done = false;
    if (!attr_done) {
        cudaFuncSetAttribute(gemm_tc<0>, cudaFuncAttributeMaxDynamicSharedMemorySize, GSMEM);
        cudaFuncSetAttribute(gemm_tc<1>, cudaFuncAttributeMaxDynamicSharedMemorySize, GSMEM);
        cudaFuncSetAttribute(gemm_tc<2>, cudaFuncAttributeMaxDynamicSharedMemorySize, GSMEM);
        attr_done = true;
    }

    cudaMemsetAsync(cnt, 0, (size_t)N * sizeof(int));
    cudaMemsetAsync(scal, 0, 4 * SSTR * sizeof(float));

    count_kernel<<<(E + 255) / 256, 256>>>(EI, cnt, E);
    dinv_kernel<<<(N + 255) / 256, 256>>>(cnt, dinvp, N);
    int nb = (N + 1023) / 1024;
    blocksum_kernel<<<nb, 1024>>>(cnt, bsum, N);
    scanbsum_kernel<<<1, 32>>>(bsum, rowptr + N, nb);
    localscan_kernel<<<nb, 1024>>>(cnt, rowptr, bsum, N);
    fill_kernel<<<(E + 255) / 256, 256>>>(EI, cnt, dinvp, cols, wp, E);

    const int GBX = (N + 63) / 64;
    dim3 g1(GBX, 1), g2(GBX, 2);
    const int VB = (n4 + 255) / 256;

    gemm_tc<1><<<g1, 256, GSMEM>>>(T, KopenW, Kopenb, Th, KopenW, Kopenb, Th, N, NH,
                                   bnOg, bnOb, bnOm, bnOv);
    gemm_tc<2><<<g1, 256, GSMEM>>>(Th, convW, convb, z, convW, convb, z, N, NH,
                                   bnAg, bnAb, bnAm, bnAv);
    gemm_tc<0><<<g2, 256, GSMEM>>>(z, Wq, bq, qb, Wk, bk, kb, N, NH, 0, 0, 0, 0);

    for (int jj = 0; jj < 4; jj++) {
        if (jj > 0) {
            gemm_tc<0><<<g2, 256, GSMEM>>>(Xb + (jj - 1) * S, Wq, bq, qb + jj * S,
                                           Wk, bk, kb + jj * S, N, NH, 0, 0, 0, 0);
        }
        const float *aq[4], *ak[4], *aa[4];
        for (int o = 0; o < 4; o++) {
            if (o < 4 - jj) { aq[o] = qb; ak[o] = kb; aa[o] = z; }
            else {
                int m = o - 4 + jj;
                aq[o] = qb + (m + 1) * S; ak[o] = kb + (m + 1) * S; aa[o] = Xb + m * S;
            }
        }
        float* sl = scal + jj * SSTR;
        attn_kernel<<<400, 256>>>(aq[0], aq[1], aq[2], aq[3], ak[0], ak[1], ak[2], ak[3],
                                  mha, sl, N);
        c_kernel<<<1, 32>>>(sl, sl + 16, 1.0f / (float)N);
        combine4<<<VB, 256>>>(aa[0], aa[1], aa[2], aa[3], sl + 16, T1, n4);

        gemm_tc<0><<<g2, 256, GSMEM>>>(T1, KR1W + jj * NH * NH, KR1b + jj * NH, A1,
                                       KR2W + jj * NH * NH, KR2b + jj * NH, A2, N, NH, 0, 0, 0, 0);
        gemm_tc<0><<<g1, 256, GSMEM>>>(Th, KRU0W + jj * NH * NH, KRU0b + jj * NH, AU,
                                       KRU0W + jj * NH * NH, KRU0b + jj * NH, AU, N, NH, 0, 0, 0, 0);

        float* X = Xb + jj * S;
        cg_kernel<<<NBLK, CGT>>>(T1, A1, A2, AU, bng + jj * NH, bnbp + jj * NH,
                                 bnm + jj * NH, bnv + jj * NH, rowptr, cols, wp,
                                 Kappa + jj * NH, X, R, P, LP, sl + 20, sl + 31, N);
    }
    gemm_tc<0><<<g1, 256, GSMEM>>>(Xb + 3 * S, KcloseW, Kcloseb, (float*)d_out,
                                   KcloseW, Kcloseb, (float*)d_out, N, 40, 0, 0, 0, 0);
}

// round 7
// speedup vs baseline: 2.0038x; 1.3162x over previous
#include <cuda_runtime.h>
#include <cuda_bf16.h>
#include <math.h>
#include <stdint.h>

#define NH 128
#define MAXN 50000
#define MAXE 800000
#define HCOEF 0.1f
#define EPS_BN 1e-5f
#define SSTR 48
#define NBLK 148
#define CGT 1024
#define CHEB_M 5

// ---------------- device scratch ----------------
__device__ float d_Th[MAXN * NH];
__device__ float d_z[MAXN * NH];
__device__ float d_Xb[4][MAXN * NH];
__device__ float d_qb[4][MAXN * NH];
__device__ float d_kb[4][MAXN * NH];
__device__ float d_T1[MAXN * NH];
__device__ float d_A1[MAXN * NH];
__device__ float d_A2[MAXN * NH];
__device__ float d_AUb[4][MAXN * NH];
__device__ float d_ZA[MAXN * NH];
__device__ float d_ZB[MAXN * NH];
__device__ int   d_rowptr[MAXN + 1];
__device__ int   d_cnt[MAXN];
__device__ int   d_bsum[64];
__device__ int   d_cols[MAXE];
__device__ float d_w[MAXE];
__device__ float d_dinv[MAXN];
__device__ float d_scal[4 * SSTR];
__device__ volatile unsigned d_barcnt = 0;
__device__ volatile unsigned d_bargen = 0;

__device__ __forceinline__ void grid_barrier() {
    __syncthreads();
    if (threadIdx.x == 0) {
        unsigned g = d_bargen;
        __threadfence();
        unsigned a = atomicInc((unsigned*)&d_barcnt, NBLK - 1);
        if (a == NBLK - 1) {
            __threadfence();
            d_bargen = g + 1;
        } else {
            while (d_bargen == g) __nanosleep(128);
        }
        __threadfence();
    }
    __syncthreads();
}

// ---------------- CSR build ----------------
__global__ void count_kernel(const int* __restrict__ EI, int* __restrict__ cnt, int E) {
    int e = blockIdx.x * blockDim.x + threadIdx.x;
    if (e >= E) return;
    int r = EI[e], c = EI[E + e];
    if (r != c) atomicAdd(&cnt[r], 1);
}
__global__ void dinv_kernel(const int* __restrict__ cnt, float* __restrict__ dinv, int N) {
    int i = blockIdx.x * blockDim.x + threadIdx.x;
    if (i >= N) return;
    int d = cnt[i];
    dinv[i] = (d > 0) ? rsqrtf((float)d) : 0.f;
}
__global__ void blocksum_kernel(const int* __restrict__ cnt, int* __restrict__ bsum, int N) {
    __shared__ int sh[1024];
    int i = blockIdx.x * 1024 + threadIdx.x;
    sh[threadIdx.x] = (i < N) ? cnt[i] : 0;
    __syncthreads();
    for (int o = 512; o; o >>= 1) {
        if (threadIdx.x < o) sh[threadIdx.x] += sh[threadIdx.x + o];
        __syncthreads();
    }
    if (threadIdx.x == 0) bsum[blockIdx.x] = sh[0];
}
__global__ void scanbsum_kernel(int* __restrict__ bsum, int* __restrict__ rowptrN, int nb) {
    if (threadIdx.x == 0) {
        int run = 0;
        for (int i = 0; i < nb; i++) { int t = bsum[i]; bsum[i] = run; run += t; }
        *rowptrN = run;
    }
}
__global__ void localscan_kernel(int* __restrict__ cnt, int* __restrict__ rowptr,
                                 const int* __restrict__ bsum, int N) {
    __shared__ int sh[1024];
    int i = blockIdx.x * 1024 + threadIdx.x;
    int x = (i < N) ? cnt[i] : 0;
    sh[threadIdx.x] = x;
    __syncthreads();
    for (int off = 1; off < 1024; off <<= 1) {
        int t = (threadIdx.x >= off) ? sh[threadIdx.x - off] : 0;
        __syncthreads();
        sh[threadIdx.x] += t;
        __syncthreads();
    }
    if (i < N) { int excl = sh[threadIdx.x] - x + bsum[blockIdx.x]; rowptr[i] = excl; cnt[i] = excl; }
}
__global__ void fill_kernel(const int* __restrict__ EI, int* __restrict__ cursor,
                            const float* __restrict__ dinv, int* __restrict__ cols,
                            float* __restrict__ w, int E) {
    int e = blockIdx.x * blockDim.x + threadIdx.x;
    if (e >= E) return;
    int r = EI[e], c = EI[E + e];
    if (r != c) {
        int pos = atomicAdd(&cursor[r], 1);
        cols[pos] = c;
        w[pos] = -dinv[r] * dinv[c];
    }
}

// ---------------- tensor-core GEMM (split-bf16) ----------------
__device__ __forceinline__ void mma16816(float* c, const uint32_t* a, const uint32_t* b) {
    asm volatile(
        "mma.sync.aligned.m16n8k16.row.col.f32.bf16.bf16.f32 "
        "{%0,%1,%2,%3}, {%4,%5,%6,%7}, {%8,%9}, {%0,%1,%2,%3};\n"
        : "+f"(c[0]), "+f"(c[1]), "+f"(c[2]), "+f"(c[3])
        : "r"(a[0]), "r"(a[1]), "r"(a[2]), "r"(a[3]), "r"(b[0]), "r"(b[1]));
}
__device__ __forceinline__ void ldsm4(uint32_t* d, uint32_t addr) {
    asm volatile("ldmatrix.sync.aligned.m8n8.x4.shared.b16 {%0,%1,%2,%3}, [%4];"
                 : "=r"(d[0]), "=r"(d[1]), "=r"(d[2]), "=r"(d[3]) : "r"(addr));
}
__device__ __forceinline__ void ldsm2(uint32_t* d, uint32_t addr) {
    asm volatile("ldmatrix.sync.aligned.m8n8.x2.shared.b16 {%0,%1}, [%2];"
                 : "=r"(d[0]), "=r"(d[1]) : "r"(addr));
}

#define LDW 136
#define GSMEM ((2 * 64 + 2 * 128) * LDW * 2)

template <int EPI>
__device__ __forceinline__ void gemm_body(
    const float* __restrict__ A, const float* __restrict__ Wsel,
    const float* __restrict__ bsel, float* __restrict__ Csel, int N, int Oc,
    const float* __restrict__ bng, const float* __restrict__ bnb,
    const float* __restrict__ bnm, const float* __restrict__ bnv) {
    extern __shared__ __align__(16) char smem_raw[];
    __nv_bfloat16* Ah = (__nv_bfloat16*)smem_raw;
    __nv_bfloat16* Al = Ah + 64 * LDW;
    __nv_bfloat16* Wh = Al + 64 * LDW;
    __nv_bfloat16* Wl = Wh + 128 * LDW;

    const int tid = threadIdx.x;
    const int brow = blockIdx.x * 64;

#pragma unroll
    for (int i = 0; i < 8; i++) {
        int fl = i * 256 + tid;
        int row = fl >> 5;
        int c4 = (fl & 31) << 2;
        float4 av = make_float4(0.f, 0.f, 0.f, 0.f);
        int gr = brow + row;
        if (gr < N) av = *(const float4*)(A + (size_t)gr * 128 + c4);
        float aval[4] = {av.x, av.y, av.z, av.w};
        int base = row * LDW + c4;
#pragma unroll
        for (int u = 0; u < 4; u++) {
            __nv_bfloat16 h = __float2bfloat16(aval[u]);
            Ah[base + u] = h;
            Al[base + u] = __float2bfloat16(aval[u] - __bfloat162float(h));
        }
    }
#pragma unroll
    for (int i = 0; i < 16; i++) {
        int fl = i * 256 + tid;
        int row = fl >> 5;
        int c4 = (fl & 31) << 2;
        float4 wv = make_float4(0.f, 0.f, 0.f, 0.f);
        if (row < Oc) wv = *(const float4*)(Wsel + (size_t)row * 128 + c4);
        float wval[4] = {wv.x, wv.y, wv.z, wv.w};
        int base = row * LDW + c4;
#pragma unroll
        for (int u = 0; u < 4; u++) {
            __nv_bfloat16 h = __float2bfloat16(wval[u]);
            Wh[base + u] = h;
            Wl[base + u] = __float2bfloat16(wval[u] - __bfloat162float(h));
        }
    }
    __syncthreads();

    const int w = tid >> 5, lane = tid & 31;
    const int wm = w >> 2, wn = w & 3;

    float acc[2][4][4];
#pragma unroll
    for (int mt = 0; mt < 2; mt++)
#pragma unroll
        for (int nt = 0; nt < 4; nt++)
#pragma unroll
            for (int u = 0; u < 4; u++) acc[mt][nt][u] = 0.f;

    uint32_t sAh = (uint32_t)__cvta_generic_to_shared(Ah);
    uint32_t sAl = (uint32_t)__cvta_generic_to_shared(Al);
    uint32_t sWh = (uint32_t)__cvta_generic_to_shared(Wh);
    uint32_t sWl = (uint32_t)__cvta_generic_to_shared(Wl);
    uint32_t aBase[3] = {sAh, sAl, sAh};
    uint32_t wBase[3] = {sWh, sWh, sWl};

#pragma unroll
    for (int p = 0; p < 3; p++) {
        uint32_t ab = aBase[p], wb = wBase[p];
#pragma unroll
        for (int kk = 0; kk < 8; kk++) {
            uint32_t bfr[4][2];
            {
                int r = lane & 7, sel = (lane >> 3) & 1;
                int kcol = kk * 16 + sel * 8;
#pragma unroll
                for (int nt = 0; nt < 4; nt++) {
                    int row = wn * 32 + nt * 8 + r;
                    ldsm2(bfr[nt], wb + (uint32_t)(row * LDW + kcol) * 2);
                }
            }
#pragma unroll
            for (int mt = 0; mt < 2; mt++) {
                uint32_t afr[4];
                int q = lane >> 3, r = lane & 7;
                int row = wm * 32 + mt * 16 + (q & 1) * 8 + r;
                int kcol = kk * 16 + (q >> 1) * 8;
                ldsm4(afr, ab + (uint32_t)(row * LDW + kcol) * 2);
#pragma unroll
                for (int nt = 0; nt < 4; nt++)
                    mma16816(acc[mt][nt], afr, bfr[nt]);
            }
        }
    }

    const int g = lane >> 2, t2 = (lane & 3) * 2;
#pragma unroll
    for (int mt = 0; mt < 2; mt++) {
#pragma unroll
        for (int nt = 0; nt < 4; nt++) {
            int col0 = wn * 32 + nt * 8 + t2;
#pragma unroll
            for (int half = 0; half < 2; half++) {
                int row = brow + wm * 32 + mt * 16 + g + half * 8;
                if (row >= N) continue;
#pragma unroll
                for (int u = 0; u < 2; u++) {
                    int col = col0 + u;
                    if (col >= Oc) continue;
                    float x = acc[mt][nt][half * 2 + u] + bsel[col];
                    if (EPI) {
                        float s = bng[col] * rsqrtf(bnv[col] + EPS_BN);
                        x = (x - bnm[col]) * s + bnb[col];
                        if (EPI == 1) x = (x > 0.f) ? x : expm1f(x);
                        else x = fmaxf(x, 0.f);
                    }
                    Csel[(size_t)row * Oc + col] = x;
                }
            }
        }
    }
}

template <int EPI>
__global__ __launch_bounds__(256, 2) void gemm_tc(
    const float* __restrict__ A,
    const float* __restrict__ W, const float* __restrict__ bias, float* __restrict__ C,
    const float* __restrict__ W2, const float* __restrict__ bias2, float* __restrict__ C2,
    int N, int Oc,
    const float* __restrict__ bng, const float* __restrict__ bnb,
    const float* __restrict__ bnm, const float* __restrict__ bnv) {
    gemm_body<EPI>(A, blockIdx.y ? W2 : W, blockIdx.y ? bias2 : bias,
                   blockIdx.y ? C2 : C, N, Oc, bng, bnb, bnm, bnv);
}

__global__ __launch_bounds__(256, 2) void gemm_tc_b4(
    const float* __restrict__ A, const float* __restrict__ Wb,
    const float* __restrict__ bb, float* __restrict__ Cb, size_t Cstride, int N) {
    gemm_body<0>(A, Wb + (size_t)blockIdx.y * NH * NH, bb + (size_t)blockIdx.y * NH,
                 Cb + (size_t)blockIdx.y * Cstride, N, NH, 0, 0, 0, 0);
}

// ---------------- attention stats ----------------
__global__ void attn_kernel(const float* __restrict__ q0, const float* __restrict__ q1,
                            const float* __restrict__ q2, const float* __restrict__ q3,
                            const float* __restrict__ k0, const float* __restrict__ k1,
                            const float* __restrict__ k2, const float* __restrict__ k3,
                            const float* __restrict__ mha, float* __restrict__ Cm, int N) {
    const float scale = 0.08838834764831845f;
    float rfac = fmaxf(mha[0], 0.f);
    int lane = threadIdx.x & 31, wid = threadIdx.x >> 5;
    int gw = blockIdx.x * (blockDim.x >> 5) + wid;
    int tw = gridDim.x * (blockDim.x >> 5);
    const float* qs[4] = {q0, q1, q2, q3};
    const float* ks[4] = {k0, k1, k2, k3};
    float acc[16];
#pragma unroll
    for (int m = 0; m < 16; m++) acc[m] = 0.f;
    for (int n = gw; n < N; n += tw) {
        float4 qv[4], kv[4];
#pragma unroll
        for (int s = 0; s < 4; s++) {
            qv[s] = *(const float4*)(qs[s] + (size_t)n * NH + lane * 4);
            kv[s] = *(const float4*)(ks[s] + (size_t)n * NH + lane * 4);
        }
        float sc[16];
#pragma unroll
        for (int i = 0; i < 4; i++)
#pragma unroll
            for (int j = 0; j < 4; j++) {
                float4 a = qv[i], b = kv[j];
                sc[i * 4 + j] = a.x * b.x + a.y * b.y + a.z * b.z + a.w * b.w;
            }
#pragma unroll
        for (int m = 0; m < 16; m++) {
            float v = sc[m];
#pragma unroll
            for (int o = 16; o; o >>= 1) v += __shfl_xor_sync(0xffffffffu, v, o);
            sc[m] = v * scale;
        }
        if (lane == 0) {
#pragma unroll
            for (int i = 0; i < 4; i++) {
                float s0 = sc[i * 4], s1 = sc[i * 4 + 1], s2 = sc[i * 4 + 2], s3 = sc[i * 4 + 3];
                float mx = fmaxf(fmaxf(s0, s1), fmaxf(s2, s3));
                float e0 = expf(s0 - mx), e1 = expf(s1 - mx), e2 = expf(s2 - mx), e3 = expf(s3 - mx);
                float inv = 1.f / (e0 + e1 + e2 + e3);
                acc[i * 4 + 0] += logf(e0 * inv * rfac + 1e-4f);
                acc[i * 4 + 1] += logf(e1 * inv * rfac + 1e-4f);
                acc[i * 4 + 2] += logf(e2 * inv * rfac + 1e-4f);
                acc[i * 4 + 3] += logf(e3 * inv * rfac + 1e-4f);
            }
        }
    }
    __shared__ float sh[8][16];
    if (lane == 0)
#pragma unroll
        for (int m = 0; m < 16; m++) sh[wid][m] = acc[m];
    __syncthreads();
    int nw = blockDim.x >> 5;
    if (threadIdx.x < 16) {
        float s = 0.f;
        for (int w2 = 0; w2 < nw; w2++) s += sh[w2][threadIdx.x];
        atomicAdd(&Cm[threadIdx.x], s);
    }
}

__global__ void c_kernel(const float* __restrict__ CmAcc, float* __restrict__ c, float Ninv) {
    if (threadIdx.x == 0) {
        float M[16];
        for (int m = 0; m < 16; m++) M[m] = CmAcc[m] * Ninv;
        float cc[4], s = 0.f;
        for (int j = 0; j < 4; j++) { cc[j] = 0.5f * (M[12 + j] + M[j * 4 + 3]); s += cc[j]; }
        float invs = 1.f / s;
        for (int j = 0; j < 4; j++) c[j] = cc[j] * invs;
    }
}

__global__ void combine4(const float* __restrict__ a0, const float* __restrict__ a1,
                         const float* __restrict__ a2, const float* __restrict__ a3,
                         const float* __restrict__ c, float* __restrict__ out, int n4) {
    int i = blockIdx.x * blockDim.x + threadIdx.x;
    if (i >= n4) return;
    float c0 = c[0], c1 = c[1], c2 = c[2], c3 = c[3];
    float4 v0 = ((const float4*)a0)[i], v1 = ((const float4*)a1)[i];
    float4 v2 = ((const float4*)a2)[i], v3 = ((const float4*)a3)[i];
    float4 o;
    o.x = c0 * v0.x + c1 * v1.x + c2 * v2.x + c3 * v3.x;
    o.y = c0 * v0.y + c1 * v1.y + c2 * v2.y + c3 * v3.y;
    o.z = c0 * v0.z + c1 * v1.z + c2 * v2.z + c3 * v3.z;
    o.w = c0 * v0.w + c1 * v1.w + c2 * v2.w + c3 * v3.w;
    ((float4*)out)[i] = o;
}

// ---------------- persistent Chebyshev solve ----------------
// Reference CG starts from X0 = Tr with R0 = Tr, i.e. it solves A Y = Tr from Y0=0
// and returns X = Tr + Y.  So: X = Tr + A^{-1} Tr, with A = (1+hk)I + hk*S per column.
// A^{-1} = w*T0(S) + sum_{k>=1} 2w(-sig)^k T_k(S);  w = 1/sqrt(1+2hk),
// sig = hk/(1+hk+sqrt(1+2hk)) <= 0.0455  (truncation ~ sig^6 ~ 1e-8).
__global__ __launch_bounds__(CGT, 1) void cheb_kernel(
    const float* __restrict__ T1, const float* __restrict__ A1,
    const float* __restrict__ A2, const float* __restrict__ AU,
    const float* __restrict__ bng, const float* __restrict__ bnb,
    const float* __restrict__ bnm, const float* __restrict__ bnv,
    const int* __restrict__ rowptr, const int* __restrict__ cols,
    const float* __restrict__ w, const float* __restrict__ Kap,
    float* __restrict__ X, float* __restrict__ ZA, float* __restrict__ ZB, int N) {
    const int n4 = N * (NH / 4);
    const int tid = blockIdx.x * CGT + threadIdx.x;
    const int nth = NBLK * CGT;
    const int lane = threadIdx.x & 31;

    // ---- reaction prologue: Tr -> ZA ; X = (1 + w(col)) * Tr ----
    for (int i = tid; i < n4; i += nth) {
        int col = (i << 2) & (NH - 1);
        float4 t1 = ((const float4*)T1)[i], a1 = ((const float4*)A1)[i];
        float4 a2 = ((const float4*)A2)[i], au = ((const float4*)AU)[i];
        float tt[4] = {t1.x, t1.y, t1.z, t1.w}, aa1[4] = {a1.x, a1.y, a1.z, a1.w};
        float aa2[4] = {a2.x, a2.y, a2.z, a2.w}, aau[4] = {au.x, au.y, au.z, au.w};
        float v[4], xv[4];
#pragma unroll
        for (int u = 0; u < 4; u++) {
            int cl = col + u;
            float d2 = fminf(fmaxf(aa2[u], -1.f), 1.f);
            float y = tt[u] + HCOEF * (aa1[u] + aau[u] + tt[u] * d2);
            float s = bng[cl] * rsqrtf(bnv[cl] + EPS_BN);
            y = (y - bnm[cl]) * s + bnb[cl];
            y = (y > 0.f) ? y : expm1f(y);
            v[u] = y;
            float kd = fminf(fmaxf(__ldg(&Kap[cl]), 0.f), 1.f);
            float hk = HCOEF * kd;
            xv[u] = (1.f + rsqrtf(1.f + 2.f * hk)) * y;   // Tr + w*T0 term
        }
        ((float4*)ZA)[i] = make_float4(v[0], v[1], v[2], v[3]);
        ((float4*)X)[i] = make_float4(xv[0], xv[1], xv[2], xv[3]);
    }
    grid_barrier();

    float4 sg, ck;
    {
        float4 kk = *(const float4*)(Kap + lane * 4);
        float kd[4] = {kk.x, kk.y, kk.z, kk.w};
        float sv[4], cv[4];
#pragma unroll
        for (int u = 0; u < 4; u++) {
            float k2 = fminf(fmaxf(kd[u], 0.f), 1.f);
            float hk = HCOEF * k2;
            float rt = sqrtf(1.f + 2.f * hk);
            float s = hk / (1.f + hk + rt);
            sv[u] = s;
            cv[u] = -2.f * s / rt;      // c1 = 2w*(-sig)
        }
        sg = make_float4(sv[0], sv[1], sv[2], sv[3]);
        ck = make_float4(cv[0], cv[1], cv[2], cv[3]);
    }

    const int gw = tid >> 5;
    const int tw = nth >> 5;

#pragma unroll
    for (int k = 1; k <= CHEB_M; k++) {
        const float* cur = (k & 1) ? ZA : ZB;
        float* oth = (k & 1) ? ZB : ZA;
        for (int r = gw; r < N; r += tw) {
            int e0 = rowptr[r], e1 = rowptr[r + 1];
            float4 acc = make_float4(0.f, 0.f, 0.f, 0.f);
            for (int e = e0; e < e1; e++) {
                int c = __ldg(&cols[e]);
                float wt = __ldg(&w[e]);
                float4 y = *(const float4*)(cur + (size_t)c * NH + lane * 4);
                acc.x = fmaf(wt, y.x, acc.x); acc.y = fmaf(wt, y.y, acc.y);
                acc.z = fmaf(wt, y.z, acc.z); acc.w = fmaf(wt, y.w, acc.w);
            }
            float4 zn;
            if (k == 1) zn = acc;
            else {
                float4 zp = *(const float4*)(oth + (size_t)r * NH + lane * 4);
                zn.x = 2.f * acc.x - zp.x; zn.y = 2.f * acc.y - zp.y;
                zn.z = 2.f * acc.z - zp.z; zn.w = 2.f * acc.w - zp.w;
            }
            float4 xv = *(const float4*)(X + (size_t)r * NH + lane * 4);
            xv.x = fmaf(ck.x, zn.x, xv.x); xv.y = fmaf(ck.y, zn.y, xv.y);
            xv.z = fmaf(ck.z, zn.z, xv.z); xv.w = fmaf(ck.w, zn.w, xv.w);
            *(float4*)(X + (size_t)r * NH + lane * 4) = xv;
            *(float4*)(oth + (size_t)r * NH + lane * 4) = zn;
        }
        ck.x *= -sg.x; ck.y *= -sg.y; ck.z *= -sg.z; ck.w *= -sg.w;
        if (k < CHEB_M) grid_barrier();
    }
}

// ---------------- host ----------------
extern "C" void kernel_launch(void* const* d_in, const int* in_sizes, int n_in,
                              void* d_out, int out_size) {
    const float* T      = (const float*)d_in[0];
    const int*   EI     = (const int*)d_in[1];
    const float* KopenW = (const float*)d_in[2];
    const float* Kopenb = (const float*)d_in[3];
    const float* bnOg   = (const float*)d_in[4];
    const float* bnOb   = (const float*)d_in[5];
    const float* bnOm   = (const float*)d_in[6];
    const float* bnOv   = (const float*)d_in[7];
    const float* convW  = (const float*)d_in[8];
    const float* convb  = (const float*)d_in[9];
    const float* bnAg   = (const float*)d_in[10];
    const float* bnAb   = (const float*)d_in[11];
    const float* bnAm   = (const float*)d_in[12];
    const float* bnAv   = (const float*)d_in[13];
    const float* Wq     = (const float*)d_in[14];
    const float* bq     = (const float*)d_in[15];
    const float* Wk     = (const float*)d_in[16];
    const float* bk     = (const float*)d_in[17];
    const float* mha    = (const float*)d_in[18];
    const float* KR1W   = (const float*)d_in[19];
    const float* KR1b   = (const float*)d_in[20];
    const float* KR2W   = (const float*)d_in[21];
    const float* KR2b   = (const float*)d_in[22];
    const float* KRU0W  = (const float*)d_in[23];
    const float* KRU0b  = (const float*)d_in[24];
    const float* bng    = (const float*)d_in[25];
    const float* bnbp   = (const float*)d_in[26];
    const float* bnm    = (const float*)d_in[27];
    const float* bnv    = (const float*)d_in[28];
    const float* Kappa  = (const float*)d_in[29];
    const float* KcloseW= (const float*)d_in[30];
    const float* Kcloseb= (const float*)d_in[31];

    const int N = in_sizes[0] / NH;
    const int E = in_sizes[1] / 2;
    const int n4 = N * (NH / 4);
    const size_t S = (size_t)MAXN * NH;

    float *Th, *z, *Xb, *qb, *kb, *T1, *A1, *A2, *AUb, *ZA, *ZB, *dinvp, *wp, *scal;
    int *rowptr, *cnt, *bsum, *cols;
    cudaGetSymbolAddress((void**)&Th, d_Th);
    cudaGetSymbolAddress((void**)&z, d_z);
    cudaGetSymbolAddress((void**)&Xb, d_Xb);
    cudaGetSymbolAddress((void**)&qb, d_qb);
    cudaGetSymbolAddress((void**)&kb, d_kb);
    cudaGetSymbolAddress((void**)&T1, d_T1);
    cudaGetSymbolAddress((void**)&A1, d_A1);
    cudaGetSymbolAddress((void**)&A2, d_A2);
    cudaGetSymbolAddress((void**)&AUb, d_AUb);
    cudaGetSymbolAddress((void**)&ZA, d_ZA);
    cudaGetSymbolAddress((void**)&ZB, d_ZB);
    cudaGetSymbolAddress((void**)&dinvp, d_dinv);
    cudaGetSymbolAddress((void**)&wp, d_w);
    cudaGetSymbolAddress((void**)&scal, d_scal);
    cudaGetSymbolAddress((void**)&rowptr, d_rowptr);
    cudaGetSymbolAddress((void**)&cnt, d_cnt);
    cudaGetSymbolAddress((void**)&bsum, d_bsum);
    cudaGetSymbolAddress((void**)&cols, d_cols);

    static bool attr_done = false;
    if (!attr_done) {
        cudaFuncSetAttribute(gemm_tc<0>, cudaFuncAttributeMaxDynamicSharedMemorySize, GSMEM);
        cudaFuncSetAttribute(gemm_tc<1>, cudaFuncAttributeMaxDynamicSharedMemorySize, GSMEM);
        cudaFuncSetAttribute(gemm_tc<2>, cudaFuncAttributeMaxDynamicSharedMemorySize, GSMEM);
        cudaFuncSetAttribute(gemm_tc_b4, cudaFuncAttributeMaxDynamicSharedMemorySize, GSMEM);
        attr_done = true;
    }

    const int GBX = (N + 63) / 64;
    dim3 g1(GBX, 1), g2(GBX, 2), g4(GBX, 4);
    const int VB = (n4 + 255) / 256;

    cudaMemsetAsync(cnt, 0, (size_t)N * sizeof(int));
    cudaMemsetAsync(scal, 0, 4 * SSTR * sizeof(float));
    count_kernel<<<(E + 255) / 256, 256>>>(EI, cnt, E);
    dinv_kernel<<<(N + 255) / 256, 256>>>(cnt, dinvp, N);
    int nb = (N + 1023) / 1024;
    blocksum_kernel<<<nb, 1024>>>(cnt, bsum, N);

    gemm_tc<1><<<g1, 256, GSMEM>>>(T, KopenW, Kopenb, Th, KopenW, Kopenb, Th, N, NH,
                                   bnOg, bnOb, bnOm, bnOv);

    scanbsum_kernel<<<1, 32>>>(bsum, rowptr + N, nb);
    localscan_kernel<<<nb, 1024>>>(cnt, rowptr, bsum, N);
    fill_kernel<<<(E + 255) / 256, 256>>>(EI, cnt, dinvp, cols, wp, E);

    gemm_tc<2><<<g1, 256, GSMEM>>>(Th, convW, convb, z, convW, convb, z, N, NH,
                                   bnAg, bnAb, bnAm, bnAv);
    gemm_tc<0><<<g2, 256, GSMEM>>>(z, Wq, bq, qb, Wk, bk, kb, N, NH, 0, 0, 0, 0);
    gemm_tc_b4<<<g4, 256, GSMEM>>>(Th, KRU0W, KRU0b, AUb, S, N);

    for (int jj = 0; jj < 4; jj++) {
        if (jj > 0) {
            gemm_tc<0><<<g2, 256, GSMEM>>>(Xb + (jj - 1) * S, Wq, bq, qb + jj * S,
                                           Wk, bk, kb + jj * S, N, NH, 0, 0, 0, 0);
        }
        const float *aq[4], *ak[4], *aa[4];
        for (int o = 0; o < 4; o++) {
            if (o < 4 - jj) { aq[o] = qb; ak[o] = kb; aa[o] = z; }
            else {
                int m = o - 4 + jj;
                aq[o] = qb + (m + 1) * S; ak[o] = kb + (m + 1) * S; aa[o] = Xb + m * S;
            }
        }
        float* sl = scal + jj * SSTR;
        attn_kernel<<<400, 256>>>(aq[0], aq[1], aq[2], aq[3], ak[0], ak[1], ak[2], ak[3],
                                  mha, sl, N);
        c_kernel<<<1, 32>>>(sl, sl + 16, 1.0f / (float)N);
        combine4<<<VB, 256>>>(aa[0], aa[1], aa[2], aa[3], sl + 16, T1, n4);

        gemm_tc<0><<<g2, 256, GSMEM>>>(T1, KR1W + jj * NH * NH, KR1b + jj * NH, A1,
                                       KR2W + jj * NH * NH, KR2b + jj * NH, A2, N, NH, 0, 0, 0, 0);

        cheb_kernel<<<NBLK, CGT>>>(T1, A1, A2, AUb + jj * S, bng + jj * NH, bnbp + jj * NH,
                                   bnm + jj * NH, bnv + jj * NH, rowptr, cols, wp,
                                   Kappa + jj * NH, Xb + jj * S, ZA, ZB, N);
    }
    gemm_tc<0><<<g1, 256, GSMEM>>>(Xb + 3 * S, KcloseW, Kcloseb, (float*)d_out,
                                   KcloseW, Kcloseb, (float*)d_out, N, 40, 0, 0, 0, 0);
}

// round 8
// speedup vs baseline: 2.2407x; 1.1182x over previous
#include <cuda_runtime.h>
#include <cuda_bf16.h>
#include <math.h>
#include <stdint.h>

#define NH 128
#define MAXN 50000
#define MAXE 800000
#define HCOEF 0.1f
#define EPS_BN 1e-5f
#define SSTR 48
#define NBLK 148
#define CGT 1024
#define CHEB_M 4
#define WSLOT (NH * NH)

// ---------------- device scratch ----------------
__device__ float d_Th[MAXN * NH];
__device__ float d_z[MAXN * NH];
__device__ float d_Xb[4][MAXN * NH];
__device__ float d_qb[4][MAXN * NH];
__device__ float d_kb[4][MAXN * NH];
__device__ float d_T1[MAXN * NH];
__device__ float d_A1[MAXN * NH];
__device__ float d_A2[MAXN * NH];
__device__ float d_AUb[4][MAXN * NH];
__device__ float d_ZA[MAXN * NH];
__device__ float d_ZB[MAXN * NH];
__device__ __nv_bfloat16 d_WH[17 * WSLOT];
__device__ __nv_bfloat16 d_WL[17 * WSLOT];
__device__ int   d_rowptr[MAXN + 1];
__device__ int   d_cnt[MAXN];
__device__ int   d_bsum[64];
__device__ int   d_cols[MAXE];
__device__ float d_w[MAXE];
__device__ float d_dinv[MAXN];
__device__ float d_scal[4 * SSTR];
__device__ volatile unsigned d_barcnt = 0;
__device__ volatile unsigned d_bargen = 0;

__device__ __forceinline__ void grid_barrier() {
    __syncthreads();
    if (threadIdx.x == 0) {
        unsigned g = d_bargen;
        __threadfence();
        unsigned a = atomicInc((unsigned*)&d_barcnt, NBLK - 1);
        if (a == NBLK - 1) {
            __threadfence();
            d_bargen = g + 1;
        } else {
            while (d_bargen == g) __nanosleep(128);
        }
        __threadfence();
    }
    __syncthreads();
}

// ---------------- CSR build ----------------
__global__ void count_kernel(const int* __restrict__ EI, int* __restrict__ cnt, int E) {
    int e = blockIdx.x * blockDim.x + threadIdx.x;
    if (e >= E) return;
    int r = EI[e], c = EI[E + e];
    if (r != c) atomicAdd(&cnt[r], 1);
}
__global__ void dinv_kernel(const int* __restrict__ cnt, float* __restrict__ dinv, int N) {
    int i = blockIdx.x * blockDim.x + threadIdx.x;
    if (i >= N) return;
    int d = cnt[i];
    dinv[i] = (d > 0) ? rsqrtf((float)d) : 0.f;
}
__global__ void blocksum_kernel(const int* __restrict__ cnt, int* __restrict__ bsum, int N) {
    __shared__ int sh[1024];
    int i = blockIdx.x * 1024 + threadIdx.x;
    sh[threadIdx.x] = (i < N) ? cnt[i] : 0;
    __syncthreads();
    for (int o = 512; o; o >>= 1) {
        if (threadIdx.x < o) sh[threadIdx.x] += sh[threadIdx.x + o];
        __syncthreads();
    }
    if (threadIdx.x == 0) bsum[blockIdx.x] = sh[0];
}
__global__ void scanbsum_kernel(int* __restrict__ bsum, int* __restrict__ rowptrN, int nb) {
    if (threadIdx.x == 0) {
        int run = 0;
        for (int i = 0; i < nb; i++) { int t = bsum[i]; bsum[i] = run; run += t; }
        *rowptrN = run;
    }
}
__global__ void localscan_kernel(int* __restrict__ cnt, int* __restrict__ rowptr,
                                 const int* __restrict__ bsum, int N) {
    __shared__ int sh[1024];
    int i = blockIdx.x * 1024 + threadIdx.x;
    int x = (i < N) ? cnt[i] : 0;
    sh[threadIdx.x] = x;
    __syncthreads();
    for (int off = 1; off < 1024; off <<= 1) {
        int t = (threadIdx.x >= off) ? sh[threadIdx.x - off] : 0;
        __syncthreads();
        sh[threadIdx.x] += t;
        __syncthreads();
    }
    if (i < N) { int excl = sh[threadIdx.x] - x + bsum[blockIdx.x]; rowptr[i] = excl; cnt[i] = excl; }
}
__global__ void fill_kernel(const int* __restrict__ EI, int* __restrict__ cursor,
                            const float* __restrict__ dinv, int* __restrict__ cols,
                            float* __restrict__ w, int E) {
    int e = blockIdx.x * blockDim.x + threadIdx.x;
    if (e >= E) return;
    int r = EI[e], c = EI[E + e];
    if (r != c) {
        int pos = atomicAdd(&cursor[r], 1);
        cols[pos] = c;
        w[pos] = -dinv[r] * dinv[c];
    }
}

// ---------------- weight pre-conversion (fp32 -> split bf16 hi/lo) ----------------
struct WPtrs { const float* p[17]; };

__global__ void wconv_kernel(WPtrs wp, __nv_bfloat16* WH, __nv_bfloat16* WL) {
    int slot = blockIdx.y;
    int rows = (slot == 16) ? 40 : 128;
    int i = (blockIdx.x * 256 + threadIdx.x) * 4;   // 0..16380
    int row = i >> 7;
    __nv_bfloat16* wh = WH + (size_t)slot * WSLOT + i;
    __nv_bfloat16* wl = WL + (size_t)slot * WSLOT + i;
    if (row < rows) {
        float4 v = *(const float4*)(wp.p[slot] + i);
        float a[4] = {v.x, v.y, v.z, v.w};
#pragma unroll
        for (int u = 0; u < 4; u++) {
            __nv_bfloat16 h = __float2bfloat16(a[u]);
            wh[u] = h;
            wl[u] = __float2bfloat16(a[u] - __bfloat162float(h));
        }
    } else {
#pragma unroll
        for (int u = 0; u < 4; u++) { wh[u] = __float2bfloat16(0.f); wl[u] = __float2bfloat16(0.f); }
    }
}

// ---------------- tensor-core GEMM ----------------
__device__ __forceinline__ void mma16816(float* c, const uint32_t* a, const uint32_t* b) {
    asm volatile(
        "mma.sync.aligned.m16n8k16.row.col.f32.bf16.bf16.f32 "
        "{%0,%1,%2,%3}, {%4,%5,%6,%7}, {%8,%9}, {%0,%1,%2,%3};\n"
        : "+f"(c[0]), "+f"(c[1]), "+f"(c[2]), "+f"(c[3])
        : "r"(a[0]), "r"(a[1]), "r"(a[2]), "r"(a[3]), "r"(b[0]), "r"(b[1]));
}
__device__ __forceinline__ void ldsm4(uint32_t* d, uint32_t addr) {
    asm volatile("ldmatrix.sync.aligned.m8n8.x4.shared.b16 {%0,%1,%2,%3}, [%4];"
                 : "=r"(d[0]), "=r"(d[1]), "=r"(d[2]), "=r"(d[3]) : "r"(addr));
}
__device__ __forceinline__ void ldsm2(uint32_t* d, uint32_t addr) {
    asm volatile("ldmatrix.sync.aligned.m8n8.x2.shared.b16 {%0,%1}, [%2];"
                 : "=r"(d[0]), "=r"(d[1]) : "r"(addr));
}
__device__ __forceinline__ void cp_async16(uint32_t dst, const void* src) {
    asm volatile("cp.async.cg.shared.global [%0], [%1], 16;" :: "r"(dst), "l"(src));
}

#define LDW 136
#define GSMEM ((2 * 64 + 2 * 128) * LDW * 2)

// A[N,128]fp32 @ (Wh+Wl)[128,128]bf16^T; EPI: 0 bias, 1 BN+ELU, 2 BN+ReLU
template <int EPI>
__device__ __forceinline__ void gemm_body(
    const float* __restrict__ A,
    const __nv_bfloat16* __restrict__ WHp, const __nv_bfloat16* __restrict__ WLp,
    const float* __restrict__ bsel, float* __restrict__ Csel, int N, int Oc,
    const float* __restrict__ bng, const float* __restrict__ bnb,
    const float* __restrict__ bnm, const float* __restrict__ bnv) {
    extern __shared__ __align__(16) char smem_raw[];
    __nv_bfloat16* Ah = (__nv_bfloat16*)smem_raw;
    __nv_bfloat16* Al = Ah + 64 * LDW;
    __nv_bfloat16* Wh = Al + 64 * LDW;
    __nv_bfloat16* Wl = Wh + 128 * LDW;

    const int tid = threadIdx.x;
    const int brow = blockIdx.x * 64;

    uint32_t sAh = (uint32_t)__cvta_generic_to_shared(Ah);
    uint32_t sAl = (uint32_t)__cvta_generic_to_shared(Al);
    uint32_t sWh = (uint32_t)__cvta_generic_to_shared(Wh);
    uint32_t sWl = (uint32_t)__cvta_generic_to_shared(Wl);

    // W planes: cp.async bf16 directly (row = 256B = 16 chunks of 16B)
#pragma unroll
    for (int i = 0; i < 8; i++) {
        int ch = i * 256 + tid;
        int row = ch >> 4, cc = ch & 15;
        cp_async16(sWh + (uint32_t)(row * (LDW * 2) + cc * 16),
                   (const char*)WHp + row * 256 + cc * 16);
    }
#pragma unroll
    for (int i = 0; i < 8; i++) {
        int ch = i * 256 + tid;
        int row = ch >> 4, cc = ch & 15;
        cp_async16(sWl + (uint32_t)(row * (LDW * 2) + cc * 16),
                   (const char*)WLp + row * 256 + cc * 16);
    }
    asm volatile("cp.async.commit_group;");

    // A: load fp32, split-convert, packed 8B stores
#pragma unroll
    for (int i = 0; i < 8; i++) {
        int fl = i * 256 + tid;
        int row = fl >> 5;
        int c4 = (fl & 31) << 2;
        float4 av = make_float4(0.f, 0.f, 0.f, 0.f);
        int gr = brow + row;
        if (gr < N) av = *(const float4*)(A + (size_t)gr * 128 + c4);
        float a[4] = {av.x, av.y, av.z, av.w};
        uint32_t hp[2], lp[2];
#pragma unroll
        for (int h2 = 0; h2 < 2; h2++) {
            __nv_bfloat16 h0 = __float2bfloat16(a[h2 * 2]);
            __nv_bfloat16 h1 = __float2bfloat16(a[h2 * 2 + 1]);
            __nv_bfloat16 l0 = __float2bfloat16(a[h2 * 2] - __bfloat162float(h0));
            __nv_bfloat16 l1 = __float2bfloat16(a[h2 * 2 + 1] - __bfloat162float(h1));
            hp[h2] = ((uint32_t)__bfloat16_as_ushort(h1) << 16) | __bfloat16_as_ushort(h0);
            lp[h2] = ((uint32_t)__bfloat16_as_ushort(l1) << 16) | __bfloat16_as_ushort(l0);
        }
        int base = row * LDW + c4;
        *(uint2*)&Ah[base] = make_uint2(hp[0], hp[1]);
        *(uint2*)&Al[base] = make_uint2(lp[0], lp[1]);
    }
    asm volatile("cp.async.wait_group 0;");
    __syncthreads();

    const int w = tid >> 5, lane = tid & 31;
    const int wm = w >> 2, wn = w & 3;

    float acc[2][4][4];
#pragma unroll
    for (int mt = 0; mt < 2; mt++)
#pragma unroll
        for (int nt = 0; nt < 4; nt++)
#pragma unroll
            for (int u = 0; u < 4; u++) acc[mt][nt][u] = 0.f;

    uint32_t aBase[3] = {sAh, sAl, sAh};
    uint32_t wBase[3] = {sWh, sWh, sWl};

#pragma unroll
    for (int p = 0; p < 3; p++) {
        uint32_t ab = aBase[p], wb = wBase[p];
#pragma unroll
        for (int kk = 0; kk < 8; kk++) {
            uint32_t bfr[4][2];
            {
                int r = lane & 7, sel = (lane >> 3) & 1;
                int kcol = kk * 16 + sel * 8;
#pragma unroll
                for (int nt = 0; nt < 4; nt++) {
                    int row = wn * 32 + nt * 8 + r;
                    ldsm2(bfr[nt], wb + (uint32_t)(row * LDW + kcol) * 2);
                }
            }
#pragma unroll
            for (int mt = 0; mt < 2; mt++) {
                uint32_t afr[4];
                int q = lane >> 3, r = lane & 7;
                int row = wm * 32 + mt * 16 + (q & 1) * 8 + r;
                int kcol = kk * 16 + (q >> 1) * 8;
                ldsm4(afr, ab + (uint32_t)(row * LDW + kcol) * 2);
#pragma unroll
                for (int nt = 0; nt < 4; nt++)
                    mma16816(acc[mt][nt], afr, bfr[nt]);
            }
        }
    }

    const int g = lane >> 2, t2 = (lane & 3) * 2;
#pragma unroll
    for (int mt = 0; mt < 2; mt++) {
#pragma unroll
        for (int nt = 0; nt < 4; nt++) {
            int col0 = wn * 32 + nt * 8 + t2;
#pragma unroll
            for (int half = 0; half < 2; half++) {
                int row = brow + wm * 32 + mt * 16 + g + half * 8;
                if (row >= N) continue;
#pragma unroll
                for (int u = 0; u < 2; u++) {
                    int col = col0 + u;
                    if (col >= Oc) continue;
                    float x = acc[mt][nt][half * 2 + u] + bsel[col];
                    if (EPI) {
                        float s = bng[col] * rsqrtf(bnv[col] + EPS_BN);
                        x = (x - bnm[col]) * s + bnb[col];
                        if (EPI == 1) x = (x > 0.f) ? x : expm1f(x);
                        else x = fmaxf(x, 0.f);
                    }
                    Csel[(size_t)row * Oc + col] = x;
                }
            }
        }
    }
}

template <int EPI>
__global__ __launch_bounds__(256, 2) void gemm_tc(
    const float* __restrict__ A,
    const __nv_bfloat16* WH1, const __nv_bfloat16* WL1, const float* b1, float* C1,
    const __nv_bfloat16* WH2, const __nv_bfloat16* WL2, const float* b2, float* C2,
    int N, int Oc,
    const float* __restrict__ bng, const float* __restrict__ bnb,
    const float* __restrict__ bnm, const float* __restrict__ bnv) {
    gemm_body<EPI>(A, blockIdx.y ? WH2 : WH1, blockIdx.y ? WL2 : WL1,
                   blockIdx.y ? b2 : b1, blockIdx.y ? C2 : C1, N, Oc, bng, bnb, bnm, bnv);
}

__global__ __launch_bounds__(256, 2) void gemm_tc_b4(
    const float* __restrict__ A, const __nv_bfloat16* WHb, const __nv_bfloat16* WLb,
    const float* __restrict__ bb, float* __restrict__ Cb, size_t Cstride, int N) {
    gemm_body<0>(A, WHb + (size_t)blockIdx.y * WSLOT, WLb + (size_t)blockIdx.y * WSLOT,
                 bb + (size_t)blockIdx.y * NH, Cb + (size_t)blockIdx.y * Cstride,
                 N, NH, 0, 0, 0, 0);
}

// ---------------- attention stats ----------------
__global__ void attn_kernel(const float* __restrict__ q0, const float* __restrict__ q1,
                            const float* __restrict__ q2, const float* __restrict__ q3,
                            const float* __restrict__ k0, const float* __restrict__ k1,
                            const float* __restrict__ k2, const float* __restrict__ k3,
                            const float* __restrict__ mha, float* __restrict__ Cm, int N) {
    const float scale = 0.08838834764831845f;
    float rfac = fmaxf(mha[0], 0.f);
    int lane = threadIdx.x & 31, wid = threadIdx.x >> 5;
    int gw = blockIdx.x * (blockDim.x >> 5) + wid;
    int tw = gridDim.x * (blockDim.x >> 5);
    const float* qs[4] = {q0, q1, q2, q3};
    const float* ks[4] = {k0, k1, k2, k3};
    float acc[16];
#pragma unroll
    for (int m = 0; m < 16; m++) acc[m] = 0.f;
    for (int n = gw; n < N; n += tw) {
        float4 qv[4], kv[4];
#pragma unroll
        for (int s = 0; s < 4; s++) {
            qv[s] = *(const float4*)(qs[s] + (size_t)n * NH + lane * 4);
            kv[s] = *(const float4*)(ks[s] + (size_t)n * NH + lane * 4);
        }
        float sc[16];
#pragma unroll
        for (int i = 0; i < 4; i++)
#pragma unroll
            for (int j = 0; j < 4; j++) {
                float4 a = qv[i], b = kv[j];
                sc[i * 4 + j] = a.x * b.x + a.y * b.y + a.z * b.z + a.w * b.w;
            }
#pragma unroll
        for (int m = 0; m < 16; m++) {
            float v = sc[m];
#pragma unroll
            for (int o = 16; o; o >>= 1) v += __shfl_xor_sync(0xffffffffu, v, o);
            sc[m] = v * scale;
        }
        if (lane == 0) {
#pragma unroll
            for (int i = 0; i < 4; i++) {
                float s0 = sc[i * 4], s1 = sc[i * 4 + 1], s2 = sc[i * 4 + 2], s3 = sc[i * 4 + 3];
                float mx = fmaxf(fmaxf(s0, s1), fmaxf(s2, s3));
                float e0 = expf(s0 - mx), e1 = expf(s1 - mx), e2 = expf(s2 - mx), e3 = expf(s3 - mx);
                float inv = 1.f / (e0 + e1 + e2 + e3);
                acc[i * 4 + 0] += logf(e0 * inv * rfac + 1e-4f);
                acc[i * 4 + 1] += logf(e1 * inv * rfac + 1e-4f);
                acc[i * 4 + 2] += logf(e2 * inv * rfac + 1e-4f);
                acc[i * 4 + 3] += logf(e3 * inv * rfac + 1e-4f);
            }
        }
    }
    __shared__ float sh[8][16];
    if (lane == 0)
#pragma unroll
        for (int m = 0; m < 16; m++) sh[wid][m] = acc[m];
    __syncthreads();
    int nw = blockDim.x >> 5;
    if (threadIdx.x < 16) {
        float s = 0.f;
        for (int w2 = 0; w2 < nw; w2++) s += sh[w2][threadIdx.x];
        atomicAdd(&Cm[threadIdx.x], s);
    }
}

__global__ void c_kernel(const float* __restrict__ CmAcc, float* __restrict__ c, float Ninv) {
    if (threadIdx.x == 0) {
        float M[16];
        for (int m = 0; m < 16; m++) M[m] = CmAcc[m] * Ninv;
        float cc[4], s = 0.f;
        for (int j = 0; j < 4; j++) { cc[j] = 0.5f * (M[12 + j] + M[j * 4 + 3]); s += cc[j]; }
        float invs = 1.f / s;
        for (int j = 0; j < 4; j++) c[j] = cc[j] * invs;
    }
}

__global__ void combine4(const float* __restrict__ a0, const float* __restrict__ a1,
                         const float* __restrict__ a2, const float* __restrict__ a3,
                         const float* __restrict__ c, float* __restrict__ out, int n4) {
    int i = blockIdx.x * blockDim.x + threadIdx.x;
    if (i >= n4) return;
    float c0 = c[0], c1 = c[1], c2 = c[2], c3 = c[3];
    float4 v0 = ((const float4*)a0)[i], v1 = ((const float4*)a1)[i];
    float4 v2 = ((const float4*)a2)[i], v3 = ((const float4*)a3)[i];
    float4 o;
    o.x = c0 * v0.x + c1 * v1.x + c2 * v2.x + c3 * v3.x;
    o.y = c0 * v0.y + c1 * v1.y + c2 * v2.y + c3 * v3.y;
    o.z = c0 * v0.z + c1 * v1.z + c2 * v2.z + c3 * v3.z;
    o.w = c0 * v0.w + c1 * v1.w + c2 * v2.w + c3 * v3.w;
    ((float4*)out)[i] = o;
}

// ---------------- persistent Chebyshev solve: X = Tr + A^{-1} Tr ----------------
__global__ __launch_bounds__(CGT, 1) void cheb_kernel(
    const float* __restrict__ T1, const float* __restrict__ A1,
    const float* __restrict__ A2, const float* __restrict__ AU,
    const float* __restrict__ bng, const float* __restrict__ bnb,
    const float* __restrict__ bnm, const float* __restrict__ bnv,
    const int* __restrict__ rowptr, const int* __restrict__ cols,
    const float* __restrict__ w, const float* __restrict__ Kap,
    float* __restrict__ X, float* __restrict__ ZA, float* __restrict__ ZB, int N) {
    const int n4 = N * (NH / 4);
    const int tid = blockIdx.x * CGT + threadIdx.x;
    const int nth = NBLK * CGT;
    const int lane = threadIdx.x & 31;

    for (int i = tid; i < n4; i += nth) {
        int col = (i << 2) & (NH - 1);
        float4 t1 = ((const float4*)T1)[i], a1 = ((const float4*)A1)[i];
        float4 a2 = ((const float4*)A2)[i], au = ((const float4*)AU)[i];
        float tt[4] = {t1.x, t1.y, t1.z, t1.w}, aa1[4] = {a1.x, a1.y, a1.z, a1.w};
        float aa2[4] = {a2.x, a2.y, a2.z, a2.w}, aau[4] = {au.x, au.y, au.z, au.w};
        float v[4], xv[4];
#pragma unroll
        for (int u = 0; u < 4; u++) {
            int cl = col + u;
            float d2 = fminf(fmaxf(aa2[u], -1.f), 1.f);
            float y = tt[u] + HCOEF * (aa1[u] + aau[u] + tt[u] * d2);
            float s = bng[cl] * rsqrtf(bnv[cl] + EPS_BN);
            y = (y - bnm[cl]) * s + bnb[cl];
            y = (y > 0.f) ? y : expm1f(y);
            v[u] = y;
            float kd = fminf(fmaxf(__ldg(&Kap[cl]), 0.f), 1.f);
            float hk = HCOEF * kd;
            xv[u] = (1.f + rsqrtf(1.f + 2.f * hk)) * y;   // Tr + w*T0 term
        }
        ((float4*)ZA)[i] = make_float4(v[0], v[1], v[2], v[3]);
        ((float4*)X)[i] = make_float4(xv[0], xv[1], xv[2], xv[3]);
    }
    grid_barrier();

    float4 sg, ck;
    {
        float4 kk = *(const float4*)(Kap + lane * 4);
        float kd[4] = {kk.x, kk.y, kk.z, kk.w};
        float sv[4], cv[4];
#pragma unroll
        for (int u = 0; u < 4; u++) {
            float k2 = fminf(fmaxf(kd[u], 0.f), 1.f);
            float hk = HCOEF * k2;
            float rt = sqrtf(1.f + 2.f * hk);
            float s = hk / (1.f + hk + rt);
            sv[u] = s;
            cv[u] = -2.f * s / rt;
        }
        sg = make_float4(sv[0], sv[1], sv[2], sv[3]);
        ck = make_float4(cv[0], cv[1], cv[2], cv[3]);
    }

    const int gw = tid >> 5;
    const int tw = nth >> 5;

#pragma unroll
    for (int k = 1; k <= CHEB_M; k++) {
        const float* cur = (k & 1) ? ZA : ZB;
        float* oth = (k & 1) ? ZB : ZA;
        for (int r = gw; r < N; r += tw) {
            int e0 = rowptr[r], e1 = rowptr[r + 1];
            float4 acc = make_float4(0.f, 0.f, 0.f, 0.f);
            for (int e = e0; e < e1; e++) {
                int c = __ldg(&cols[e]);
                float wt = __ldg(&w[e]);
                float4 y = *(const float4*)(cur + (size_t)c * NH + lane * 4);
                acc.x = fmaf(wt, y.x, acc.x); acc.y = fmaf(wt, y.y, acc.y);
                acc.z = fmaf(wt, y.z, acc.z); acc.w = fmaf(wt, y.w, acc.w);
            }
            float4 zn;
            if (k == 1) zn = acc;
            else {
                float4 zp = *(const float4*)(oth + (size_t)r * NH + lane * 4);
                zn.x = 2.f * acc.x - zp.x; zn.y = 2.f * acc.y - zp.y;
                zn.z = 2.f * acc.z - zp.z; zn.w = 2.f * acc.w - zp.w;
            }
            float4 xv = *(const float4*)(X + (size_t)r * NH + lane * 4);
            xv.x = fmaf(ck.x, zn.x, xv.x); xv.y = fmaf(ck.y, zn.y, xv.y);
            xv.z = fmaf(ck.z, zn.z, xv.z); xv.w = fmaf(ck.w, zn.w, xv.w);
            *(float4*)(X + (size_t)r * NH + lane * 4) = xv;
            *(float4*)(oth + (size_t)r * NH + lane * 4) = zn;
        }
        ck.x *= -sg.x; ck.y *= -sg.y; ck.z *= -sg.z; ck.w *= -sg.w;
        if (k < CHEB_M) grid_barrier();
    }
}

// ---------------- host ----------------
extern "C" void kernel_launch(void* const* d_in, const int* in_sizes, int n_in,
                              void* d_out, int out_size) {
    const float* T      = (const float*)d_in[0];
    const int*   EI     = (const int*)d_in[1];
    const float* KopenW = (const float*)d_in[2];
    const float* Kopenb = (const float*)d_in[3];
    const float* bnOg   = (const float*)d_in[4];
    const float* bnOb   = (const float*)d_in[5];
    const float* bnOm   = (const float*)d_in[6];
    const float* bnOv   = (const float*)d_in[7];
    const float* convW  = (const float*)d_in[8];
    const float* convb  = (const float*)d_in[9];
    const float* bnAg   = (const float*)d_in[10];
    const float* bnAb   = (const float*)d_in[11];
    const float* bnAm   = (const float*)d_in[12];
    const float* bnAv   = (const float*)d_in[13];
    const float* Wq     = (const float*)d_in[14];
    const float* bq     = (const float*)d_in[15];
    const float* Wk     = (const float*)d_in[16];
    const float* bk     = (const float*)d_in[17];
    const float* mha    = (const float*)d_in[18];
    const float* KR1W   = (const float*)d_in[19];
    const float* KR1b   = (const float*)d_in[20];
    const float* KR2W   = (const float*)d_in[21];
    const float* KR2b   = (const float*)d_in[22];
    const float* KRU0W  = (const float*)d_in[23];
    const float* KRU0b  = (const float*)d_in[24];
    const float* bng    = (const float*)d_in[25];
    const float* bnbp   = (const float*)d_in[26];
    const float* bnm    = (const float*)d_in[27];
    const float* bnv    = (const float*)d_in[28];
    const float* Kappa  = (const float*)d_in[29];
    const float* KcloseW= (const float*)d_in[30];
    const float* Kcloseb= (const float*)d_in[31];

    const int N = in_sizes[0] / NH;
    const int E = in_sizes[1] / 2;
    const int n4 = N * (NH / 4);
    const size_t S = (size_t)MAXN * NH;

    float *Th, *z, *Xb, *qb, *kb, *T1, *A1, *A2, *AUb, *ZA, *ZB, *dinvp, *wp, *scal;
    __nv_bfloat16 *WH, *WL;
    int *rowptr, *cnt, *bsum, *cols;
    cudaGetSymbolAddress((void**)&Th, d_Th);
    cudaGetSymbolAddress((void**)&z, d_z);
    cudaGetSymbolAddress((void**)&Xb, d_Xb);
    cudaGetSymbolAddress((void**)&qb, d_qb);
    cudaGetSymbolAddress((void**)&kb, d_kb);
    cudaGetSymbolAddress((void**)&T1, d_T1);
    cudaGetSymbolAddress((void**)&A1, d_A1);
    cudaGetSymbolAddress((void**)&A2, d_A2);
    cudaGetSymbolAddress((void**)&AUb, d_AUb);
    cudaGetSymbolAddress((void**)&ZA, d_ZA);
    cudaGetSymbolAddress((void**)&ZB, d_ZB);
    cudaGetSymbolAddress((void**)&WH, d_WH);
    cudaGetSymbolAddress((void**)&WL, d_WL);
    cudaGetSymbolAddress((void**)&dinvp, d_dinv);
    cudaGetSymbolAddress((void**)&wp, d_w);
    cudaGetSymbolAddress((void**)&scal, d_scal);
    cudaGetSymbolAddress((void**)&rowptr, d_rowptr);
    cudaGetSymbolAddress((void**)&cnt, d_cnt);
    cudaGetSymbolAddress((void**)&bsum, d_bsum);
    cudaGetSymbolAddress((void**)&cols, d_cols);

    static bool attr_done = false;
    if (!attr_done) {
        cudaFuncSetAttribute(gemm_tc<0>, cudaFuncAttributeMaxDynamicSharedMemorySize, GSMEM);
        cudaFuncSetAttribute(gemm_tc<1>, cudaFuncAttributeMaxDynamicSharedMemorySize, GSMEM);
        cudaFuncSetAttribute(gemm_tc<2>, cudaFuncAttributeMaxDynamicSharedMemorySize, GSMEM);
        cudaFuncSetAttribute(gemm_tc_b4, cudaFuncAttributeMaxDynamicSharedMemorySize, GSMEM);
        attr_done = true;
    }

    const int GBX = (N + 63) / 64;
    dim3 g1(GBX, 1), g2(GBX, 2), g4(GBX, 4);
    const int VB = (n4 + 255) / 256;

    cudaMemsetAsync(cnt, 0, (size_t)N * sizeof(int));
    cudaMemsetAsync(scal, 0, 4 * SSTR * sizeof(float));

    // weight pre-conversion (slots: 0 Kopen, 1 conv, 2 Wq, 3 Wk, 4-7 KR1, 8-11 KR2,
    // 12-15 KRU0, 16 Kclose)
    WPtrs wpt;
    wpt.p[0] = KopenW; wpt.p[1] = convW; wpt.p[2] = Wq; wpt.p[3] = Wk;
    for (int j = 0; j < 4; j++) {
        wpt.p[4 + j] = KR1W + (size_t)j * WSLOT;
        wpt.p[8 + j] = KR2W + (size_t)j * WSLOT;
        wpt.p[12 + j] = KRU0W + (size_t)j * WSLOT;
    }
    wpt.p[16] = KcloseW;
    wconv_kernel<<<dim3(16, 17), 256>>>(wpt, WH, WL);

    count_kernel<<<(E + 255) / 256, 256>>>(EI, cnt, E);
    dinv_kernel<<<(N + 255) / 256, 256>>>(cnt, dinvp, N);
    int nb = (N + 1023) / 1024;
    blocksum_kernel<<<nb, 1024>>>(cnt, bsum, N);

    gemm_tc<1><<<g1, 256, GSMEM>>>(T, WH, WL, Kopenb, Th, WH, WL, Kopenb, Th, N, NH,
                                   bnOg, bnOb, bnOm, bnOv);

    scanbsum_kernel<<<1, 32>>>(bsum, rowptr + N, nb);
    localscan_kernel<<<nb, 1024>>>(cnt, rowptr, bsum, N);
    fill_kernel<<<(E + 255) / 256, 256>>>(EI, cnt, dinvp, cols, wp, E);

    gemm_tc<2><<<g1, 256, GSMEM>>>(Th, WH + 1 * WSLOT, WL + 1 * WSLOT, convb, z,
                                   WH + 1 * WSLOT, WL + 1 * WSLOT, convb, z, N, NH,
                                   bnAg, bnAb, bnAm, bnAv);
    gemm_tc<0><<<g2, 256, GSMEM>>>(z, WH + 2 * WSLOT, WL + 2 * WSLOT, bq, qb,
                                   WH + 3 * WSLOT, WL + 3 * WSLOT, bk, kb, N, NH, 0, 0, 0, 0);
    gemm_tc_b4<<<g4, 256, GSMEM>>>(Th, WH + 12 * WSLOT, WL + 12 * WSLOT, KRU0b, AUb, S, N);

    for (int jj = 0; jj < 4; jj++) {
        if (jj > 0) {
            gemm_tc<0><<<g2, 256, GSMEM>>>(Xb + (jj - 1) * S,
                                           WH + 2 * WSLOT, WL + 2 * WSLOT, bq, qb + jj * S,
                                           WH + 3 * WSLOT, WL + 3 * WSLOT, bk, kb + jj * S,
                                           N, NH, 0, 0, 0, 0);
        }
        const float *aq[4], *ak[4], *aa[4];
        for (int o = 0; o < 4; o++) {
            if (o < 4 - jj) { aq[o] = qb; ak[o] = kb; aa[o] = z; }
            else {
                int m = o - 4 + jj;
                aq[o] = qb + (m + 1) * S; ak[o] = kb + (m + 1) * S; aa[o] = Xb + m * S;
            }
        }
        float* sl = scal + jj * SSTR;
        attn_kernel<<<400, 256>>>(aq[0], aq[1], aq[2], aq[3], ak[0], ak[1], ak[2], ak[3],
                                  mha, sl, N);
        c_kernel<<<1, 32>>>(sl, sl + 16, 1.0f / (float)N);
        combine4<<<VB, 256>>>(aa[0], aa[1], aa[2], aa[3], sl + 16, T1, n4);

        gemm_tc<0><<<g2, 256, GSMEM>>>(T1,
                                       WH + (4 + jj) * WSLOT, WL + (4 + jj) * WSLOT,
                                       KR1b + jj * NH, A1,
                                       WH + (8 + jj) * WSLOT, WL + (8 + jj) * WSLOT,
                                       KR2b + jj * NH, A2, N, NH, 0, 0, 0, 0);

        cheb_kernel<<<NBLK, CGT>>>(T1, A1, A2, AUb + jj * S, bng + jj * NH, bnbp + jj * NH,
                                   bnm + jj * NH, bnv + jj * NH, rowptr, cols, wp,
                                   Kappa + jj * NH, Xb + jj * S, ZA, ZB, N);
    }
    gemm_tc<0><<<g1, 256, GSMEM>>>(Xb + 3 * S, WH + 16 * WSLOT, WL + 16 * WSLOT, Kcloseb,
                                   (float*)d_out, WH + 16 * WSLOT, WL + 16 * WSLOT, Kcloseb,
                                   (float*)d_out, N, 40, 0, 0, 0, 0);
}

// round 9
// speedup vs baseline: 2.5506x; 1.1383x over previous
#include <cuda_runtime.h>
#include <cuda_bf16.h>
#include <math.h>
#include <stdint.h>

#define NH 128
#define MAXN 50000
#define MAXE 800000
#define HCOEF 0.1f
#define EPS_BN 1e-5f
#define SSTR 48
#define NBLK 148
#define CGT 1024
#define CHEB_M 3
#define WSLOT (NH * NH)

// ---------------- device scratch ----------------
__device__ float d_Th[MAXN * NH];
__device__ float d_z[MAXN * NH];
__device__ float d_Xb[4][MAXN * NH];
__device__ float d_vb[4][MAXN * NH];
__device__ float d_T1[MAXN * NH];
__device__ float d_A1[MAXN * NH];
__device__ float d_A2[MAXN * NH];
__device__ float d_AUb[4][MAXN * NH];
__device__ float d_ZA[MAXN * NH];
__device__ float d_ZB[MAXN * NH];
__device__ __nv_bfloat16 d_WH[17 * WSLOT];
__device__ __nv_bfloat16 d_WL[17 * WSLOT];
__device__ float d_M[WSLOT];
__device__ float d_uvec[NH];
__device__ float d_tvec[NH];
__device__ float d_c0s[1];
__device__ float d_zbias[NH];
__device__ int   d_rowptr[MAXN + 1];
__device__ int   d_cnt[MAXN];
__device__ int   d_bsum[64];
__device__ int   d_cols[MAXE];
__device__ float d_w[MAXE];
__device__ float d_dinv[MAXN];
__device__ float d_scal[4 * SSTR];
__device__ volatile unsigned d_barcnt = 0;
__device__ volatile unsigned d_bargen = 0;

__device__ __forceinline__ void grid_barrier() {
    __syncthreads();
    if (threadIdx.x == 0) {
        unsigned g = d_bargen;
        __threadfence();
        unsigned a = atomicInc((unsigned*)&d_barcnt, NBLK - 1);
        if (a == NBLK - 1) {
            __threadfence();
            d_bargen = g + 1;
        } else {
            while (d_bargen == g) __nanosleep(128);
        }
        __threadfence();
    }
    __syncthreads();
}

// ---------------- CSR build ----------------
__global__ void count_kernel(const int* __restrict__ EI, int* __restrict__ cnt, int E) {
    int e = blockIdx.x * blockDim.x + threadIdx.x;
    if (e >= E) return;
    int r = EI[e], c = EI[E + e];
    if (r != c) atomicAdd(&cnt[r], 1);
}
__global__ void dinv_kernel(const int* __restrict__ cnt, float* __restrict__ dinv, int N) {
    int i = blockIdx.x * blockDim.x + threadIdx.x;
    if (i >= N) return;
    int d = cnt[i];
    dinv[i] = (d > 0) ? rsqrtf((float)d) : 0.f;
}
__global__ void blocksum_kernel(const int* __restrict__ cnt, int* __restrict__ bsum, int N) {
    __shared__ int sh[1024];
    int i = blockIdx.x * 1024 + threadIdx.x;
    sh[threadIdx.x] = (i < N) ? cnt[i] : 0;
    __syncthreads();
    for (int o = 512; o; o >>= 1) {
        if (threadIdx.x < o) sh[threadIdx.x] += sh[threadIdx.x + o];
        __syncthreads();
    }
    if (threadIdx.x == 0) bsum[blockIdx.x] = sh[0];
}
__global__ void scanbsum_kernel(int* __restrict__ bsum, int* __restrict__ rowptrN, int nb) {
    if (threadIdx.x == 0) {
        int run = 0;
        for (int i = 0; i < nb; i++) { int t = bsum[i]; bsum[i] = run; run += t; }
        *rowptrN = run;
    }
}
__global__ void localscan_kernel(int* __restrict__ cnt, int* __restrict__ rowptr,
                                 const int* __restrict__ bsum, int N) {
    __shared__ int sh[1024];
    int i = blockIdx.x * 1024 + threadIdx.x;
    int x = (i < N) ? cnt[i] : 0;
    sh[threadIdx.x] = x;
    __syncthreads();
    for (int off = 1; off < 1024; off <<= 1) {
        int t = (threadIdx.x >= off) ? sh[threadIdx.x - off] : 0;
        __syncthreads();
        sh[threadIdx.x] += t;
        __syncthreads();
    }
    if (i < N) { int excl = sh[threadIdx.x] - x + bsum[blockIdx.x]; rowptr[i] = excl; cnt[i] = excl; }
}
__global__ void fill_kernel(const int* __restrict__ EI, int* __restrict__ cursor,
                            const float* __restrict__ dinv, int* __restrict__ cols,
                            float* __restrict__ w, int E) {
    int e = blockIdx.x * blockDim.x + threadIdx.x;
    if (e >= E) return;
    int r = EI[e], c = EI[E + e];
    if (r != c) {
        int pos = atomicAdd(&cursor[r], 1);
        cols[pos] = c;
        w[pos] = -dinv[r] * dinv[c];
    }
}

// ---------------- Gram precompute: M = Wq^T Wk ; u = Wk^T bq ; t = Wq^T bk ; c0 = bq.bk ----
__global__ void gram_kernel(const float* __restrict__ Wq, const float* __restrict__ Wk,
                            const float* __restrict__ bq, const float* __restrict__ bk,
                            float* __restrict__ M, float* __restrict__ uv,
                            float* __restrict__ tv, float* __restrict__ c0) {
    if (blockIdx.x < 64) {
        int idx = blockIdx.x * 256 + threadIdx.x;
        int e = idx >> 7, f = idx & 127;
        float s = 0.f;
        for (int d = 0; d < 128; d++)
            s = fmaf(__ldg(&Wq[d * 128 + e]), __ldg(&Wk[d * 128 + f]), s);
        M[e * 128 + f] = s;
    } else if (threadIdx.x < 128) {
        int f = threadIdx.x;
        float su = 0.f, st = 0.f;
        for (int d = 0; d < 128; d++) {
            su = fmaf(__ldg(&bq[d]), __ldg(&Wk[d * 128 + f]), su);
            st = fmaf(__ldg(&bk[d]), __ldg(&Wq[d * 128 + f]), st);
        }
        uv[f] = su;
        tv[f] = st;
        if (f == 0) {
            float s = 0.f;
            for (int d = 0; d < 128; d++) s = fmaf(bq[d], bk[d], s);
            *c0 = s;
        }
    }
}

// ---------------- weight pre-conversion ----------------
struct WPtrs { const float* p[17]; };

__global__ void wconv_kernel(WPtrs wp, __nv_bfloat16* WH, __nv_bfloat16* WL) {
    int slot = blockIdx.y;
    int rows = (slot == 16) ? 40 : 128;
    int i = (blockIdx.x * 256 + threadIdx.x) * 4;
    int row = i >> 7;
    __nv_bfloat16* wh = WH + (size_t)slot * WSLOT + i;
    __nv_bfloat16* wl = WL + (size_t)slot * WSLOT + i;
    if (row < rows) {
        float4 v = *(const float4*)(wp.p[slot] + i);
        float a[4] = {v.x, v.y, v.z, v.w};
#pragma unroll
        for (int u = 0; u < 4; u++) {
            __nv_bfloat16 h = __float2bfloat16(a[u]);
            wh[u] = h;
            wl[u] = __float2bfloat16(a[u] - __bfloat162float(h));
        }
    } else {
#pragma unroll
        for (int u = 0; u < 4; u++) { wh[u] = __float2bfloat16(0.f); wl[u] = __float2bfloat16(0.f); }
    }
}

// ---------------- tensor-core GEMM ----------------
__device__ __forceinline__ void mma16816(float* c, const uint32_t* a, const uint32_t* b) {
    asm volatile(
        "mma.sync.aligned.m16n8k16.row.col.f32.bf16.bf16.f32 "
        "{%0,%1,%2,%3}, {%4,%5,%6,%7}, {%8,%9}, {%0,%1,%2,%3};\n"
        : "+f"(c[0]), "+f"(c[1]), "+f"(c[2]), "+f"(c[3])
        : "r"(a[0]), "r"(a[1]), "r"(a[2]), "r"(a[3]), "r"(b[0]), "r"(b[1]));
}
__device__ __forceinline__ void ldsm4(uint32_t* d, uint32_t addr) {
    asm volatile("ldmatrix.sync.aligned.m8n8.x4.shared.b16 {%0,%1,%2,%3}, [%4];"
                 : "=r"(d[0]), "=r"(d[1]), "=r"(d[2]), "=r"(d[3]) : "r"(addr));
}
__device__ __forceinline__ void ldsm2(uint32_t* d, uint32_t addr) {
    asm volatile("ldmatrix.sync.aligned.m8n8.x2.shared.b16 {%0,%1}, [%2];"
                 : "=r"(d[0]), "=r"(d[1]) : "r"(addr));
}
__device__ __forceinline__ void cp_async16(uint32_t dst, const void* src) {
    asm volatile("cp.async.cg.shared.global [%0], [%1], 16;" :: "r"(dst), "l"(src));
}

#define LDW 136
#define GSMEM ((2 * 64 + 2 * 128) * LDW * 2)

template <int EPI>
__device__ __forceinline__ void gemm_body(
    const float* __restrict__ A,
    const __nv_bfloat16* __restrict__ WHp, const __nv_bfloat16* __restrict__ WLp,
    const float* __restrict__ bsel, float* __restrict__ Csel, int N, int Oc,
    const float* __restrict__ bng, const float* __restrict__ bnb,
    const float* __restrict__ bnm, const float* __restrict__ bnv) {
    extern __shared__ __align__(16) char smem_raw[];
    __nv_bfloat16* Ah = (__nv_bfloat16*)smem_raw;
    __nv_bfloat16* Al = Ah + 64 * LDW;
    __nv_bfloat16* Wh = Al + 64 * LDW;
    __nv_bfloat16* Wl = Wh + 128 * LDW;

    const int tid = threadIdx.x;
    const int brow = blockIdx.x * 64;

    uint32_t sAh = (uint32_t)__cvta_generic_to_shared(Ah);
    uint32_t sAl = (uint32_t)__cvta_generic_to_shared(Al);
    uint32_t sWh = (uint32_t)__cvta_generic_to_shared(Wh);
    uint32_t sWl = (uint32_t)__cvta_generic_to_shared(Wl);

#pragma unroll
    for (int i = 0; i < 8; i++) {
        int ch = i * 256 + tid;
        int row = ch >> 4, cc = ch & 15;
        cp_async16(sWh + (uint32_t)(row * (LDW * 2) + cc * 16),
                   (const char*)WHp + row * 256 + cc * 16);
    }
#pragma unroll
    for (int i = 0; i < 8; i++) {
        int ch = i * 256 + tid;
        int row = ch >> 4, cc = ch & 15;
        cp_async16(sWl + (uint32_t)(row * (LDW * 2) + cc * 16),
                   (const char*)WLp + row * 256 + cc * 16);
    }
    asm volatile("cp.async.commit_group;");

#pragma unroll
    for (int i = 0; i < 8; i++) {
        int fl = i * 256 + tid;
        int row = fl >> 5;
        int c4 = (fl & 31) << 2;
        float4 av = make_float4(0.f, 0.f, 0.f, 0.f);
        int gr = brow + row;
        if (gr < N) av = *(const float4*)(A + (size_t)gr * 128 + c4);
        float a[4] = {av.x, av.y, av.z, av.w};
        uint32_t hp[2], lp[2];
#pragma unroll
        for (int h2 = 0; h2 < 2; h2++) {
            __nv_bfloat16 h0 = __float2bfloat16(a[h2 * 2]);
            __nv_bfloat16 h1 = __float2bfloat16(a[h2 * 2 + 1]);
            __nv_bfloat16 l0 = __float2bfloat16(a[h2 * 2] - __bfloat162float(h0));
            __nv_bfloat16 l1 = __float2bfloat16(a[h2 * 2 + 1] - __bfloat162float(h1));
            hp[h2] = ((uint32_t)__bfloat16_as_ushort(h1) << 16) | __bfloat16_as_ushort(h0);
            lp[h2] = ((uint32_t)__bfloat16_as_ushort(l1) << 16) | __bfloat16_as_ushort(l0);
        }
        int base = row * LDW + c4;
        *(uint2*)&Ah[base] = make_uint2(hp[0], hp[1]);
        *(uint2*)&Al[base] = make_uint2(lp[0], lp[1]);
    }
    asm volatile("cp.async.wait_group 0;");
    __syncthreads();

    const int w = tid >> 5, lane = tid & 31;
    const int wm = w >> 2, wn = w & 3;

    float acc[2][4][4];
#pragma unroll
    for (int mt = 0; mt < 2; mt++)
#pragma unroll
        for (int nt = 0; nt < 4; nt++)
#pragma unroll
            for (int u = 0; u < 4; u++) acc[mt][nt][u] = 0.f;

    uint32_t aBase[3] = {sAh, sAl, sAh};
    uint32_t wBase[3] = {sWh, sWh, sWl};

#pragma unroll
    for (int p = 0; p < 3; p++) {
        uint32_t ab = aBase[p], wb = wBase[p];
#pragma unroll
        for (int kk = 0; kk < 8; kk++) {
            uint32_t bfr[4][2];
            {
                int r = lane & 7, sel = (lane >> 3) & 1;
                int kcol = kk * 16 + sel * 8;
#pragma unroll
                for (int nt = 0; nt < 4; nt++) {
                    int row = wn * 32 + nt * 8 + r;
                    ldsm2(bfr[nt], wb + (uint32_t)(row * LDW + kcol) * 2);
                }
            }
#pragma unroll
            for (int mt = 0; mt < 2; mt++) {
                uint32_t afr[4];
                int q = lane >> 3, r = lane & 7;
                int row = wm * 32 + mt * 16 + (q & 1) * 8 + r;
                int kcol = kk * 16 + (q >> 1) * 8;
                ldsm4(afr, ab + (uint32_t)(row * LDW + kcol) * 2);
#pragma unroll
                for (int nt = 0; nt < 4; nt++)
                    mma16816(acc[mt][nt], afr, bfr[nt]);
            }
        }
    }

    const int g = lane >> 2, t2 = (lane & 3) * 2;
#pragma unroll
    for (int mt = 0; mt < 2; mt++) {
#pragma unroll
        for (int nt = 0; nt < 4; nt++) {
            int col0 = wn * 32 + nt * 8 + t2;
#pragma unroll
            for (int half = 0; half < 2; half++) {
                int row = brow + wm * 32 + mt * 16 + g + half * 8;
                if (row >= N) continue;
#pragma unroll
                for (int u = 0; u < 2; u++) {
                    int col = col0 + u;
                    if (col >= Oc) continue;
                    float x = acc[mt][nt][half * 2 + u] + bsel[col];
                    if (EPI) {
                        float s = bng[col] * rsqrtf(bnv[col] + EPS_BN);
                        x = (x - bnm[col]) * s + bnb[col];
                        if (EPI == 1) x = (x > 0.f) ? x : expm1f(x);
                        else x = fmaxf(x, 0.f);
                    }
                    Csel[(size_t)row * Oc + col] = x;
                }
            }
        }
    }
}

template <int EPI>
__global__ __launch_bounds__(256, 2) void gemm_tc(
    const float* __restrict__ A,
    const __nv_bfloat16* WH1, const __nv_bfloat16* WL1, const float* b1, float* C1,
    const __nv_bfloat16* WH2, const __nv_bfloat16* WL2, const float* b2, float* C2,
    int N, int Oc,
    const float* __restrict__ bng, const float* __restrict__ bnb,
    const float* __restrict__ bnm, const float* __restrict__ bnv) {
    gemm_body<EPI>(A, blockIdx.y ? WH2 : WH1, blockIdx.y ? WL2 : WL1,
                   blockIdx.y ? b2 : b1, blockIdx.y ? C2 : C1, N, Oc, bng, bnb, bnm, bnv);
}

__global__ __launch_bounds__(256, 2) void gemm_tc_b4(
    const float* __restrict__ A, const __nv_bfloat16* WHb, const __nv_bfloat16* WLb,
    const float* __restrict__ bb, float* __restrict__ Cb, size_t Cstride, int N) {
    gemm_body<0>(A, WHb + (size_t)blockIdx.y * WSLOT, WLb + (size_t)blockIdx.y * WSLOT,
                 bb + (size_t)blockIdx.y * NH, Cb + (size_t)blockIdx.y * Cstride,
                 N, NH, 0, 0, 0, 0);
}

// ---------------- attention stats via Gram trick ----------------
// s_ij = (a_i . v_j + t.a_i + u.a_j + c0) * scale, v = a @ M^T
__global__ void attn_kernel(const float* __restrict__ a0, const float* __restrict__ a1,
                            const float* __restrict__ a2, const float* __restrict__ a3,
                            const float* __restrict__ v0, const float* __restrict__ v1,
                            const float* __restrict__ v2, const float* __restrict__ v3,
                            const float* __restrict__ uvp, const float* __restrict__ tvp,
                            const float* __restrict__ c0p,
                            const float* __restrict__ mha, float* __restrict__ Cm, int N) {
    const float scale = 0.08838834764831845f;
    float rfac = fmaxf(mha[0], 0.f);
    float c0 = *c0p;
    int lane = threadIdx.x & 31, wid = threadIdx.x >> 5;
    int gw = blockIdx.x * (blockDim.x >> 5) + wid;
    int tw = gridDim.x * (blockDim.x >> 5);
    const float* as[4] = {a0, a1, a2, a3};
    const float* vs[4] = {v0, v1, v2, v3};
    float4 u4 = *(const float4*)(uvp + lane * 4);
    float4 t4 = *(const float4*)(tvp + lane * 4);
    float acc[16];
#pragma unroll
    for (int m = 0; m < 16; m++) acc[m] = 0.f;
    for (int n = gw; n < N; n += tw) {
        float4 av[4], vv[4];
#pragma unroll
        for (int s = 0; s < 4; s++) {
            av[s] = *(const float4*)(as[s] + (size_t)n * NH + lane * 4);
            vv[s] = *(const float4*)(vs[s] + (size_t)n * NH + lane * 4);
        }
        float red[24];
#pragma unroll
        for (int i = 0; i < 4; i++)
#pragma unroll
            for (int j = 0; j < 4; j++) {
                float4 a = av[i], b = vv[j];
                red[i * 4 + j] = a.x * b.x + a.y * b.y + a.z * b.z + a.w * b.w;
            }
#pragma unroll
        for (int i = 0; i < 4; i++) {
            float4 a = av[i];
            red[16 + i] = t4.x * a.x + t4.y * a.y + t4.z * a.z + t4.w * a.w;  // t.a_i
            red[20 + i] = u4.x * a.x + u4.y * a.y + u4.z * a.z + u4.w * a.w;  // u.a_i
        }
#pragma unroll
        for (int m = 0; m < 24; m++) {
            float v = red[m];
#pragma unroll
            for (int o = 16; o; o >>= 1) v += __shfl_xor_sync(0xffffffffu, v, o);
            red[m] = v;
        }
        if (lane == 0) {
#pragma unroll
            for (int i = 0; i < 4; i++) {
                float s[4];
#pragma unroll
                for (int j = 0; j < 4; j++)
                    s[j] = (red[i * 4 + j] + red[16 + i] + red[20 + j] + c0) * scale;
                float mx = fmaxf(fmaxf(s[0], s[1]), fmaxf(s[2], s[3]));
                float e0 = expf(s[0] - mx), e1 = expf(s[1] - mx);
                float e2 = expf(s[2] - mx), e3 = expf(s[3] - mx);
                float inv = 1.f / (e0 + e1 + e2 + e3);
                acc[i * 4 + 0] += logf(e0 * inv * rfac + 1e-4f);
                acc[i * 4 + 1] += logf(e1 * inv * rfac + 1e-4f);
                acc[i * 4 + 2] += logf(e2 * inv * rfac + 1e-4f);
                acc[i * 4 + 3] += logf(e3 * inv * rfac + 1e-4f);
            }
        }
    }
    __shared__ float sh[8][16];
    if (lane == 0)
#pragma unroll
        for (int m = 0; m < 16; m++) sh[wid][m] = acc[m];
    __syncthreads();
    int nw = blockDim.x >> 5;
    if (threadIdx.x < 16) {
        float s = 0.f;
        for (int w2 = 0; w2 < nw; w2++) s += sh[w2][threadIdx.x];
        atomicAdd(&Cm[threadIdx.x], s);
    }
}

// combine with inline c computation from CmAcc
__global__ void combine4(const float* __restrict__ a0, const float* __restrict__ a1,
                         const float* __restrict__ a2, const float* __restrict__ a3,
                         const float* __restrict__ CmAcc, float Ninv,
                         float* __restrict__ out, int n4) {
    int i = blockIdx.x * blockDim.x + threadIdx.x;
    if (i >= n4) return;
    float c[4];
    {
        float M[16];
#pragma unroll
        for (int m = 0; m < 16; m++) M[m] = __ldg(&CmAcc[m]) * Ninv;
        float s = 0.f;
#pragma unroll
        for (int j = 0; j < 4; j++) { c[j] = 0.5f * (M[12 + j] + M[j * 4 + 3]); s += c[j]; }
        float invs = 1.f / s;
#pragma unroll
        for (int j = 0; j < 4; j++) c[j] *= invs;
    }
    float4 v0 = ((const float4*)a0)[i], v1 = ((const float4*)a1)[i];
    float4 v2 = ((const float4*)a2)[i], v3 = ((const float4*)a3)[i];
    float4 o;
    o.x = c[0] * v0.x + c[1] * v1.x + c[2] * v2.x + c[3] * v3.x;
    o.y = c[0] * v0.y + c[1] * v1.y + c[2] * v2.y + c[3] * v3.y;
    o.z = c[0] * v0.z + c[1] * v1.z + c[2] * v2.z + c[3] * v3.z;
    o.w = c[0] * v0.w + c[1] * v1.w + c[2] * v2.w + c[3] * v3.w;
    ((float4*)out)[i] = o;
}

// ---------------- persistent Chebyshev solve: X = Tr + A^{-1} Tr ----------------
__global__ __launch_bounds__(CGT, 1) void cheb_kernel(
    const float* __restrict__ T1, const float* __restrict__ A1,
    const float* __restrict__ A2, const float* __restrict__ AU,
    const float* __restrict__ bng, const float* __restrict__ bnb,
    const float* __restrict__ bnm, const float* __restrict__ bnv,
    const int* __restrict__ rowptr, const int* __restrict__ cols,
    const float* __restrict__ w, const float* __restrict__ Kap,
    float* __restrict__ X, float* __restrict__ ZA, float* __restrict__ ZB, int N) {
    const int n4 = N * (NH / 4);
    const int tid = blockIdx.x * CGT + threadIdx.x;
    const int nth = NBLK * CGT;
    const int lane = threadIdx.x & 31;

    for (int i = tid; i < n4; i += nth) {
        int col = (i << 2) & (NH - 1);
        float4 t1 = ((const float4*)T1)[i], a1 = ((const float4*)A1)[i];
        float4 a2 = ((const float4*)A2)[i], au = ((const float4*)AU)[i];
        float tt[4] = {t1.x, t1.y, t1.z, t1.w}, aa1[4] = {a1.x, a1.y, a1.z, a1.w};
        float aa2[4] = {a2.x, a2.y, a2.z, a2.w}, aau[4] = {au.x, au.y, au.z, au.w};
        float v[4], xv[4];
#pragma unroll
        for (int u = 0; u < 4; u++) {
            int cl = col + u;
            float d2 = fminf(fmaxf(aa2[u], -1.f), 1.f);
            float y = tt[u] + HCOEF * (aa1[u] + aau[u] + tt[u] * d2);
            float s = bng[cl] * rsqrtf(bnv[cl] + EPS_BN);
            y = (y - bnm[cl]) * s + bnb[cl];
            y = (y > 0.f) ? y : expm1f(y);
            v[u] = y;
            float kd = fminf(fmaxf(__ldg(&Kap[cl]), 0.f), 1.f);
            float hk = HCOEF * kd;
            xv[u] = (1.f + rsqrtf(1.f + 2.f * hk)) * y;
        }
        ((float4*)ZA)[i] = make_float4(v[0], v[1], v[2], v[3]);
        ((float4*)X)[i] = make_float4(xv[0], xv[1], xv[2], xv[3]);
    }
    grid_barrier();

    float4 sg, ck;
    {
        float4 kk = *(const float4*)(Kap + lane * 4);
        float kd[4] = {kk.x, kk.y, kk.z, kk.w};
        float sv[4], cv[4];
#pragma unroll
        for (int u = 0; u < 4; u++) {
            float k2 = fminf(fmaxf(kd[u], 0.f), 1.f);
            float hk = HCOEF * k2;
            float rt = sqrtf(1.f + 2.f * hk);
            float s = hk / (1.f + hk + rt);
            sv[u] = s;
            cv[u] = -2.f * s / rt;
        }
        sg = make_float4(sv[0], sv[1], sv[2], sv[3]);
        ck = make_float4(cv[0], cv[1], cv[2], cv[3]);
    }

    const int gw = tid >> 5;
    const int tw = nth >> 5;

#pragma unroll
    for (int k = 1; k <= CHEB_M; k++) {
        const float* cur = (k & 1) ? ZA : ZB;
        float* oth = (k & 1) ? ZB : ZA;
        for (int r = gw; r < N; r += tw) {
            int e0 = rowptr[r], e1 = rowptr[r + 1];
            float4 acc = make_float4(0.f, 0.f, 0.f, 0.f);
            for (int e = e0; e < e1; e++) {
                int c = __ldg(&cols[e]);
                float wt = __ldg(&w[e]);
                float4 y = *(const float4*)(cur + (size_t)c * NH + lane * 4);
                acc.x = fmaf(wt, y.x, acc.x); acc.y = fmaf(wt, y.y, acc.y);
                acc.z = fmaf(wt, y.z, acc.z); acc.w = fmaf(wt, y.w, acc.w);
            }
            float4 zn;
            if (k == 1) zn = acc;
            else {
                float4 zp = *(const float4*)(oth + (size_t)r * NH + lane * 4);
                zn.x = 2.f * acc.x - zp.x; zn.y = 2.f * acc.y - zp.y;
                zn.z = 2.f * acc.z - zp.z; zn.w = 2.f * acc.w - zp.w;
            }
            float4 xv = *(const float4*)(X + (size_t)r * NH + lane * 4);
            xv.x = fmaf(ck.x, zn.x, xv.x); xv.y = fmaf(ck.y, zn.y, xv.y);
            xv.z = fmaf(ck.z, zn.z, xv.z); xv.w = fmaf(ck.w, zn.w, xv.w);
            *(float4*)(X + (size_t)r * NH + lane * 4) = xv;
            *(float4*)(oth + (size_t)r * NH + lane * 4) = zn;
        }
        ck.x *= -sg.x; ck.y *= -sg.y; ck.z *= -sg.z; ck.w *= -sg.w;
        if (k < CHEB_M) grid_barrier();
    }
}

// ---------------- host ----------------
extern "C" void kernel_launch(void* const* d_in, const int* in_sizes, int n_in,
                              void* d_out, int out_size) {
    const float* T      = (const float*)d_in[0];
    const int*   EI     = (const int*)d_in[1];
    const float* KopenW = (const float*)d_in[2];
    const float* Kopenb = (const float*)d_in[3];
    const float* bnOg   = (const float*)d_in[4];
    const float* bnOb   = (const float*)d_in[5];
    const float* bnOm   = (const float*)d_in[6];
    const float* bnOv   = (const float*)d_in[7];
    const float* convW  = (const float*)d_in[8];
    const float* convb  = (const float*)d_in[9];
    const float* bnAg   = (const float*)d_in[10];
    const float* bnAb   = (const float*)d_in[11];
    const float* bnAm   = (const float*)d_in[12];
    const float* bnAv   = (const float*)d_in[13];
    const float* Wq     = (const float*)d_in[14];
    const float* bq     = (const float*)d_in[15];
    const float* Wk     = (const float*)d_in[16];
    const float* bk     = (const float*)d_in[17];
    const float* mha    = (const float*)d_in[18];
    const float* KR1W   = (const float*)d_in[19];
    const float* KR1b   = (const float*)d_in[20];
    const float* KR2W   = (const float*)d_in[21];
    const float* KR2b   = (const float*)d_in[22];
    const float* KRU0W  = (const float*)d_in[23];
    const float* KRU0b  = (const float*)d_in[24];
    const float* bng    = (const float*)d_in[25];
    const float* bnbp   = (const float*)d_in[26];
    const float* bnm    = (const float*)d_in[27];
    const float* bnv    = (const float*)d_in[28];
    const float* Kappa  = (const float*)d_in[29];
    const float* KcloseW= (const float*)d_in[30];
    const float* Kcloseb= (const float*)d_in[31];

    const int N = in_sizes[0] / NH;
    const int E = in_sizes[1] / 2;
    const int n4 = N * (NH / 4);
    const size_t S = (size_t)MAXN * NH;

    float *Th, *z, *Xb, *vb, *T1, *A1, *A2, *AUb, *ZA, *ZB, *dinvp, *wp, *scal;
    float *Mg, *uvp, *tvp, *c0p, *zb;
    __nv_bfloat16 *WH, *WL;
    int *rowptr, *cnt, *bsum, *cols;
    cudaGetSymbolAddress((void**)&Th, d_Th);
    cudaGetSymbolAddress((void**)&z, d_z);
    cudaGetSymbolAddress((void**)&Xb, d_Xb);
    cudaGetSymbolAddress((void**)&vb, d_vb);
    cudaGetSymbolAddress((void**)&T1, d_T1);
    cudaGetSymbolAddress((void**)&A1, d_A1);
    cudaGetSymbolAddress((void**)&A2, d_A2);
    cudaGetSymbolAddress((void**)&AUb, d_AUb);
    cudaGetSymbolAddress((void**)&ZA, d_ZA);
    cudaGetSymbolAddress((void**)&ZB, d_ZB);
    cudaGetSymbolAddress((void**)&WH, d_WH);
    cudaGetSymbolAddress((void**)&WL, d_WL);
    cudaGetSymbolAddress((void**)&Mg, d_M);
    cudaGetSymbolAddress((void**)&uvp, d_uvec);
    cudaGetSymbolAddress((void**)&tvp, d_tvec);
    cudaGetSymbolAddress((void**)&c0p, d_c0s);
    cudaGetSymbolAddress((void**)&zb, d_zbias);
    cudaGetSymbolAddress((void**)&dinvp, d_dinv);
    cudaGetSymbolAddress((void**)&wp, d_w);
    cudaGetSymbolAddress((void**)&scal, d_scal);
    cudaGetSymbolAddress((void**)&rowptr, d_rowptr);
    cudaGetSymbolAddress((void**)&cnt, d_cnt);
    cudaGetSymbolAddress((void**)&bsum, d_bsum);
    cudaGetSymbolAddress((void**)&cols, d_cols);

    static bool attr_done = false;
    if (!attr_done) {
        cudaFuncSetAttribute(gemm_tc<0>, cudaFuncAttributeMaxDynamicSharedMemorySize, GSMEM);
        cudaFuncSetAttribute(gemm_tc<1>, cudaFuncAttributeMaxDynamicSharedMemorySize, GSMEM);
        cudaFuncSetAttribute(gemm_tc<2>, cudaFuncAttributeMaxDynamicSharedMemorySize, GSMEM);
        cudaFuncSetAttribute(gemm_tc_b4, cudaFuncAttributeMaxDynamicSharedMemorySize, GSMEM);
        attr_done = true;
    }

    const int GBX = (N + 63) / 64;
    dim3 g1(GBX, 1), g2(GBX, 2), g4(GBX, 4);
    const int VB = (n4 + 255) / 256;

    cudaMemsetAsync(cnt, 0, (size_t)N * sizeof(int));
    cudaMemsetAsync(scal, 0, 4 * SSTR * sizeof(float));
    cudaMemsetAsync(zb, 0, NH * sizeof(float));

    // Gram precompute, then weight conversion (slot 2 = M; slot 3 unused)
    gram_kernel<<<65, 256>>>(Wq, Wk, bq, bk, Mg, uvp, tvp, c0p);

    WPtrs wpt;
    wpt.p[0] = KopenW; wpt.p[1] = convW; wpt.p[2] = Mg; wpt.p[3] = Mg;
    for (int j = 0; j < 4; j++) {
        wpt.p[4 + j] = KR1W + (size_t)j * WSLOT;
        wpt.p[8 + j] = KR2W + (size_t)j * WSLOT;
        wpt.p[12 + j] = KRU0W + (size_t)j * WSLOT;
    }
    wpt.p[16] = KcloseW;
    wconv_kernel<<<dim3(16, 17), 256>>>(wpt, WH, WL);

    count_kernel<<<(E + 255) / 256, 256>>>(EI, cnt, E);
    dinv_kernel<<<(N + 255) / 256, 256>>>(cnt, dinvp, N);
    int nb = (N + 1023) / 1024;
    blocksum_kernel<<<nb, 1024>>>(cnt, bsum, N);

    gemm_tc<1><<<g1, 256, GSMEM>>>(T, WH, WL, Kopenb, Th, WH, WL, Kopenb, Th, N, NH,
                                   bnOg, bnOb, bnOm, bnOv);

    scanbsum_kernel<<<1, 32>>>(bsum, rowptr + N, nb);
    localscan_kernel<<<nb, 1024>>>(cnt, rowptr, bsum, N);
    fill_kernel<<<(E + 255) / 256, 256>>>(EI, cnt, dinvp, cols, wp, E);

    gemm_tc<2><<<g1, 256, GSMEM>>>(Th, WH + 1 * WSLOT, WL + 1 * WSLOT, convb, z,
                                   WH + 1 * WSLOT, WL + 1 * WSLOT, convb, z, N, NH,
                                   bnAg, bnAb, bnAm, bnAv);
    // v0 = z @ M^T
    gemm_tc<0><<<g1, 256, GSMEM>>>(z, WH + 2 * WSLOT, WL + 2 * WSLOT, zb, vb,
                                   WH + 2 * WSLOT, WL + 2 * WSLOT, zb, vb, N, NH, 0, 0, 0, 0);
    gemm_tc_b4<<<g4, 256, GSMEM>>>(Th, WH + 12 * WSLOT, WL + 12 * WSLOT, KRU0b, AUb, S, N);

    for (int jj = 0; jj < 4; jj++) {
        if (jj > 0) {
            // v_jj = X_{jj-1} @ M^T
            gemm_tc<0><<<g1, 256, GSMEM>>>(Xb + (jj - 1) * S,
                                           WH + 2 * WSLOT, WL + 2 * WSLOT, zb, vb + jj * S,
                                           WH + 2 * WSLOT, WL + 2 * WSLOT, zb, vb + jj * S,
                                           N, NH, 0, 0, 0, 0);
        }
        const float *aa[4], *av[4];
        for (int o = 0; o < 4; o++) {
            if (o < 4 - jj) { aa[o] = z; av[o] = vb; }
            else {
                int m = o - 4 + jj;
                aa[o] = Xb + m * S; av[o] = vb + (m + 1) * S;
            }
        }
        float* sl = scal + jj * SSTR;
        attn_kernel<<<400, 256>>>(aa[0], aa[1], aa[2], aa[3], av[0], av[1], av[2], av[3],
                                  uvp, tvp, c0p, mha, sl, N);
        combine4<<<VB, 256>>>(aa[0], aa[1], aa[2], aa[3], sl, 1.0f / (float)N, T1, n4);

        gemm_tc<0><<<g2, 256, GSMEM>>>(T1,
                                       WH + (4 + jj) * WSLOT, WL + (4 + jj) * WSLOT,
                                       KR1b + jj * NH, A1,
                                       WH + (8 + jj) * WSLOT, WL + (8 + jj) * WSLOT,
                                       KR2b + jj * NH, A2, N, NH, 0, 0, 0, 0);

        cheb_kernel<<<NBLK, CGT>>>(T1, A1, A2, AUb + jj * S, bng + jj * NH, bnbp + jj * NH,
                                   bnm + jj * NH, bnv + jj * NH, rowptr, cols, wp,
                                   Kappa + jj * NH, Xb + jj * S, ZA, ZB, N);
    }
    gemm_tc<0><<<g1, 256, GSMEM>>>(Xb + 3 * S, WH + 16 * WSLOT, WL + 16 * WSLOT, Kcloseb,
                                   (float*)d_out, WH + 16 * WSLOT, WL + 16 * WSLOT, Kcloseb,
                                   (float*)d_out, N, 40, 0, 0, 0, 0);
}

// round 10
// speedup vs baseline: 2.8466x; 1.1161x over previous
#include <cuda_runtime.h>
#include <cuda_bf16.h>
#include <math.h>
#include <stdint.h>

#define NH 128
#define MAXN 50000
#define MAXE 800000
#define HCOEF 0.1f
#define EPS_BN 1e-5f
#define SSTR 48
#define NBLK 148
#define CGT 1024
#define CHEB_M 3
#define WSLOT (NH * NH)
#define MAXR 11   // ceil(MAXN / (NBLK*CGT/32))

// ---------------- device scratch ----------------
__device__ float d_Th[MAXN * NH];
__device__ float d_z[MAXN * NH];
__device__ float d_Xb[4][MAXN * NH];
__device__ float d_vb[4][MAXN * NH];
__device__ float d_T1[MAXN * NH];
__device__ float d_A1[MAXN * NH];
__device__ float d_A2[MAXN * NH];
__device__ float d_AUb[4][MAXN * NH];
__device__ __nv_bfloat16 d_ZA[MAXN * NH];
__device__ __nv_bfloat16 d_ZB[MAXN * NH];
__device__ __nv_bfloat16 d_WH[17 * WSLOT];
__device__ __nv_bfloat16 d_WL[17 * WSLOT];
__device__ float d_M[WSLOT];
__device__ float d_uvec[NH];
__device__ float d_tvec[NH];
__device__ float d_c0s[1];
__device__ float d_zbias[NH];
__device__ int   d_rowptr[MAXN + 1];
__device__ int   d_cnt[MAXN];
__device__ int   d_bsum[64];
__device__ int   d_cols[MAXE];
__device__ float d_w[MAXE];
__device__ float d_dinv[MAXN];
__device__ float d_scal[4 * SSTR];
__device__ volatile unsigned d_barcnt = 0;
__device__ volatile unsigned d_bargen = 0;

__device__ __forceinline__ void grid_barrier() {
    __syncthreads();
    if (threadIdx.x == 0) {
        unsigned g = d_bargen;
        __threadfence();
        unsigned a = atomicInc((unsigned*)&d_barcnt, NBLK - 1);
        if (a == NBLK - 1) {
            __threadfence();
            d_bargen = g + 1;
        } else {
            while (d_bargen == g) __nanosleep(128);
        }
        __threadfence();
    }
    __syncthreads();
}

// ---------------- CSR build ----------------
__global__ void count_kernel(const int* __restrict__ EI, int* __restrict__ cnt, int E) {
    int e = blockIdx.x * blockDim.x + threadIdx.x;
    if (e >= E) return;
    int r = EI[e], c = EI[E + e];
    if (r != c) atomicAdd(&cnt[r], 1);
}
__global__ void dinv_kernel(const int* __restrict__ cnt, float* __restrict__ dinv, int N) {
    int i = blockIdx.x * blockDim.x + threadIdx.x;
    if (i >= N) return;
    int d = cnt[i];
    dinv[i] = (d > 0) ? rsqrtf((float)d) : 0.f;
}
__global__ void blocksum_kernel(const int* __restrict__ cnt, int* __restrict__ bsum, int N) {
    __shared__ int sh[1024];
    int i = blockIdx.x * 1024 + threadIdx.x;
    sh[threadIdx.x] = (i < N) ? cnt[i] : 0;
    __syncthreads();
    for (int o = 512; o; o >>= 1) {
        if (threadIdx.x < o) sh[threadIdx.x] += sh[threadIdx.x + o];
        __syncthreads();
    }
    if (threadIdx.x == 0) bsum[blockIdx.x] = sh[0];
}
__global__ void scanbsum_kernel(int* __restrict__ bsum, int* __restrict__ rowptrN, int nb) {
    if (threadIdx.x == 0) {
        int run = 0;
        for (int i = 0; i < nb; i++) { int t = bsum[i]; bsum[i] = run; run += t; }
        *rowptrN = run;
    }
}
__global__ void localscan_kernel(int* __restrict__ cnt, int* __restrict__ rowptr,
                                 const int* __restrict__ bsum, int N) {
    __shared__ int sh[1024];
    int i = blockIdx.x * 1024 + threadIdx.x;
    int x = (i < N) ? cnt[i] : 0;
    sh[threadIdx.x] = x;
    __syncthreads();
    for (int off = 1; off < 1024; off <<= 1) {
        int t = (threadIdx.x >= off) ? sh[threadIdx.x - off] : 0;
        __syncthreads();
        sh[threadIdx.x] += t;
        __syncthreads();
    }
    if (i < N) { int excl = sh[threadIdx.x] - x + bsum[blockIdx.x]; rowptr[i] = excl; cnt[i] = excl; }
}
__global__ void fill_kernel(const int* __restrict__ EI, int* __restrict__ cursor,
                            const float* __restrict__ dinv, int* __restrict__ cols,
                            float* __restrict__ w, int E) {
    int e = blockIdx.x * blockDim.x + threadIdx.x;
    if (e >= E) return;
    int r = EI[e], c = EI[E + e];
    if (r != c) {
        int pos = atomicAdd(&cursor[r], 1);
        cols[pos] = c;
        w[pos] = -dinv[r] * dinv[c];
    }
}

// ---------------- Gram precompute ----------------
__global__ void gram_kernel(const float* __restrict__ Wq, const float* __restrict__ Wk,
                            const float* __restrict__ bq, const float* __restrict__ bk,
                            float* __restrict__ M, float* __restrict__ uv,
                            float* __restrict__ tv, float* __restrict__ c0) {
    if (blockIdx.x < 64) {
        int idx = blockIdx.x * 256 + threadIdx.x;
        int e = idx >> 7, f = idx & 127;
        float s = 0.f;
        for (int d = 0; d < 128; d++)
            s = fmaf(__ldg(&Wq[d * 128 + e]), __ldg(&Wk[d * 128 + f]), s);
        M[e * 128 + f] = s;
    } else if (threadIdx.x < 128) {
        int f = threadIdx.x;
        float su = 0.f, st = 0.f;
        for (int d = 0; d < 128; d++) {
            su = fmaf(__ldg(&bq[d]), __ldg(&Wk[d * 128 + f]), su);
            st = fmaf(__ldg(&bk[d]), __ldg(&Wq[d * 128 + f]), st);
        }
        uv[f] = su;
        tv[f] = st;
        if (f == 0) {
            float s = 0.f;
            for (int d = 0; d < 128; d++) s = fmaf(bq[d], bk[d], s);
            *c0 = s;
        }
    }
}

// ---------------- weight pre-conversion ----------------
struct WPtrs { const float* p[17]; };

__global__ void wconv_kernel(WPtrs wp, __nv_bfloat16* WH, __nv_bfloat16* WL) {
    int slot = blockIdx.y;
    int rows = (slot == 16) ? 40 : 128;
    int i = (blockIdx.x * 256 + threadIdx.x) * 4;
    int row = i >> 7;
    __nv_bfloat16* wh = WH + (size_t)slot * WSLOT + i;
    __nv_bfloat16* wl = WL + (size_t)slot * WSLOT + i;
    if (row < rows) {
        float4 v = *(const float4*)(wp.p[slot] + i);
        float a[4] = {v.x, v.y, v.z, v.w};
#pragma unroll
        for (int u = 0; u < 4; u++) {
            __nv_bfloat16 h = __float2bfloat16(a[u]);
            wh[u] = h;
            wl[u] = __float2bfloat16(a[u] - __bfloat162float(h));
        }
    } else {
#pragma unroll
        for (int u = 0; u < 4; u++) { wh[u] = __float2bfloat16(0.f); wl[u] = __float2bfloat16(0.f); }
    }
}

// ---------------- tensor-core GEMM ----------------
__device__ __forceinline__ void mma16816(float* c, const uint32_t* a, const uint32_t* b) {
    asm volatile(
        "mma.sync.aligned.m16n8k16.row.col.f32.bf16.bf16.f32 "
        "{%0,%1,%2,%3}, {%4,%5,%6,%7}, {%8,%9}, {%0,%1,%2,%3};\n"
        : "+f"(c[0]), "+f"(c[1]), "+f"(c[2]), "+f"(c[3])
        : "r"(a[0]), "r"(a[1]), "r"(a[2]), "r"(a[3]), "r"(b[0]), "r"(b[1]));
}
__device__ __forceinline__ void ldsm4(uint32_t* d, uint32_t addr) {
    asm volatile("ldmatrix.sync.aligned.m8n8.x4.shared.b16 {%0,%1,%2,%3}, [%4];"
                 : "=r"(d[0]), "=r"(d[1]), "=r"(d[2]), "=r"(d[3]) : "r"(addr));
}
__device__ __forceinline__ void ldsm2(uint32_t* d, uint32_t addr) {
    asm volatile("ldmatrix.sync.aligned.m8n8.x2.shared.b16 {%0,%1}, [%2];"
                 : "=r"(d[0]), "=r"(d[1]) : "r"(addr));
}
__device__ __forceinline__ void cp_async16(uint32_t dst, const void* src) {
    asm volatile("cp.async.cg.shared.global [%0], [%1], 16;" :: "r"(dst), "l"(src));
}

#define LDW 136
#define GSMEM ((2 * 64 + 2 * 128) * LDW * 2)

template <int EPI>
__device__ __forceinline__ void gemm_body(
    const float* __restrict__ A,
    const __nv_bfloat16* __restrict__ WHp, const __nv_bfloat16* __restrict__ WLp,
    const float* __restrict__ bsel, float* __restrict__ Csel, int N, int Oc,
    const float* __restrict__ bng, const float* __restrict__ bnb,
    const float* __restrict__ bnm, const float* __restrict__ bnv) {
    extern __shared__ __align__(16) char smem_raw[];
    __nv_bfloat16* Ah = (__nv_bfloat16*)smem_raw;
    __nv_bfloat16* Al = Ah + 64 * LDW;
    __nv_bfloat16* Wh = Al + 64 * LDW;
    __nv_bfloat16* Wl = Wh + 128 * LDW;

    const int tid = threadIdx.x;
    const int brow = blockIdx.x * 64;

    uint32_t sAh = (uint32_t)__cvta_generic_to_shared(Ah);
    uint32_t sAl = (uint32_t)__cvta_generic_to_shared(Al);
    uint32_t sWh = (uint32_t)__cvta_generic_to_shared(Wh);
    uint32_t sWl = (uint32_t)__cvta_generic_to_shared(Wl);

#pragma unroll
    for (int i = 0; i < 8; i++) {
        int ch = i * 256 + tid;
        int row = ch >> 4, cc = ch & 15;
        cp_async16(sWh + (uint32_t)(row * (LDW * 2) + cc * 16),
                   (const char*)WHp + row * 256 + cc * 16);
    }
#pragma unroll
    for (int i = 0; i < 8; i++) {
        int ch = i * 256 + tid;
        int row = ch >> 4, cc = ch & 15;
        cp_async16(sWl + (uint32_t)(row * (LDW * 2) + cc * 16),
                   (const char*)WLp + row * 256 + cc * 16);
    }
    asm volatile("cp.async.commit_group;");

#pragma unroll
    for (int i = 0; i < 8; i++) {
        int fl = i * 256 + tid;
        int row = fl >> 5;
        int c4 = (fl & 31) << 2;
        float4 av = make_float4(0.f, 0.f, 0.f, 0.f);
        int gr = brow + row;
        if (gr < N) av = *(const float4*)(A + (size_t)gr * 128 + c4);
        float a[4] = {av.x, av.y, av.z, av.w};
        uint32_t hp[2], lp[2];
#pragma unroll
        for (int h2 = 0; h2 < 2; h2++) {
            __nv_bfloat16 h0 = __float2bfloat16(a[h2 * 2]);
            __nv_bfloat16 h1 = __float2bfloat16(a[h2 * 2 + 1]);
            __nv_bfloat16 l0 = __float2bfloat16(a[h2 * 2] - __bfloat162float(h0));
            __nv_bfloat16 l1 = __float2bfloat16(a[h2 * 2 + 1] - __bfloat162float(h1));
            hp[h2] = ((uint32_t)__bfloat16_as_ushort(h1) << 16) | __bfloat16_as_ushort(h0);
            lp[h2] = ((uint32_t)__bfloat16_as_ushort(l1) << 16) | __bfloat16_as_ushort(l0);
        }
        int base = row * LDW + c4;
        *(uint2*)&Ah[base] = make_uint2(hp[0], hp[1]);
        *(uint2*)&Al[base] = make_uint2(lp[0], lp[1]);
    }
    asm volatile("cp.async.wait_group 0;");
    __syncthreads();

    const int w = tid >> 5, lane = tid & 31;
    const int wm = w >> 2, wn = w & 3;

    float acc[2][4][4];
#pragma unroll
    for (int mt = 0; mt < 2; mt++)
#pragma unroll
        for (int nt = 0; nt < 4; nt++)
#pragma unroll
            for (int u = 0; u < 4; u++) acc[mt][nt][u] = 0.f;

    uint32_t aBase[3] = {sAh, sAl, sAh};
    uint32_t wBase[3] = {sWh, sWh, sWl};

#pragma unroll
    for (int p = 0; p < 3; p++) {
        uint32_t ab = aBase[p], wb = wBase[p];
#pragma unroll
        for (int kk = 0; kk < 8; kk++) {
            uint32_t bfr[4][2];
            {
                int r = lane & 7, sel = (lane >> 3) & 1;
                int kcol = kk * 16 + sel * 8;
#pragma unroll
                for (int nt = 0; nt < 4; nt++) {
                    int row = wn * 32 + nt * 8 + r;
                    ldsm2(bfr[nt], wb + (uint32_t)(row * LDW + kcol) * 2);
                }
            }
#pragma unroll
            for (int mt = 0; mt < 2; mt++) {
                uint32_t afr[4];
                int q = lane >> 3, r = lane & 7;
                int row = wm * 32 + mt * 16 + (q & 1) * 8 + r;
                int kcol = kk * 16 + (q >> 1) * 8;
                ldsm4(afr, ab + (uint32_t)(row * LDW + kcol) * 2);
#pragma unroll
                for (int nt = 0; nt < 4; nt++)
                    mma16816(acc[mt][nt], afr, bfr[nt]);
            }
        }
    }

    const int g = lane >> 2, t2 = (lane & 3) * 2;
#pragma unroll
    for (int mt = 0; mt < 2; mt++) {
#pragma unroll
        for (int nt = 0; nt < 4; nt++) {
            int col0 = wn * 32 + nt * 8 + t2;
#pragma unroll
            for (int half = 0; half < 2; half++) {
                int row = brow + wm * 32 + mt * 16 + g + half * 8;
                if (row >= N) continue;
#pragma unroll
                for (int u = 0; u < 2; u++) {
                    int col = col0 + u;
                    if (col >= Oc) continue;
                    float x = acc[mt][nt][half * 2 + u] + bsel[col];
                    if (EPI) {
                        float s = bng[col] * rsqrtf(bnv[col] + EPS_BN);
                        x = (x - bnm[col]) * s + bnb[col];
                        if (EPI == 1) x = (x > 0.f) ? x : expm1f(x);
                        else x = fmaxf(x, 0.f);
                    }
                    Csel[(size_t)row * Oc + col] = x;
                }
            }
        }
    }
}

template <int EPI>
__global__ __launch_bounds__(256, 2) void gemm_tc(
    const float* __restrict__ A,
    const __nv_bfloat16* WH1, const __nv_bfloat16* WL1, const float* b1, float* C1,
    const __nv_bfloat16* WH2, const __nv_bfloat16* WL2, const float* b2, float* C2,
    int N, int Oc,
    const float* __restrict__ bng, const float* __restrict__ bnb,
    const float* __restrict__ bnm, const float* __restrict__ bnv) {
    gemm_body<EPI>(A, blockIdx.y ? WH2 : WH1, blockIdx.y ? WL2 : WL1,
                   blockIdx.y ? b2 : b1, blockIdx.y ? C2 : C1, N, Oc, bng, bnb, bnm, bnv);
}

__global__ __launch_bounds__(256, 2) void gemm_tc_b4(
    const float* __restrict__ A, const __nv_bfloat16* WHb, const __nv_bfloat16* WLb,
    const float* __restrict__ bb, float* __restrict__ Cb, size_t Cstride, int N) {
    gemm_body<0>(A, WHb + (size_t)blockIdx.y * WSLOT, WLb + (size_t)blockIdx.y * WSLOT,
                 bb + (size_t)blockIdx.y * NH, Cb + (size_t)blockIdx.y * Cstride,
                 N, NH, 0, 0, 0, 0);
}

// ---------------- attention stats via Gram trick ----------------
__global__ void attn_kernel(const float* __restrict__ a0, const float* __restrict__ a1,
                            const float* __restrict__ a2, const float* __restrict__ a3,
                            const float* __restrict__ v0, const float* __restrict__ v1,
                            const float* __restrict__ v2, const float* __restrict__ v3,
                            const float* __restrict__ uvp, const float* __restrict__ tvp,
                            const float* __restrict__ c0p,
                            const float* __restrict__ mha, float* __restrict__ Cm, int N) {
    const float scale = 0.08838834764831845f;
    float rfac = fmaxf(mha[0], 0.f);
    float c0 = *c0p;
    int lane = threadIdx.x & 31, wid = threadIdx.x >> 5;
    int gw = blockIdx.x * (blockDim.x >> 5) + wid;
    int tw = gridDim.x * (blockDim.x >> 5);
    const float* as[4] = {a0, a1, a2, a3};
    const float* vs[4] = {v0, v1, v2, v3};
    float4 u4 = *(const float4*)(uvp + lane * 4);
    float4 t4 = *(const float4*)(tvp + lane * 4);
    float acc[16];
#pragma unroll
    for (int m = 0; m < 16; m++) acc[m] = 0.f;
    for (int n = gw; n < N; n += tw) {
        float4 av[4], vv[4];
#pragma unroll
        for (int s = 0; s < 4; s++) {
            av[s] = *(const float4*)(as[s] + (size_t)n * NH + lane * 4);
            vv[s] = *(const float4*)(vs[s] + (size_t)n * NH + lane * 4);
        }
        float red[24];
#pragma unroll
        for (int i = 0; i < 4; i++)
#pragma unroll
            for (int j = 0; j < 4; j++) {
                float4 a = av[i], b = vv[j];
                red[i * 4 + j] = a.x * b.x + a.y * b.y + a.z * b.z + a.w * b.w;
            }
#pragma unroll
        for (int i = 0; i < 4; i++) {
            float4 a = av[i];
            red[16 + i] = t4.x * a.x + t4.y * a.y + t4.z * a.z + t4.w * a.w;
            red[20 + i] = u4.x * a.x + u4.y * a.y + u4.z * a.z + u4.w * a.w;
        }
#pragma unroll
        for (int m = 0; m < 24; m++) {
            float v = red[m];
#pragma unroll
            for (int o = 16; o; o >>= 1) v += __shfl_xor_sync(0xffffffffu, v, o);
            red[m] = v;
        }
        if (lane == 0) {
#pragma unroll
            for (int i = 0; i < 4; i++) {
                float s[4];
#pragma unroll
                for (int j = 0; j < 4; j++)
                    s[j] = (red[i * 4 + j] + red[16 + i] + red[20 + j] + c0) * scale;
                float mx = fmaxf(fmaxf(s[0], s[1]), fmaxf(s[2], s[3]));
                float e0 = expf(s[0] - mx), e1 = expf(s[1] - mx);
                float e2 = expf(s[2] - mx), e3 = expf(s[3] - mx);
                float inv = 1.f / (e0 + e1 + e2 + e3);
                acc[i * 4 + 0] += logf(e0 * inv * rfac + 1e-4f);
                acc[i * 4 + 1] += logf(e1 * inv * rfac + 1e-4f);
                acc[i * 4 + 2] += logf(e2 * inv * rfac + 1e-4f);
                acc[i * 4 + 3] += logf(e3 * inv * rfac + 1e-4f);
            }
        }
    }
    __shared__ float sh[8][16];
    if (lane == 0)
#pragma unroll
        for (int m = 0; m < 16; m++) sh[wid][m] = acc[m];
    __syncthreads();
    int nw = blockDim.x >> 5;
    if (threadIdx.x < 16) {
        float s = 0.f;
        for (int w2 = 0; w2 < nw; w2++) s += sh[w2][threadIdx.x];
        atomicAdd(&Cm[threadIdx.x], s);
    }
}

__global__ void combine4(const float* __restrict__ a0, const float* __restrict__ a1,
                         const float* __restrict__ a2, const float* __restrict__ a3,
                         const float* __restrict__ CmAcc, float Ninv,
                         float* __restrict__ out, int n4) {
    int i = blockIdx.x * blockDim.x + threadIdx.x;
    if (i >= n4) return;
    float c[4];
    {
        float M[16];
#pragma unroll
        for (int m = 0; m < 16; m++) M[m] = __ldg(&CmAcc[m]) * Ninv;
        float s = 0.f;
#pragma unroll
        for (int j = 0; j < 4; j++) { c[j] = 0.5f * (M[12 + j] + M[j * 4 + 3]); s += c[j]; }
        float invs = 1.f / s;
#pragma unroll
        for (int j = 0; j < 4; j++) c[j] *= invs;
    }
    float4 v0 = ((const float4*)a0)[i], v1 = ((const float4*)a1)[i];
    float4 v2 = ((const float4*)a2)[i], v3 = ((const float4*)a3)[i];
    float4 o;
    o.x = c[0] * v0.x + c[1] * v1.x + c[2] * v2.x + c[3] * v3.x;
    o.y = c[0] * v0.y + c[1] * v1.y + c[2] * v2.y + c[3] * v3.y;
    o.z = c[0] * v0.z + c[1] * v1.z + c[2] * v2.z + c[3] * v3.z;
    o.w = c[0] * v0.w + c[1] * v1.w + c[2] * v2.w + c[3] * v3.w;
    ((float4*)out)[i] = o;
}

// ---------------- persistent Chebyshev solve (row-major, bf16 Z, register X) ----------------
__device__ __forceinline__ float4 bf16row_load(const __nv_bfloat16* p) {
    uint2 zz = *reinterpret_cast<const uint2*>(p);
    __nv_bfloat162 h0 = *reinterpret_cast<__nv_bfloat162*>(&zz.x);
    __nv_bfloat162 h1 = *reinterpret_cast<__nv_bfloat162*>(&zz.y);
    float2 f0 = __bfloat1622float2(h0), f1 = __bfloat1622float2(h1);
    return make_float4(f0.x, f0.y, f1.x, f1.y);
}
__device__ __forceinline__ void bf16row_store(__nv_bfloat16* p, float4 v) {
    __nv_bfloat162 h0 = __floats2bfloat162_rn(v.x, v.y);
    __nv_bfloat162 h1 = __floats2bfloat162_rn(v.z, v.w);
    uint2 zz;
    zz.x = *reinterpret_cast<uint32_t*>(&h0);
    zz.y = *reinterpret_cast<uint32_t*>(&h1);
    *reinterpret_cast<uint2*>(p) = zz;
}

__global__ __launch_bounds__(CGT, 1) void cheb_kernel(
    const float* __restrict__ T1, const float* __restrict__ A1,
    const float* __restrict__ A2, const float* __restrict__ AU,
    const float* __restrict__ bng, const float* __restrict__ bnb,
    const float* __restrict__ bnm, const float* __restrict__ bnv,
    const int* __restrict__ rowptr, const int* __restrict__ cols,
    const float* __restrict__ w, const float* __restrict__ Kap,
    float* __restrict__ X, __nv_bfloat16* __restrict__ ZA,
    __nv_bfloat16* __restrict__ ZB, int N) {
    const int tid = blockIdx.x * CGT + threadIdx.x;
    const int lane = threadIdx.x & 31;
    const int gw = tid >> 5;
    const int tw = (NBLK * CGT) >> 5;
    const int cl = lane * 4;

    // per-lane params
    float4 bg = *(const float4*)(bng + cl), bb = *(const float4*)(bnb + cl);
    float4 bm = *(const float4*)(bnm + cl), bv = *(const float4*)(bnv + cl);
    float4 kk = *(const float4*)(Kap + cl);
    float w1p[4], sg[4], ck[4];
    {
        float kd[4] = {kk.x, kk.y, kk.z, kk.w};
#pragma unroll
        for (int u = 0; u < 4; u++) {
            float k2 = fminf(fmaxf(kd[u], 0.f), 1.f);
            float hk = HCOEF * k2;
            float rt = sqrtf(1.f + 2.f * hk);
            float s = hk / (1.f + hk + rt);
            w1p[u] = 1.f + 1.f / rt;
            sg[u] = s;
            ck[u] = -2.f * s / rt;
        }
    }
    float bgs[4] = {bg.x * rsqrtf(bv.x + EPS_BN), bg.y * rsqrtf(bv.y + EPS_BN),
                    bg.z * rsqrtf(bv.z + EPS_BN), bg.w * rsqrtf(bv.w + EPS_BN)};

    float4 xl[MAXR];

    // ---- prologue: per-row Tr -> ZA (bf16) ; X init in regs ----
    {
        int mi = 0;
        for (int r = gw; r < N; r += tw, mi++) {
            size_t off = (size_t)r * NH + cl;
            float4 t1 = *(const float4*)(T1 + off);
            float4 a1 = *(const float4*)(A1 + off);
            float4 a2 = *(const float4*)(A2 + off);
            float4 au = *(const float4*)(AU + off);
            float tt[4] = {t1.x, t1.y, t1.z, t1.w}, aa1[4] = {a1.x, a1.y, a1.z, a1.w};
            float aa2[4] = {a2.x, a2.y, a2.z, a2.w}, aau[4] = {au.x, au.y, au.z, au.w};
            float bbv[4] = {bb.x, bb.y, bb.z, bb.w}, bmv[4] = {bm.x, bm.y, bm.z, bm.w};
            float y[4], xv[4];
#pragma unroll
            for (int u = 0; u < 4; u++) {
                float d2 = fminf(fmaxf(aa2[u], -1.f), 1.f);
                float yy = tt[u] + HCOEF * (aa1[u] + aau[u] + tt[u] * d2);
                yy = (yy - bmv[u]) * bgs[u] + bbv[u];
                yy = (yy > 0.f) ? yy : expm1f(yy);
                y[u] = yy;
                xv[u] = w1p[u] * yy;
            }
            bf16row_store(ZA + off, make_float4(y[0], y[1], y[2], y[3]));
            xl[mi] = make_float4(xv[0], xv[1], xv[2], xv[3]);
        }
    }
    grid_barrier();

    float4 ckv = make_float4(ck[0], ck[1], ck[2], ck[3]);
    float4 sgv = make_float4(sg[0], sg[1], sg[2], sg[3]);

#pragma unroll
    for (int k = 1; k <= CHEB_M; k++) {
        const __nv_bfloat16* cur = (k & 1) ? ZA : ZB;
        __nv_bfloat16* oth = (k & 1) ? ZB : ZA;
        int mi = 0;
        for (int r = gw; r < N; r += tw, mi++) {
            int e0 = rowptr[r], e1 = rowptr[r + 1];
            float4 acc = make_float4(0.f, 0.f, 0.f, 0.f);
            for (int e = e0; e < e1; e++) {
                int c = __ldg(&cols[e]);
                float wt = __ldg(&w[e]);
                float4 y = bf16row_load(cur + (size_t)c * NH + cl);
                acc.x = fmaf(wt, y.x, acc.x); acc.y = fmaf(wt, y.y, acc.y);
                acc.z = fmaf(wt, y.z, acc.z); acc.w = fmaf(wt, y.w, acc.w);
            }
            size_t off = (size_t)r * NH + cl;
            float4 zn;
            if (k == 1) zn = acc;
            else {
                float4 zp = bf16row_load(oth + off);
                zn.x = 2.f * acc.x - zp.x; zn.y = 2.f * acc.y - zp.y;
                zn.z = 2.f * acc.z - zp.z; zn.w = 2.f * acc.w - zp.w;
            }
            float4 xv = xl[mi];
            xv.x = fmaf(ckv.x, zn.x, xv.x); xv.y = fmaf(ckv.y, zn.y, xv.y);
            xv.z = fmaf(ckv.z, zn.z, xv.z); xv.w = fmaf(ckv.w, zn.w, xv.w);
            xl[mi] = xv;
            if (k < CHEB_M) bf16row_store(oth + off, zn);
        }
        ckv.x *= -sgv.x; ckv.y *= -sgv.y; ckv.z *= -sgv.z; ckv.w *= -sgv.w;
        if (k < CHEB_M) grid_barrier();
    }

    // ---- write X ----
    {
        int mi = 0;
        for (int r = gw; r < N; r += tw, mi++)
            *(float4*)(X + (size_t)r * NH + cl) = xl[mi];
    }
}

// ---------------- host ----------------
extern "C" void kernel_launch(void* const* d_in, const int* in_sizes, int n_in,
                              void* d_out, int out_size) {
    const float* T      = (const float*)d_in[0];
    const int*   EI     = (const int*)d_in[1];
    const float* KopenW = (const float*)d_in[2];
    const float* Kopenb = (const float*)d_in[3];
    const float* bnOg   = (const float*)d_in[4];
    const float* bnOb   = (const float*)d_in[5];
    const float* bnOm   = (const float*)d_in[6];
    const float* bnOv   = (const float*)d_in[7];
    const float* convW  = (const float*)d_in[8];
    const float* convb  = (const float*)d_in[9];
    const float* bnAg   = (const float*)d_in[10];
    const float* bnAb   = (const float*)d_in[11];
    const float* bnAm   = (const float*)d_in[12];
    const float* bnAv   = (const float*)d_in[13];
    const float* Wq     = (const float*)d_in[14];
    const float* bq     = (const float*)d_in[15];
    const float* Wk     = (const float*)d_in[16];
    const float* bk     = (const float*)d_in[17];
    const float* mha    = (const float*)d_in[18];
    const float* KR1W   = (const float*)d_in[19];
    const float* KR1b   = (const float*)d_in[20];
    const float* KR2W   = (const float*)d_in[21];
    const float* KR2b   = (const float*)d_in[22];
    const float* KRU0W  = (const float*)d_in[23];
    const float* KRU0b  = (const float*)d_in[24];
    const float* bng    = (const float*)d_in[25];
    const float* bnbp   = (const float*)d_in[26];
    const float* bnm    = (const float*)d_in[27];
    const float* bnv    = (const float*)d_in[28];
    const float* Kappa  = (const float*)d_in[29];
    const float* KcloseW= (const float*)d_in[30];
    const float* Kcloseb= (const float*)d_in[31];

    const int N = in_sizes[0] / NH;
    const int E = in_sizes[1] / 2;
    const int n4 = N * (NH / 4);
    const size_t S = (size_t)MAXN * NH;

    float *Th, *z, *Xb, *vb, *T1, *A1, *A2, *AUb, *dinvp, *wp, *scal;
    float *Mg, *uvp, *tvp, *c0p, *zb;
    __nv_bfloat16 *WH, *WL, *ZA, *ZB;
    int *rowptr, *cnt, *bsum, *cols;
    cudaGetSymbolAddress((void**)&Th, d_Th);
    cudaGetSymbolAddress((void**)&z, d_z);
    cudaGetSymbolAddress((void**)&Xb, d_Xb);
    cudaGetSymbolAddress((void**)&vb, d_vb);
    cudaGetSymbolAddress((void**)&T1, d_T1);
    cudaGetSymbolAddress((void**)&A1, d_A1);
    cudaGetSymbolAddress((void**)&A2, d_A2);
    cudaGetSymbolAddress((void**)&AUb, d_AUb);
    cudaGetSymbolAddress((void**)&ZA, d_ZA);
    cudaGetSymbolAddress((void**)&ZB, d_ZB);
    cudaGetSymbolAddress((void**)&WH, d_WH);
    cudaGetSymbolAddress((void**)&WL, d_WL);
    cudaGetSymbolAddress((void**)&Mg, d_M);
    cudaGetSymbolAddress((void**)&uvp, d_uvec);
    cudaGetSymbolAddress((void**)&tvp, d_tvec);
    cudaGetSymbolAddress((void**)&c0p, d_c0s);
    cudaGetSymbolAddress((void**)&zb, d_zbias);
    cudaGetSymbolAddress((void**)&dinvp, d_dinv);
    cudaGetSymbolAddress((void**)&wp, d_w);
    cudaGetSymbolAddress((void**)&scal, d_scal);
    cudaGetSymbolAddress((void**)&rowptr, d_rowptr);
    cudaGetSymbolAddress((void**)&cnt, d_cnt);
    cudaGetSymbolAddress((void**)&bsum, d_bsum);
    cudaGetSymbolAddress((void**)&cols, d_cols);

    static bool attr_done = false;
    if (!attr_done) {
        cudaFuncSetAttribute(gemm_tc<0>, cudaFuncAttributeMaxDynamicSharedMemorySize, GSMEM);
        cudaFuncSetAttribute(gemm_tc<1>, cudaFuncAttributeMaxDynamicSharedMemorySize, GSMEM);
        cudaFuncSetAttribute(gemm_tc<2>, cudaFuncAttributeMaxDynamicSharedMemorySize, GSMEM);
        cudaFuncSetAttribute(gemm_tc_b4, cudaFuncAttributeMaxDynamicSharedMemorySize, GSMEM);
        attr_done = true;
    }

    const int GBX = (N + 63) / 64;
    dim3 g1(GBX, 1), g2(GBX, 2), g4(GBX, 4);
    const int VB = (n4 + 255) / 256;

    cudaMemsetAsync(cnt, 0, (size_t)N * sizeof(int));
    cudaMemsetAsync(scal, 0, 4 * SSTR * sizeof(float));
    cudaMemsetAsync(zb, 0, NH * sizeof(float));

    gram_kernel<<<65, 256>>>(Wq, Wk, bq, bk, Mg, uvp, tvp, c0p);

    WPtrs wpt;
    wpt.p[0] = KopenW; wpt.p[1] = convW; wpt.p[2] = Mg; wpt.p[3] = Mg;
    for (int j = 0; j < 4; j++) {
        wpt.p[4 + j] = KR1W + (size_t)j * WSLOT;
        wpt.p[8 + j] = KR2W + (size_t)j * WSLOT;
        wpt.p[12 + j] = KRU0W + (size_t)j * WSLOT;
    }
    wpt.p[16] = KcloseW;
    wconv_kernel<<<dim3(16, 17), 256>>>(wpt, WH, WL);

    count_kernel<<<(E + 255) / 256, 256>>>(EI, cnt, E);
    dinv_kernel<<<(N + 255) / 256, 256>>>(cnt, dinvp, N);
    int nb = (N + 1023) / 1024;
    blocksum_kernel<<<nb, 1024>>>(cnt, bsum, N);

    gemm_tc<1><<<g1, 256, GSMEM>>>(T, WH, WL, Kopenb, Th, WH, WL, Kopenb, Th, N, NH,
                                   bnOg, bnOb, bnOm, bnOv);

    scanbsum_kernel<<<1, 32>>>(bsum, rowptr + N, nb);
    localscan_kernel<<<nb, 1024>>>(cnt, rowptr, bsum, N);
    fill_kernel<<<(E + 255) / 256, 256>>>(EI, cnt, dinvp, cols, wp, E);

    gemm_tc<2><<<g1, 256, GSMEM>>>(Th, WH + 1 * WSLOT, WL + 1 * WSLOT, convb, z,
                                   WH + 1 * WSLOT, WL + 1 * WSLOT, convb, z, N, NH,
                                   bnAg, bnAb, bnAm, bnAv);
    gemm_tc<0><<<g1, 256, GSMEM>>>(z, WH + 2 * WSLOT, WL + 2 * WSLOT, zb, vb,
                                   WH + 2 * WSLOT, WL + 2 * WSLOT, zb, vb, N, NH, 0, 0, 0, 0);
    gemm_tc_b4<<<g4, 256, GSMEM>>>(Th, WH + 12 * WSLOT, WL + 12 * WSLOT, KRU0b, AUb, S, N);

    for (int jj = 0; jj < 4; jj++) {
        const float* T1in;
        if (jj == 0) {
            // all acts slots identical -> softmax exactly uniform -> T1 == z
            T1in = z;
        } else {
            gemm_tc<0><<<g1, 256, GSMEM>>>(Xb + (jj - 1) * S,
                                           WH + 2 * WSLOT, WL + 2 * WSLOT, zb, vb + jj * S,
                                           WH + 2 * WSLOT, WL + 2 * WSLOT, zb, vb + jj * S,
                                           N, NH, 0, 0, 0, 0);
            const float *aa[4], *av[4];
            for (int o = 0; o < 4; o++) {
                if (o < 4 - jj) { aa[o] = z; av[o] = vb; }
                else {
                    int m = o - 4 + jj;
                    aa[o] = Xb + m * S; av[o] = vb + (m + 1) * S;
                }
            }
            float* sl = scal + jj * SSTR;
            attn_kernel<<<400, 256>>>(aa[0], aa[1], aa[2], aa[3], av[0], av[1], av[2], av[3],
                                      uvp, tvp, c0p, mha, sl, N);
            combine4<<<VB, 256>>>(aa[0], aa[1], aa[2], aa[3], sl, 1.0f / (float)N, T1, n4);
            T1in = T1;
        }

        gemm_tc<0><<<g2, 256, GSMEM>>>(T1in,
                                       WH + (4 + jj) * WSLOT, WL + (4 + jj) * WSLOT,
                                       KR1b + jj * NH, A1,
                                       WH + (8 + jj) * WSLOT, WL + (8 + jj) * WSLOT,
                                       KR2b + jj * NH, A2, N, NH, 0, 0, 0, 0);

        cheb_kernel<<<NBLK, CGT>>>(T1in, A1, A2, AUb + jj * S, bng + jj * NH, bnbp + jj * NH,
                                   bnm + jj * NH, bnv + jj * NH, rowptr, cols, wp,
                                   Kappa + jj * NH, Xb + jj * S, ZA, ZB, N);
    }
    gemm_tc<0><<<g1, 256, GSMEM>>>(Xb + 3 * S, WH + 16 * WSLOT, WL + 16 * WSLOT, Kcloseb,
                                   (float*)d_out, WH + 16 * WSLOT, WL + 16 * WSLOT, Kcloseb,
                                   (float*)d_out, N, 40, 0, 0, 0, 0);
}